// round 7
// baseline (speedup 1.0000x reference)
#include <cuda_runtime.h>
#include <cuda_bf16.h>
#include <math.h>
#include <stdint.h>

#define NN      100000
#define INC     128
#define EMB     256
#define NHEAD   4
#define HID     64
#define NLAYER  3
#define NE      300000
#define ET      400000          // NE + NN self loops
#define BN_EPS  1e-5f

// ---------------- scratch ----------------
__device__ float g_h  [NN * EMB];
__device__ float g_xlr[(size_t)NN * 512];          // cols 0-255: xl, 256-511: xr
__device__ __nv_bfloat16 g_hbh[NN * EMB], g_hbl[NN * EMB];   // h split
__device__ __nv_bfloat16 g_xbh[NN * INC], g_xbl[NN * INC];   // x split
__device__ __nv_bfloat16 g_wth[NLAYER * 512 * EMB], g_wtl[NLAYER * 512 * EMB];
__device__ __nv_bfloat16 g_pjh[EMB * INC], g_pjl[EMB * INC]; // proj^T [256][128]
__device__ __nv_bfloat16 g_dch[INC * EMB], g_dcl[INC * EMB]; // dec^T  [128][256]
// CSR
__device__ int g_cnt[NN];
__device__ int g_rowp[NN + 1];
__device__ int g_col[ET];
__device__ int g_bsum[512];

__device__ __forceinline__ uint32_t smem_u32(const void* p) {
    uint32_t a;
    asm("{ .reg .u64 t; cvta.to.shared.u64 t, %1; cvt.u32.u64 %0, t; }"
        : "=r"(a) : "l"(p));
    return a;
}
__device__ __forceinline__ void split_bf16(float v, __nv_bfloat16& h, __nv_bfloat16& l) {
    h = __float2bfloat16(v);
    l = __float2bfloat16(v - __bfloat162float(h));
}

// ---------------- weight prep ----------------
// generic: fp32 [K][NC] -> bf16 hi/lo [NC][K]
__global__ void prep_weights(const float* __restrict__ W, int K, int NC,
                             __nv_bfloat16* __restrict__ hi,
                             __nv_bfloat16* __restrict__ lo)
{
    const int idx = blockIdx.x * 256 + threadIdx.x;
    if (idx >= K * NC) return;
    const int k = idx / NC, n = idx - k * NC;
    __nv_bfloat16 h, l;
    split_bf16(W[idx], h, l);
    hi[(size_t)n * K + k] = h;
    lo[(size_t)n * K + k] = l;
}
// all layers' Wl|Wr -> fused transposed images in one launch
__global__ void prep_wlr(const float* __restrict__ Wl, const float* __restrict__ Wr)
{
    const int idx = blockIdx.x * 256 + threadIdx.x;   // NLAYER*2*EMB*EMB
    if (idx >= NLAYER * 2 * EMB * EMB) return;
    const int l = idx / (2 * EMB * EMB);
    const int r = idx - l * 2 * EMB * EMB;
    const int sel = r / (EMB * EMB);
    const int t = r - sel * EMB * EMB;
    const int k = t / EMB, n = t - k * EMB;
    const float v = (sel ? Wr : Wl)[(size_t)l * EMB * EMB + t];
    __nv_bfloat16 h, lo;
    split_bf16(v, h, lo);
    const size_t d = (size_t)l * 512 * EMB + (size_t)(sel * 256 + n) * EMB + k;
    g_wth[d] = h;
    g_wtl[d] = lo;
}
__global__ void prep_x(const float* __restrict__ x)
{
    const int idx = blockIdx.x * 256 + threadIdx.x;
    if (idx >= NN * INC) return;
    __nv_bfloat16 h, l;
    split_bf16(x[idx], h, l);
    g_xbh[idx] = h;
    g_xbl[idx] = l;
}

// ---------------- CSR build ----------------
__global__ void csr_zero() {
    const int i = blockIdx.x * 256 + threadIdx.x;
    if (i < NN) g_cnt[i] = 1;                        // self loop
}
__global__ void csr_hist(const int* __restrict__ ei) {
    const int e = blockIdx.x * 256 + threadIdx.x;
    if (e < NE) atomicAdd(&g_cnt[ei[NE + e]], 1);
}
__global__ void csr_scan1() {                        // per-block exclusive scan
    __shared__ int s[256];
    const int i = blockIdx.x * 256 + threadIdx.x;
    int v = (i < NN) ? g_cnt[i] : 0;
    s[threadIdx.x] = v;
    __syncthreads();
    int sum = v;
    #pragma unroll
    for (int off = 1; off < 256; off <<= 1) {
        int t = (threadIdx.x >= off) ? s[threadIdx.x - off] : 0;
        __syncthreads();
        s[threadIdx.x] = sum = sum + t;
        __syncthreads();
    }
    if (i < NN) g_rowp[i] = sum - v;                 // exclusive
    if (threadIdx.x == 255) g_bsum[blockIdx.x] = s[255];
}
__global__ void csr_scan2(int nb) {                  // parallel block-sum scan
    __shared__ int s[512];
    const int t = threadIdx.x;
    int v = (t < nb) ? g_bsum[t] : 0;
    s[t] = v;
    __syncthreads();
    int sum = v;
    #pragma unroll
    for (int off = 1; off < 512; off <<= 1) {
        int u = (t >= off) ? s[t - off] : 0;
        __syncthreads();
        s[t] = sum = sum + u;
        __syncthreads();
    }
    if (t < nb) g_bsum[t] = sum - v;                 // exclusive
}
__global__ void csr_scan3() {
    const int i = blockIdx.x * 256 + threadIdx.x;
    if (i == 0) g_rowp[NN] = ET;
    if (i >= NN) return;
    const int r = g_rowp[i] + g_bsum[i >> 8];
    g_rowp[i] = r;
    g_col[r] = i;                                    // self loop at slot 0
    g_cnt[i] = r + 1;                                // cursor
}
__global__ void csr_fill(const int* __restrict__ ei) {
    const int e = blockIdx.x * 256 + threadIdx.x;
    if (e >= NE) return;
    const int pos = atomicAdd(&g_cnt[ei[NE + e]], 1);
    g_col[pos] = ei[e];
}

// ============ bf16 mma.sync GEMM, 2-stage cp.async pipeline ==============
// C[M,NC] = A[M,K] @ W[K,NC]; A, Bt pre-split bf16 hi/lo, Bt = W^T [NC][K].
// 3-term split: Ah*Bh + Al*Bh + Ah*Bl.
// EPI 0: none   EPI 1: +bias, BN, ELU, also write g_hb split   EPI 2: +bias
#define RS  72
#define SMBUF (128 * RS)              // elems per operand buffer
#define STAGEB (4 * SMBUF * 2)        // bytes per stage (4 buffers)
#define SMBYTES (2 * STAGEB)          // 147456

#define CPA(dst32, src, pb) \
    asm volatile("cp.async.cg.shared.global [%0], [%1], 16, %2;" \
                 :: "r"(dst32), "l"(src), "r"(pb))

__device__ __forceinline__ void ldsm_x4(uint32_t* r, uint32_t addr) {
    asm volatile("ldmatrix.sync.aligned.m8n8.x4.shared.b16 {%0,%1,%2,%3}, [%4];"
                 : "=r"(r[0]), "=r"(r[1]), "=r"(r[2]), "=r"(r[3]) : "r"(addr));
}
__device__ __forceinline__ void ldsm_x2(uint32_t* r, uint32_t addr) {
    asm volatile("ldmatrix.sync.aligned.m8n8.x2.shared.b16 {%0,%1}, [%2];"
                 : "=r"(r[0]), "=r"(r[1]) : "r"(addr));
}
__device__ __forceinline__ void mma16816(float* c, const uint32_t* a, const uint32_t* b) {
    asm volatile("mma.sync.aligned.m16n8k16.row.col.f32.bf16.bf16.f32 "
                 "{%0,%1,%2,%3}, {%4,%5,%6,%7}, {%8,%9}, {%0,%1,%2,%3};"
                 : "+f"(c[0]), "+f"(c[1]), "+f"(c[2]), "+f"(c[3])
                 : "r"(a[0]), "r"(a[1]), "r"(a[2]), "r"(a[3]), "r"(b[0]), "r"(b[1]));
}

template<int EPI>
__global__ __launch_bounds__(256, 1)
void hgemm(const __nv_bfloat16* __restrict__ Ath, const __nv_bfloat16* __restrict__ Atl,
           const __nv_bfloat16* __restrict__ Bth, const __nv_bfloat16* __restrict__ Btl,
           float* __restrict__ C, int M, int K, int NC,
           const float* __restrict__ bias, const float* __restrict__ gg,
           const float* __restrict__ gb, const float* __restrict__ gm,
           const float* __restrict__ gv)
{
    extern __shared__ __nv_bfloat16 sm[];
    const uint32_t s32 = smem_u32(sm);
    const int tid = threadIdx.x, lane = tid & 31, w = tid >> 5;
    const int m0 = blockIdx.y * 128, n0 = blockIdx.x * 128;
    const int wm = (w >> 2) * 64, wn = (w & 3) * 32;

    float acc[4][4][4] = {};
    const int nchunks = K >> 6;

    auto load_chunk = [&](int ch, int st) {
        const uint32_t sb = s32 + (uint32_t)st * STAGEB;
        #pragma unroll
        for (int i = 0; i < 4; i++) {
            const int idx = i * 256 + tid, r = idx >> 3, q = idx & 7;
            const uint32_t doff = (uint32_t)(r * RS + q * 8) * 2;
            const size_t aoff = (size_t)(m0 + r) * K + ch * 64 + q * 8;
            const size_t boff = (size_t)(n0 + r) * K + ch * 64 + q * 8;
            const unsigned av = (m0 + r < M) ? 16u : 0u;
            CPA(sb + doff,                 Ath + aoff, av);
            CPA(sb + SMBUF * 2 + doff,     Atl + aoff, av);
            CPA(sb + 2 * SMBUF * 2 + doff, Bth + boff, 16u);
            CPA(sb + 3 * SMBUF * 2 + doff, Btl + boff, 16u);
        }
        asm volatile("cp.async.commit_group;" ::: "memory");
    };

    load_chunk(0, 0);

    for (int ch = 0; ch < nchunks; ch++) {
        if (ch + 1 < nchunks) {
            load_chunk(ch + 1, (ch + 1) & 1);
            asm volatile("cp.async.wait_group 1;" ::: "memory");
        } else {
            asm volatile("cp.async.wait_group 0;" ::: "memory");
        }
        __syncthreads();

        const uint32_t sb = s32 + (uint32_t)(ch & 1) * STAGEB;
        const int lra = lane & 15, lka = (lane >> 4) * 8;
        const int lrb = lane & 7,  lkb = ((lane >> 3) & 1) * 8;

        #pragma unroll
        for (int ks = 0; ks < 4; ks++) {
            const int k0 = ks * 16;
            uint32_t ah[4][4], al[4][4], bh[4][2], bl[4][2];
            #pragma unroll
            for (int mt = 0; mt < 4; mt++)
                ldsm_x4(ah[mt], sb + ((wm + mt * 16 + lra) * RS + k0 + lka) * 2);
            #pragma unroll
            for (int nt = 0; nt < 4; nt++)
                ldsm_x2(bh[nt], sb + (2 * SMBUF + (wn + nt * 8 + lrb) * RS + k0 + lkb) * 2);
            #pragma unroll
            for (int mt = 0; mt < 4; mt++)
                #pragma unroll
                for (int nt = 0; nt < 4; nt++)
                    mma16816(acc[mt][nt], ah[mt], bh[nt]);
            #pragma unroll
            for (int mt = 0; mt < 4; mt++)
                ldsm_x4(al[mt], sb + (SMBUF + (wm + mt * 16 + lra) * RS + k0 + lka) * 2);
            #pragma unroll
            for (int mt = 0; mt < 4; mt++)
                #pragma unroll
                for (int nt = 0; nt < 4; nt++)
                    mma16816(acc[mt][nt], al[mt], bh[nt]);
            #pragma unroll
            for (int nt = 0; nt < 4; nt++)
                ldsm_x2(bl[nt], sb + (3 * SMBUF + (wn + nt * 8 + lrb) * RS + k0 + lkb) * 2);
            #pragma unroll
            for (int mt = 0; mt < 4; mt++)
                #pragma unroll
                for (int nt = 0; nt < 4; nt++)
                    mma16816(acc[mt][nt], ah[mt], bl[nt]);
        }
        __syncthreads();
    }

    #pragma unroll
    for (int mt = 0; mt < 4; mt++) {
        #pragma unroll
        for (int nt = 0; nt < 4; nt++) {
            #pragma unroll
            for (int q = 0; q < 4; q++) {
                const int row = m0 + wm + mt * 16 + (lane >> 2) + (q >> 1) * 8;
                const int col = n0 + wn + nt * 8 + 2 * (lane & 3) + (q & 1);
                if (row >= M) continue;
                float v = acc[mt][nt][q];
                if (EPI >= 1) v += bias[col];
                if (EPI == 1) {
                    v = (v - gm[col]) * (gg[col] * rsqrtf(gv[col] + BN_EPS)) + gb[col];
                    v = v > 0.f ? v : expf(v) - 1.f;
                }
                C[(size_t)row * NC + col] = v;
                if (EPI == 1) {
                    __nv_bfloat16 hb, lb;
                    split_bf16(v, hb, lb);
                    g_hbh[(size_t)row * EMB + col] = hb;
                    g_hbl[(size_t)row * EMB + col] = lb;
                }
            }
        }
    }
}

// ====== fused GATv2 aggregation: warp per dst node (CSR, no atomics) =====
__global__ __launch_bounds__(256)
void gat_aggregate(const float* __restrict__ att, const float* __restrict__ cb,
                   const float* __restrict__ bg, const float* __restrict__ bb,
                   const float* __restrict__ bm, const float* __restrict__ bv,
                   float* __restrict__ out_h)
{
    const int lane = threadIdx.x & 31;
    const int n = (blockIdx.x * 256 + threadIdx.x) >> 5;
    if (n >= NN) return;
    const int j0 = lane * 8;

    float sA[8], xr8[8];
    {
        const float4* ap = (const float4*)(att + j0);
        float4 a0 = ap[0], a1 = ap[1];
        sA[0]=a0.x; sA[1]=a0.y; sA[2]=a0.z; sA[3]=a0.w;
        sA[4]=a1.x; sA[5]=a1.y; sA[6]=a1.z; sA[7]=a1.w;
        const float4* rp = (const float4*)(g_xlr + (size_t)n * 512 + 256 + j0);
        float4 r0 = rp[0], r1 = rp[1];
        xr8[0]=r0.x; xr8[1]=r0.y; xr8[2]=r0.z; xr8[3]=r0.w;
        xr8[4]=r1.x; xr8[5]=r1.y; xr8[6]=r1.z; xr8[7]=r1.w;
    }

    float acc[8] = {};
    float den = 0.f;
    const int e0 = g_rowp[n], e1 = g_rowp[n + 1];

    // software-pipelined gather: next edge's row in flight during compute
    int src = g_col[e0];
    const float4* lp = (const float4*)(g_xlr + (size_t)src * 512 + j0);
    float4 c0 = lp[0], c1 = lp[1];
    for (int e = e0; e < e1; e++) {
        const float4 l0 = c0, l1 = c1;
        if (e + 1 < e1) {
            const int s2 = g_col[e + 1];
            const float4* np = (const float4*)(g_xlr + (size_t)s2 * 512 + j0);
            c0 = np[0]; c1 = np[1];
        }
        float xl8[8] = {l0.x, l0.y, l0.z, l0.w, l1.x, l1.y, l1.z, l1.w};
        float part = 0.f;
        #pragma unroll
        for (int u = 0; u < 8; u++) {
            float s = xl8[u] + xr8[u];
            s = s > 0.f ? s : 0.2f * s;
            part += s * sA[u];
        }
        part += __shfl_xor_sync(0xffffffffu, part, 1);
        part += __shfl_xor_sync(0xffffffffu, part, 2);
        part += __shfl_xor_sync(0xffffffffu, part, 4);
        const float p = expf(part);
        den += p;
        #pragma unroll
        for (int u = 0; u < 8; u++) acc[u] += p * xl8[u];
    }

    const float inv = 1.f / den;
    float* hp = g_h + (size_t)n * EMB + j0;
    float4 h0 = ((const float4*)hp)[0], h1 = ((const float4*)hp)[1];
    float hold[8] = {h0.x, h0.y, h0.z, h0.w, h1.x, h1.y, h1.z, h1.w};
    float outv[8];
    #pragma unroll
    for (int u = 0; u < 8; u++) {
        const int j = j0 + u;
        float v = acc[u] * inv + cb[j];
        v = (v - bm[j]) * (bg[j] * rsqrtf(bv[j] + BN_EPS)) + bb[j];
        v = v > 0.f ? v : expf(v) - 1.f;
        outv[u] = hold[u] + v;
    }
    const float4 o0 = make_float4(outv[0], outv[1], outv[2], outv[3]);
    const float4 o1 = make_float4(outv[4], outv[5], outv[6], outv[7]);
    ((float4*)hp)[0] = o0;
    ((float4*)hp)[1] = o1;
    if (out_h) {
        float* op = out_h + (size_t)n * EMB + j0;
        ((float4*)op)[0] = o0;
        ((float4*)op)[1] = o1;
    }
    #pragma unroll
    for (int u = 0; u < 8; u++) {
        __nv_bfloat16 hb, lb;
        split_bf16(outv[u], hb, lb);
        g_hbh[(size_t)n * EMB + j0 + u] = hb;
        g_hbl[(size_t)n * EMB + j0 + u] = lb;
    }
}

// ---------------- heads: preds[k] = h @ head_W[k] + head_b[k] ------------
__global__ void head_kernel(const float* __restrict__ hW, const float* __restrict__ hb,
                            float* __restrict__ out)
{
    __shared__ float sW[4 * EMB];
    for (int i = threadIdx.x; i < 4 * EMB; i += blockDim.x) sW[i] = hW[i];
    __syncthreads();

    const int gw = (blockIdx.x * blockDim.x + threadIdx.x) >> 5;
    const int lane = threadIdx.x & 31;
    if (gw >= NN) return;
    const float* hp = g_h + (size_t)gw * EMB;
    float s0 = 0.f, s1 = 0.f, s2 = 0.f, s3 = 0.f;
    #pragma unroll
    for (int k = 0; k < 8; k++) {
        const int c = lane + k * 32;
        const float hv = hp[c];
        s0 += hv * sW[c];
        s1 += hv * sW[EMB + c];
        s2 += hv * sW[2 * EMB + c];
        s3 += hv * sW[3 * EMB + c];
    }
    #pragma unroll
    for (int off = 16; off; off >>= 1) {
        s0 += __shfl_down_sync(0xffffffffu, s0, off);
        s1 += __shfl_down_sync(0xffffffffu, s1, off);
        s2 += __shfl_down_sync(0xffffffffu, s2, off);
        s3 += __shfl_down_sync(0xffffffffu, s3, off);
    }
    if (lane == 0) {
        out[gw]          = s0 + hb[0];
        out[NN + gw]     = s1 + hb[1];
        out[2 * NN + gw] = s2 + hb[2];
        out[3 * NN + gw] = s3 + hb[3];
    }
}

// ---------------- launch ----------------
extern "C" void kernel_launch(void* const* d_in, const int* in_sizes, int n_in,
                              void* d_out, int out_size)
{
    const float* x      = (const float*)d_in[0];
    const int*   ei     = (const int*)  d_in[1];
    const float* proj_W = (const float*)d_in[2];
    const float* proj_b = (const float*)d_in[3];
    const float* ibn_g  = (const float*)d_in[4];
    const float* ibn_b  = (const float*)d_in[5];
    const float* ibn_m  = (const float*)d_in[6];
    const float* ibn_v  = (const float*)d_in[7];
    const float* Wl     = (const float*)d_in[8];
    const float* Wr     = (const float*)d_in[9];
    const float* att    = (const float*)d_in[10];
    const float* conv_b = (const float*)d_in[11];
    const float* bn_g   = (const float*)d_in[12];
    const float* bn_b   = (const float*)d_in[13];
    const float* bn_m   = (const float*)d_in[14];
    const float* bn_v   = (const float*)d_in[15];
    const float* head_W = (const float*)d_in[16];
    const float* head_b = (const float*)d_in[17];
    const float* dec_W  = (const float*)d_in[18];
    const float* dec_b  = (const float*)d_in[19];
    float* out = (float*)d_out;

    float* h;
    float* xlr;
    cudaGetSymbolAddress((void**)&h,   g_h);
    cudaGetSymbolAddress((void**)&xlr, g_xlr);
    __nv_bfloat16 *hbh, *hbl, *xbh, *xbl, *wth, *wtl, *pjh, *pjl, *dch, *dcl;
    cudaGetSymbolAddress((void**)&hbh, g_hbh);
    cudaGetSymbolAddress((void**)&hbl, g_hbl);
    cudaGetSymbolAddress((void**)&xbh, g_xbh);
    cudaGetSymbolAddress((void**)&xbl, g_xbl);
    cudaGetSymbolAddress((void**)&wth, g_wth);
    cudaGetSymbolAddress((void**)&wtl, g_wtl);
    cudaGetSymbolAddress((void**)&pjh, g_pjh);
    cudaGetSymbolAddress((void**)&pjl, g_pjl);
    cudaGetSymbolAddress((void**)&dch, g_dch);
    cudaGetSymbolAddress((void**)&dcl, g_dcl);

    cudaFuncSetAttribute(hgemm<0>, cudaFuncAttributeMaxDynamicSharedMemorySize, SMBYTES);
    cudaFuncSetAttribute(hgemm<1>, cudaFuncAttributeMaxDynamicSharedMemorySize, SMBYTES);
    cudaFuncSetAttribute(hgemm<2>, cudaFuncAttributeMaxDynamicSharedMemorySize, SMBYTES);

    const int gy = (NN + 127) / 128;          // 782
    const int nb = (NN + 255) / 256;          // 391

    // ---- prep: weights, x split, CSR ----
    prep_weights<<<(INC * EMB + 255) / 256, 256>>>(proj_W, INC, EMB, pjh, pjl);
    prep_wlr<<<(NLAYER * 2 * EMB * EMB + 255) / 256, 256>>>(Wl, Wr);
    prep_weights<<<(EMB * INC + 255) / 256, 256>>>(dec_W, EMB, INC, dch, dcl);
    prep_x<<<(NN * INC + 255) / 256, 256>>>(x);

    csr_zero<<<nb, 256>>>();
    csr_hist<<<(NE + 255) / 256, 256>>>(ei);
    csr_scan1<<<nb, 256>>>();
    csr_scan2<<<1, 512>>>(nb);
    csr_scan3<<<nb, 256>>>();
    csr_fill<<<(NE + 255) / 256, 256>>>(ei);

    // ---- h = elu(bn(x @ proj_W + proj_b)) ----
    hgemm<1><<<dim3(2, gy), 256, SMBYTES>>>(xbh, xbl, pjh, pjl, h, NN, INC, EMB,
                                            proj_b, ibn_g, ibn_b, ibn_m, ibn_v);

    for (int i = 0; i < NLAYER; i++) {
        hgemm<0><<<dim3(4, gy), 256, SMBYTES>>>(hbh, hbl,
                                                wth + (size_t)i * 512 * EMB,
                                                wtl + (size_t)i * 512 * EMB,
                                                xlr, NN, EMB, 512,
                                                nullptr, nullptr, nullptr, nullptr, nullptr);
        gat_aggregate<<<(NN * 32 + 255) / 256, 256>>>(att + (size_t)i * NHEAD * HID,
                                                      conv_b + (size_t)i * EMB,
                                                      bn_g + (size_t)i * EMB, bn_b + (size_t)i * EMB,
                                                      bn_m + (size_t)i * EMB, bn_v + (size_t)i * EMB,
                                                      (i == NLAYER - 1) ? out + (size_t)4 * NN : nullptr);
    }

    // preds (4 x [N]) at out[0 .. 4N)
    head_kernel<<<(NN * 32 + 255) / 256, 256>>>(head_W, head_b, out);
    // recon at out[260N .. 388N)
    hgemm<2><<<dim3(1, gy), 256, SMBYTES>>>(hbh, hbl, dch, dcl, out + (size_t)260 * NN,
                                            NN, EMB, INC, dec_b,
                                            nullptr, nullptr, nullptr, nullptr);
}

// round 8
// speedup vs baseline: 1.0577x; 1.0577x over previous
#include <cuda_runtime.h>
#include <cuda_bf16.h>
#include <math.h>
#include <stdint.h>

#define NN      100000
#define INC     128
#define EMB     256
#define NHEAD   4
#define HID     64
#define NLAYER  3
#define NE      300000
#define ET      400000          // NE + NN self loops
#define BN_EPS  1e-5f

// ---------------- scratch ----------------
__device__ float g_h  [NN * EMB];
__device__ float g_xlr[(size_t)NN * 512];          // cols 0-255: xl, 256-511: xr
__device__ __nv_bfloat16 g_hbh[NN * EMB], g_hbl[NN * EMB];   // h split
__device__ __nv_bfloat16 g_xbh[NN * INC], g_xbl[NN * INC];   // x split
__device__ __nv_bfloat16 g_wth[NLAYER * 512 * EMB], g_wtl[NLAYER * 512 * EMB];
__device__ __nv_bfloat16 g_pjh[EMB * INC], g_pjl[EMB * INC]; // proj^T [256][128]
__device__ __nv_bfloat16 g_dch[INC * EMB], g_dcl[INC * EMB]; // dec^T  [128][256]
// CSR
__device__ int g_cnt[NN];
__device__ int g_rowp[NN + 1];
__device__ int g_col[ET];
__device__ int g_bsum[512];

__device__ __forceinline__ uint32_t smem_u32(const void* p) {
    uint32_t a;
    asm("{ .reg .u64 t; cvta.to.shared.u64 t, %1; cvt.u32.u64 %0, t; }"
        : "=r"(a) : "l"(p));
    return a;
}
__device__ __forceinline__ void split_bf16(float v, __nv_bfloat16& h, __nv_bfloat16& l) {
    h = __float2bfloat16(v);
    l = __float2bfloat16(v - __bfloat162float(h));
}

// ---------------- weight prep ----------------
__global__ void prep_weights(const float* __restrict__ W, int K, int NC,
                             __nv_bfloat16* __restrict__ hi,
                             __nv_bfloat16* __restrict__ lo)
{
    const int idx = blockIdx.x * 256 + threadIdx.x;
    if (idx >= K * NC) return;
    const int k = idx / NC, n = idx - k * NC;
    __nv_bfloat16 h, l;
    split_bf16(W[idx], h, l);
    hi[(size_t)n * K + k] = h;
    lo[(size_t)n * K + k] = l;
}
// all layers' Wl|Wr -> fused transposed images in one launch
__global__ void prep_wlr(const float* __restrict__ Wl, const float* __restrict__ Wr)
{
    const int idx = blockIdx.x * 256 + threadIdx.x;   // NLAYER*2*EMB*EMB
    if (idx >= NLAYER * 2 * EMB * EMB) return;
    const int l = idx / (2 * EMB * EMB);
    const int r = idx - l * 2 * EMB * EMB;
    const int sel = r / (EMB * EMB);
    const int t = r - sel * EMB * EMB;
    const int k = t / EMB, n = t - k * EMB;
    const float v = (sel ? Wr : Wl)[(size_t)l * EMB * EMB + t];
    __nv_bfloat16 h, lo;
    split_bf16(v, h, lo);
    const size_t d = (size_t)l * 512 * EMB + (size_t)(sel * 256 + n) * EMB + k;
    g_wth[d] = h;
    g_wtl[d] = lo;
}
__global__ void prep_x(const float* __restrict__ x)
{
    const int idx = blockIdx.x * 256 + threadIdx.x;
    if (idx >= NN * INC) return;
    __nv_bfloat16 h, l;
    split_bf16(x[idx], h, l);
    g_xbh[idx] = h;
    g_xbl[idx] = l;
}

// ---------------- CSR build ----------------
__global__ void csr_zero() {
    const int i = blockIdx.x * 256 + threadIdx.x;
    if (i < NN) g_cnt[i] = 1;                        // self loop
}
__global__ void csr_hist(const int* __restrict__ ei) {
    const int e = blockIdx.x * 256 + threadIdx.x;
    if (e < NE) atomicAdd(&g_cnt[ei[NE + e]], 1);
}
__global__ void csr_scan1() {                        // per-block exclusive scan
    __shared__ int s[256];
    const int i = blockIdx.x * 256 + threadIdx.x;
    int v = (i < NN) ? g_cnt[i] : 0;
    s[threadIdx.x] = v;
    __syncthreads();
    int sum = v;
    #pragma unroll
    for (int off = 1; off < 256; off <<= 1) {
        int t = (threadIdx.x >= off) ? s[threadIdx.x - off] : 0;
        __syncthreads();
        s[threadIdx.x] = sum = sum + t;
        __syncthreads();
    }
    if (i < NN) g_rowp[i] = sum - v;                 // exclusive
    if (threadIdx.x == 255) g_bsum[blockIdx.x] = s[255];
}
__global__ void csr_scan2(int nb) {                  // parallel block-sum scan
    __shared__ int s[512];
    const int t = threadIdx.x;
    int v = (t < nb) ? g_bsum[t] : 0;
    s[t] = v;
    __syncthreads();
    int sum = v;
    #pragma unroll
    for (int off = 1; off < 512; off <<= 1) {
        int u = (t >= off) ? s[t - off] : 0;
        __syncthreads();
        s[t] = sum = sum + u;
        __syncthreads();
    }
    if (t < nb) g_bsum[t] = sum - v;                 // exclusive
}
__global__ void csr_scan3() {
    const int i = blockIdx.x * 256 + threadIdx.x;
    if (i == 0) g_rowp[NN] = ET;
    if (i >= NN) return;
    const int r = g_rowp[i] + g_bsum[i >> 8];
    g_rowp[i] = r;
    g_col[r] = i;                                    // self loop at slot 0
    g_cnt[i] = r + 1;                                // cursor
}
__global__ void csr_fill(const int* __restrict__ ei) {
    const int e = blockIdx.x * 256 + threadIdx.x;
    if (e >= NE) return;
    const int pos = atomicAdd(&g_cnt[ei[NE + e]], 1);
    g_col[pos] = ei[e];
}

// ============ bf16 mma.sync GEMM (single stage, occ 2) ===================
// C[M,NC] = A[M,K] @ W[K,NC]; A, Bt pre-split bf16 hi/lo, Bt = W^T [NC][K].
// 3-term split: Ah*Bh + Al*Bh + Ah*Bl.
// EPI 0: none   EPI 1: +bias, BN, ELU, also write g_hb split   EPI 2: +bias
#define RS  72
#define SMBUF (128 * RS)
#define SMBYTES (4 * SMBUF * 2)        // 73728 -> 2 CTAs/SM

#define CPA(dst32, src, pb) \
    asm volatile("cp.async.cg.shared.global [%0], [%1], 16, %2;" \
                 :: "r"(dst32), "l"(src), "r"(pb))

__device__ __forceinline__ void ldsm_x4(uint32_t* r, uint32_t addr) {
    asm volatile("ldmatrix.sync.aligned.m8n8.x4.shared.b16 {%0,%1,%2,%3}, [%4];"
                 : "=r"(r[0]), "=r"(r[1]), "=r"(r[2]), "=r"(r[3]) : "r"(addr));
}
__device__ __forceinline__ void ldsm_x2(uint32_t* r, uint32_t addr) {
    asm volatile("ldmatrix.sync.aligned.m8n8.x2.shared.b16 {%0,%1}, [%2];"
                 : "=r"(r[0]), "=r"(r[1]) : "r"(addr));
}
__device__ __forceinline__ void mma16816(float* c, const uint32_t* a, const uint32_t* b) {
    asm volatile("mma.sync.aligned.m16n8k16.row.col.f32.bf16.bf16.f32 "
                 "{%0,%1,%2,%3}, {%4,%5,%6,%7}, {%8,%9}, {%0,%1,%2,%3};"
                 : "+f"(c[0]), "+f"(c[1]), "+f"(c[2]), "+f"(c[3])
                 : "r"(a[0]), "r"(a[1]), "r"(a[2]), "r"(a[3]), "r"(b[0]), "r"(b[1]));
}

template<int EPI>
__global__ __launch_bounds__(256, 2)
void hgemm(const __nv_bfloat16* __restrict__ Ath, const __nv_bfloat16* __restrict__ Atl,
           const __nv_bfloat16* __restrict__ Bth, const __nv_bfloat16* __restrict__ Btl,
           float* __restrict__ C, int M, int K, int NC,
           const float* __restrict__ bias, const float* __restrict__ gg,
           const float* __restrict__ gb, const float* __restrict__ gm,
           const float* __restrict__ gv)
{
    extern __shared__ __nv_bfloat16 sm[];
    const uint32_t s32 = smem_u32(sm);
    const int tid = threadIdx.x, lane = tid & 31, w = tid >> 5;
    const int m0 = blockIdx.y * 128, n0 = blockIdx.x * 128;
    const int wm = (w >> 2) * 64, wn = (w & 3) * 32;

    float acc[4][4][4] = {};

    const int nchunks = K >> 6;
    for (int ch = 0; ch < nchunks; ch++) {
        #pragma unroll
        for (int i = 0; i < 4; i++) {
            const int idx = i * 256 + tid, r = idx >> 3, q = idx & 7;
            const uint32_t doff = (uint32_t)(r * RS + q * 8) * 2;
            const size_t aoff = (size_t)(m0 + r) * K + ch * 64 + q * 8;
            const size_t boff = (size_t)(n0 + r) * K + ch * 64 + q * 8;
            const unsigned av = (m0 + r < M) ? 16u : 0u;
            CPA(s32 + doff,                   Ath + aoff, av);
            CPA(s32 + SMBUF * 2 + doff,       Atl + aoff, av);
            CPA(s32 + 2 * SMBUF * 2 + doff,   Bth + boff, 16u);
            CPA(s32 + 3 * SMBUF * 2 + doff,   Btl + boff, 16u);
        }
        asm volatile("cp.async.wait_all;" ::: "memory");
        __syncthreads();

        const int lra = lane & 15, lka = (lane >> 4) * 8;
        const int lrb = lane & 7,  lkb = ((lane >> 3) & 1) * 8;

        #pragma unroll
        for (int ks = 0; ks < 4; ks++) {
            const int k0 = ks * 16;
            uint32_t ah[4][4], al[4][4], bh[4][2], bl[4][2];
            #pragma unroll
            for (int mt = 0; mt < 4; mt++)
                ldsm_x4(ah[mt], s32 + ((wm + mt * 16 + lra) * RS + k0 + lka) * 2);
            #pragma unroll
            for (int nt = 0; nt < 4; nt++)
                ldsm_x2(bh[nt], s32 + (2 * SMBUF + (wn + nt * 8 + lrb) * RS + k0 + lkb) * 2);
            #pragma unroll
            for (int mt = 0; mt < 4; mt++)
                #pragma unroll
                for (int nt = 0; nt < 4; nt++)
                    mma16816(acc[mt][nt], ah[mt], bh[nt]);
            #pragma unroll
            for (int mt = 0; mt < 4; mt++)
                ldsm_x4(al[mt], s32 + (SMBUF + (wm + mt * 16 + lra) * RS + k0 + lka) * 2);
            #pragma unroll
            for (int mt = 0; mt < 4; mt++)
                #pragma unroll
                for (int nt = 0; nt < 4; nt++)
                    mma16816(acc[mt][nt], al[mt], bh[nt]);
            #pragma unroll
            for (int nt = 0; nt < 4; nt++)
                ldsm_x2(bl[nt], s32 + (3 * SMBUF + (wn + nt * 8 + lrb) * RS + k0 + lkb) * 2);
            #pragma unroll
            for (int mt = 0; mt < 4; mt++)
                #pragma unroll
                for (int nt = 0; nt < 4; nt++)
                    mma16816(acc[mt][nt], ah[mt], bl[nt]);
        }
        __syncthreads();
    }

    #pragma unroll
    for (int mt = 0; mt < 4; mt++) {
        #pragma unroll
        for (int nt = 0; nt < 4; nt++) {
            #pragma unroll
            for (int q = 0; q < 4; q++) {
                const int row = m0 + wm + mt * 16 + (lane >> 2) + (q >> 1) * 8;
                const int col = n0 + wn + nt * 8 + 2 * (lane & 3) + (q & 1);
                if (row >= M) continue;
                float v = acc[mt][nt][q];
                if (EPI >= 1) v += bias[col];
                if (EPI == 1) {
                    v = (v - gm[col]) * (gg[col] * rsqrtf(gv[col] + BN_EPS)) + gb[col];
                    v = v > 0.f ? v : expf(v) - 1.f;
                }
                C[(size_t)row * NC + col] = v;
                if (EPI == 1) {
                    __nv_bfloat16 hb, lb;
                    split_bf16(v, hb, lb);
                    g_hbh[(size_t)row * EMB + col] = hb;
                    g_hbl[(size_t)row * EMB + col] = lb;
                }
            }
        }
    }
}

// ====== fused GATv2 aggregation: warp per dst node (CSR, no atomics) =====
__global__ __launch_bounds__(256)
void gat_aggregate(const float* __restrict__ att, const float* __restrict__ cb,
                   const float* __restrict__ bg, const float* __restrict__ bb,
                   const float* __restrict__ bm, const float* __restrict__ bv,
                   float* __restrict__ out_h)
{
    const int lane = threadIdx.x & 31;
    const int n = (blockIdx.x * 256 + threadIdx.x) >> 5;
    if (n >= NN) return;
    const int j0 = lane * 8;

    float sA[8], xr8[8];
    {
        const float4* ap = (const float4*)(att + j0);
        float4 a0 = ap[0], a1 = ap[1];
        sA[0]=a0.x; sA[1]=a0.y; sA[2]=a0.z; sA[3]=a0.w;
        sA[4]=a1.x; sA[5]=a1.y; sA[6]=a1.z; sA[7]=a1.w;
        const float4* rp = (const float4*)(g_xlr + (size_t)n * 512 + 256 + j0);
        float4 r0 = rp[0], r1 = rp[1];
        xr8[0]=r0.x; xr8[1]=r0.y; xr8[2]=r0.z; xr8[3]=r0.w;
        xr8[4]=r1.x; xr8[5]=r1.y; xr8[6]=r1.z; xr8[7]=r1.w;
    }

    float acc[8] = {};
    float den = 0.f;
    const int e0 = g_rowp[n], e1 = g_rowp[n + 1];

    // software-pipelined gather: next edge's row in flight during compute
    int src = g_col[e0];
    const float4* lp = (const float4*)(g_xlr + (size_t)src * 512 + j0);
    float4 c0 = lp[0], c1 = lp[1];
    for (int e = e0; e < e1; e++) {
        const float4 l0 = c0, l1 = c1;
        if (e + 1 < e1) {
            const int s2 = g_col[e + 1];
            const float4* np = (const float4*)(g_xlr + (size_t)s2 * 512 + j0);
            c0 = np[0]; c1 = np[1];
        }
        float xl8[8] = {l0.x, l0.y, l0.z, l0.w, l1.x, l1.y, l1.z, l1.w};
        float part = 0.f;
        #pragma unroll
        for (int u = 0; u < 8; u++) {
            float s = xl8[u] + xr8[u];
            s = s > 0.f ? s : 0.2f * s;
            part += s * sA[u];
        }
        part += __shfl_xor_sync(0xffffffffu, part, 1);
        part += __shfl_xor_sync(0xffffffffu, part, 2);
        part += __shfl_xor_sync(0xffffffffu, part, 4);
        const float p = expf(part);
        den += p;
        #pragma unroll
        for (int u = 0; u < 8; u++) acc[u] += p * xl8[u];
    }

    const float inv = 1.f / den;
    float* hp = g_h + (size_t)n * EMB + j0;
    float4 h0 = ((const float4*)hp)[0], h1 = ((const float4*)hp)[1];
    float hold[8] = {h0.x, h0.y, h0.z, h0.w, h1.x, h1.y, h1.z, h1.w};
    float outv[8];
    #pragma unroll
    for (int u = 0; u < 8; u++) {
        const int j = j0 + u;
        float v = acc[u] * inv + cb[j];
        v = (v - bm[j]) * (bg[j] * rsqrtf(bv[j] + BN_EPS)) + bb[j];
        v = v > 0.f ? v : expf(v) - 1.f;
        outv[u] = hold[u] + v;
    }
    const float4 o0 = make_float4(outv[0], outv[1], outv[2], outv[3]);
    const float4 o1 = make_float4(outv[4], outv[5], outv[6], outv[7]);
    ((float4*)hp)[0] = o0;
    ((float4*)hp)[1] = o1;
    if (out_h) {
        float* op = out_h + (size_t)n * EMB + j0;
        ((float4*)op)[0] = o0;
        ((float4*)op)[1] = o1;
    }
    #pragma unroll
    for (int u = 0; u < 8; u++) {
        __nv_bfloat16 hb, lb;
        split_bf16(outv[u], hb, lb);
        g_hbh[(size_t)n * EMB + j0 + u] = hb;
        g_hbl[(size_t)n * EMB + j0 + u] = lb;
    }
}

// ---------------- heads: preds[k] = h @ head_W[k] + head_b[k] ------------
__global__ void head_kernel(const float* __restrict__ hW, const float* __restrict__ hb,
                            float* __restrict__ out)
{
    __shared__ float sW[4 * EMB];
    for (int i = threadIdx.x; i < 4 * EMB; i += blockDim.x) sW[i] = hW[i];
    __syncthreads();

    const int gw = (blockIdx.x * blockDim.x + threadIdx.x) >> 5;
    const int lane = threadIdx.x & 31;
    if (gw >= NN) return;
    const float* hp = g_h + (size_t)gw * EMB;
    float s0 = 0.f, s1 = 0.f, s2 = 0.f, s3 = 0.f;
    #pragma unroll
    for (int k = 0; k < 8; k++) {
        const int c = lane + k * 32;
        const float hv = hp[c];
        s0 += hv * sW[c];
        s1 += hv * sW[EMB + c];
        s2 += hv * sW[2 * EMB + c];
        s3 += hv * sW[3 * EMB + c];
    }
    #pragma unroll
    for (int off = 16; off; off >>= 1) {
        s0 += __shfl_down_sync(0xffffffffu, s0, off);
        s1 += __shfl_down_sync(0xffffffffu, s1, off);
        s2 += __shfl_down_sync(0xffffffffu, s2, off);
        s3 += __shfl_down_sync(0xffffffffu, s3, off);
    }
    if (lane == 0) {
        out[gw]          = s0 + hb[0];
        out[NN + gw]     = s1 + hb[1];
        out[2 * NN + gw] = s2 + hb[2];
        out[3 * NN + gw] = s3 + hb[3];
    }
}

// ---------------- launch ----------------
extern "C" void kernel_launch(void* const* d_in, const int* in_sizes, int n_in,
                              void* d_out, int out_size)
{
    const float* x      = (const float*)d_in[0];
    const int*   ei     = (const int*)  d_in[1];
    const float* proj_W = (const float*)d_in[2];
    const float* proj_b = (const float*)d_in[3];
    const float* ibn_g  = (const float*)d_in[4];
    const float* ibn_b  = (const float*)d_in[5];
    const float* ibn_m  = (const float*)d_in[6];
    const float* ibn_v  = (const float*)d_in[7];
    const float* Wl     = (const float*)d_in[8];
    const float* Wr     = (const float*)d_in[9];
    const float* att    = (const float*)d_in[10];
    const float* conv_b = (const float*)d_in[11];
    const float* bn_g   = (const float*)d_in[12];
    const float* bn_b   = (const float*)d_in[13];
    const float* bn_m   = (const float*)d_in[14];
    const float* bn_v   = (const float*)d_in[15];
    const float* head_W = (const float*)d_in[16];
    const float* head_b = (const float*)d_in[17];
    const float* dec_W  = (const float*)d_in[18];
    const float* dec_b  = (const float*)d_in[19];
    float* out = (float*)d_out;

    float* h;
    float* xlr;
    cudaGetSymbolAddress((void**)&h,   g_h);
    cudaGetSymbolAddress((void**)&xlr, g_xlr);
    __nv_bfloat16 *hbh, *hbl, *xbh, *xbl, *wth, *wtl, *pjh, *pjl, *dch, *dcl;
    cudaGetSymbolAddress((void**)&hbh, g_hbh);
    cudaGetSymbolAddress((void**)&hbl, g_hbl);
    cudaGetSymbolAddress((void**)&xbh, g_xbh);
    cudaGetSymbolAddress((void**)&xbl, g_xbl);
    cudaGetSymbolAddress((void**)&wth, g_wth);
    cudaGetSymbolAddress((void**)&wtl, g_wtl);
    cudaGetSymbolAddress((void**)&pjh, g_pjh);
    cudaGetSymbolAddress((void**)&pjl, g_pjl);
    cudaGetSymbolAddress((void**)&dch, g_dch);
    cudaGetSymbolAddress((void**)&dcl, g_dcl);

    cudaFuncSetAttribute(hgemm<0>, cudaFuncAttributeMaxDynamicSharedMemorySize, SMBYTES);
    cudaFuncSetAttribute(hgemm<1>, cudaFuncAttributeMaxDynamicSharedMemorySize, SMBYTES);
    cudaFuncSetAttribute(hgemm<2>, cudaFuncAttributeMaxDynamicSharedMemorySize, SMBYTES);

    const int gy = (NN + 127) / 128;          // 782
    const int nb = (NN + 255) / 256;          // 391

    // ---- prep: weights, x split, CSR ----
    prep_weights<<<(INC * EMB + 255) / 256, 256>>>(proj_W, INC, EMB, pjh, pjl);
    prep_wlr<<<(NLAYER * 2 * EMB * EMB + 255) / 256, 256>>>(Wl, Wr);
    prep_weights<<<(EMB * INC + 255) / 256, 256>>>(dec_W, EMB, INC, dch, dcl);
    prep_x<<<(NN * INC + 255) / 256, 256>>>(x);

    csr_zero<<<nb, 256>>>();
    csr_hist<<<(NE + 255) / 256, 256>>>(ei);
    csr_scan1<<<nb, 256>>>();
    csr_scan2<<<1, 512>>>(nb);
    csr_scan3<<<nb, 256>>>();
    csr_fill<<<(NE + 255) / 256, 256>>>(ei);

    // ---- h = elu(bn(x @ proj_W + proj_b)) ----
    hgemm<1><<<dim3(2, gy), 256, SMBYTES>>>(xbh, xbl, pjh, pjl, h, NN, INC, EMB,
                                            proj_b, ibn_g, ibn_b, ibn_m, ibn_v);

    for (int i = 0; i < NLAYER; i++) {
        hgemm<0><<<dim3(4, gy), 256, SMBYTES>>>(hbh, hbl,
                                                wth + (size_t)i * 512 * EMB,
                                                wtl + (size_t)i * 512 * EMB,
                                                xlr, NN, EMB, 512,
                                                nullptr, nullptr, nullptr, nullptr, nullptr);
        gat_aggregate<<<(NN * 32 + 255) / 256, 256>>>(att + (size_t)i * NHEAD * HID,
                                                      conv_b + (size_t)i * EMB,
                                                      bn_g + (size_t)i * EMB, bn_b + (size_t)i * EMB,
                                                      bn_m + (size_t)i * EMB, bn_v + (size_t)i * EMB,
                                                      (i == NLAYER - 1) ? out + (size_t)4 * NN : nullptr);
    }

    // preds (4 x [N]) at out[0 .. 4N)
    head_kernel<<<(NN * 32 + 255) / 256, 256>>>(head_W, head_b, out);
    // recon at out[260N .. 388N)
    hgemm<2><<<dim3(1, gy), 256, SMBYTES>>>(hbh, hbl, dch, dcl, out + (size_t)260 * NN,
                                            NN, EMB, INC, dec_b,
                                            nullptr, nullptr, nullptr, nullptr);
}

// round 9
// speedup vs baseline: 1.0689x; 1.0106x over previous
#include <cuda_runtime.h>
#include <cuda_bf16.h>
#include <math.h>
#include <stdint.h>

#define NN      100000
#define INC     128
#define EMB     256
#define NHEAD   4
#define HID     64
#define NLAYER  3
#define NE      300000
#define ET      400000          // NE + NN self loops
#define BN_EPS  1e-5f

// ---------------- scratch ----------------
__device__ float g_h  [NN * EMB];
__device__ float g_xlr[(size_t)NN * 512];          // cols 0-255: xl, 256-511: xr
__device__ __nv_bfloat16 g_hbh[NN * EMB], g_hbl[NN * EMB];   // h split
__device__ __nv_bfloat16 g_xbh[NN * INC], g_xbl[NN * INC];   // x split
__device__ __nv_bfloat16 g_wth[NLAYER * 512 * EMB], g_wtl[NLAYER * 512 * EMB];
__device__ __nv_bfloat16 g_pjh[EMB * INC], g_pjl[EMB * INC]; // proj^T [256][128]
__device__ __nv_bfloat16 g_dch[INC * EMB], g_dcl[INC * EMB]; // dec^T  [128][256]
// CSR
__device__ int g_cnt[NN];
__device__ int g_rowp[NN + 1];
__device__ int g_col[ET];
__device__ int g_bsum[512];

__device__ __forceinline__ uint32_t smem_u32(const void* p) {
    uint32_t a;
    asm("{ .reg .u64 t; cvta.to.shared.u64 t, %1; cvt.u32.u64 %0, t; }"
        : "=r"(a) : "l"(p));
    return a;
}
__device__ __forceinline__ void split_bf16(float v, __nv_bfloat16& h, __nv_bfloat16& l) {
    h = __float2bfloat16(v);
    l = __float2bfloat16(v - __bfloat162float(h));
}

// ---------------- weight prep ----------------
__global__ void prep_weights(const float* __restrict__ W, int K, int NC,
                             __nv_bfloat16* __restrict__ hi,
                             __nv_bfloat16* __restrict__ lo)
{
    const int idx = blockIdx.x * 256 + threadIdx.x;
    if (idx >= K * NC) return;
    const int k = idx / NC, n = idx - k * NC;
    __nv_bfloat16 h, l;
    split_bf16(W[idx], h, l);
    hi[(size_t)n * K + k] = h;
    lo[(size_t)n * K + k] = l;
}
__global__ void prep_wlr(const float* __restrict__ Wl, const float* __restrict__ Wr)
{
    const int idx = blockIdx.x * 256 + threadIdx.x;   // NLAYER*2*EMB*EMB
    if (idx >= NLAYER * 2 * EMB * EMB) return;
    const int l = idx / (2 * EMB * EMB);
    const int r = idx - l * 2 * EMB * EMB;
    const int sel = r / (EMB * EMB);
    const int t = r - sel * EMB * EMB;
    const int k = t / EMB, n = t - k * EMB;
    const float v = (sel ? Wr : Wl)[(size_t)l * EMB * EMB + t];
    __nv_bfloat16 h, lo;
    split_bf16(v, h, lo);
    const size_t d = (size_t)l * 512 * EMB + (size_t)(sel * 256 + n) * EMB + k;
    g_wth[d] = h;
    g_wtl[d] = lo;
}
// vectorized: float4 in, uint2 (4 bf16) out
__global__ void prep_x(const float* __restrict__ x)
{
    const int idx = blockIdx.x * 256 + threadIdx.x;   // NN*INC/4
    if (idx >= NN * INC / 4) return;
    const float4 v = ((const float4*)x)[idx];
    __nv_bfloat16 h0, h1, h2, h3, l0, l1, l2, l3;
    split_bf16(v.x, h0, l0); split_bf16(v.y, h1, l1);
    split_bf16(v.z, h2, l2); split_bf16(v.w, h3, l3);
    uint2 hp, lp;
    hp.x = ((uint32_t)__bfloat16_as_ushort(h1) << 16) | __bfloat16_as_ushort(h0);
    hp.y = ((uint32_t)__bfloat16_as_ushort(h3) << 16) | __bfloat16_as_ushort(h2);
    lp.x = ((uint32_t)__bfloat16_as_ushort(l1) << 16) | __bfloat16_as_ushort(l0);
    lp.y = ((uint32_t)__bfloat16_as_ushort(l3) << 16) | __bfloat16_as_ushort(l2);
    ((uint2*)g_xbh)[idx] = hp;
    ((uint2*)g_xbl)[idx] = lp;
}

// ---------------- CSR build ----------------
__global__ void csr_zero() {
    const int i = blockIdx.x * 256 + threadIdx.x;
    if (i < NN) g_cnt[i] = 1;                        // self loop
}
__global__ void csr_hist(const int* __restrict__ ei) {
    const int e = blockIdx.x * 256 + threadIdx.x;
    if (e < NE) atomicAdd(&g_cnt[ei[NE + e]], 1);
}
__global__ void csr_scan1() {
    __shared__ int s[256];
    const int i = blockIdx.x * 256 + threadIdx.x;
    int v = (i < NN) ? g_cnt[i] : 0;
    s[threadIdx.x] = v;
    __syncthreads();
    int sum = v;
    #pragma unroll
    for (int off = 1; off < 256; off <<= 1) {
        int t = (threadIdx.x >= off) ? s[threadIdx.x - off] : 0;
        __syncthreads();
        s[threadIdx.x] = sum = sum + t;
        __syncthreads();
    }
    if (i < NN) g_rowp[i] = sum - v;
    if (threadIdx.x == 255) g_bsum[blockIdx.x] = s[255];
}
__global__ void csr_scan2(int nb) {
    __shared__ int s[512];
    const int t = threadIdx.x;
    int v = (t < nb) ? g_bsum[t] : 0;
    s[t] = v;
    __syncthreads();
    int sum = v;
    #pragma unroll
    for (int off = 1; off < 512; off <<= 1) {
        int u = (t >= off) ? s[t - off] : 0;
        __syncthreads();
        s[t] = sum = sum + u;
        __syncthreads();
    }
    if (t < nb) g_bsum[t] = sum - v;
}
__global__ void csr_scan3() {
    const int i = blockIdx.x * 256 + threadIdx.x;
    if (i == 0) g_rowp[NN] = ET;
    if (i >= NN) return;
    const int r = g_rowp[i] + g_bsum[i >> 8];
    g_rowp[i] = r;
    g_col[r] = i;
    g_cnt[i] = r + 1;
}
__global__ void csr_fill(const int* __restrict__ ei) {
    const int e = blockIdx.x * 256 + threadIdx.x;
    if (e >= NE) return;
    const int pos = atomicAdd(&g_cnt[ei[NE + e]], 1);
    g_col[pos] = ei[e];
}

// ====== bf16 mma.sync GEMM: 2-stage BK=32 pipeline, occ 2 ================
// C[M,NC] = A[M,K] @ W[K,NC]; A, Bt pre-split bf16 hi/lo, Bt = W^T [NC][K].
// 3-term split: Ah*Bh + Al*Bh + Ah*Bl.
#define RS2 40                          // row stride (elems): 80B, 16B-aligned
#define BUF2 (128 * RS2)                // elems per operand buffer
#define BUFB (BUF2 * 2)                 // 10240 bytes
#define STAGEB (4 * BUFB)               // 40960 bytes
#define SMBYTES (2 * STAGEB)            // 81920 -> occ 2

#define CPA(dst32, src, pb) \
    asm volatile("cp.async.cg.shared.global [%0], [%1], 16, %2;" \
                 :: "r"(dst32), "l"(src), "r"(pb))

__device__ __forceinline__ void ldsm_x4(uint32_t* r, uint32_t addr) {
    asm volatile("ldmatrix.sync.aligned.m8n8.x4.shared.b16 {%0,%1,%2,%3}, [%4];"
                 : "=r"(r[0]), "=r"(r[1]), "=r"(r[2]), "=r"(r[3]) : "r"(addr));
}
__device__ __forceinline__ void ldsm_x2(uint32_t* r, uint32_t addr) {
    asm volatile("ldmatrix.sync.aligned.m8n8.x2.shared.b16 {%0,%1}, [%2];"
                 : "=r"(r[0]), "=r"(r[1]) : "r"(addr));
}
__device__ __forceinline__ void mma16816(float* c, const uint32_t* a, const uint32_t* b) {
    asm volatile("mma.sync.aligned.m16n8k16.row.col.f32.bf16.bf16.f32 "
                 "{%0,%1,%2,%3}, {%4,%5,%6,%7}, {%8,%9}, {%0,%1,%2,%3};"
                 : "+f"(c[0]), "+f"(c[1]), "+f"(c[2]), "+f"(c[3])
                 : "r"(a[0]), "r"(a[1]), "r"(a[2]), "r"(a[3]), "r"(b[0]), "r"(b[1]));
}

template<int EPI>
__global__ __launch_bounds__(256, 2)
void hgemm(const __nv_bfloat16* __restrict__ Ath, const __nv_bfloat16* __restrict__ Atl,
           const __nv_bfloat16* __restrict__ Bth, const __nv_bfloat16* __restrict__ Btl,
           float* __restrict__ C, int M, int K, int NC,
           const float* __restrict__ bias, const float* __restrict__ gg,
           const float* __restrict__ gb, const float* __restrict__ gm,
           const float* __restrict__ gv)
{
    extern __shared__ __nv_bfloat16 sm[];
    const uint32_t s32 = smem_u32(sm);
    const int tid = threadIdx.x, lane = tid & 31, w = tid >> 5;
    const int m0 = blockIdx.y * 128, n0 = blockIdx.x * 128;
    const int wm = (w >> 2) * 64, wn = (w & 3) * 32;

    float acc[4][4][4] = {};
    const int nchunks = K >> 5;

    const __nv_bfloat16* srcs[4] = {Ath, Atl, Bth, Btl};

    auto load_chunk = [&](int ch, int st) {
        const uint32_t sb = s32 + (uint32_t)st * STAGEB;
        #pragma unroll
        for (int i = 0; i < 8; i++) {
            const int buf = i >> 1;
            const int s = (i & 1) * 256 + tid;          // 0..511 per buffer
            const int r = s >> 2, q = s & 3;
            const int base = (buf < 2) ? m0 : n0;
            const uint32_t doff = (uint32_t)buf * BUFB + (uint32_t)(r * RS2 + q * 8) * 2;
            const size_t goff = (size_t)(base + r) * K + ch * 32 + q * 8;
            const unsigned pb = (buf >= 2 || base + r < M) ? 16u : 0u;
            CPA(sb + doff, srcs[buf] + goff, pb);
        }
        asm volatile("cp.async.commit_group;" ::: "memory");
    };

    load_chunk(0, 0);

    for (int ch = 0; ch < nchunks; ch++) {
        if (ch + 1 < nchunks) {
            load_chunk(ch + 1, (ch + 1) & 1);
            asm volatile("cp.async.wait_group 1;" ::: "memory");
        } else {
            asm volatile("cp.async.wait_group 0;" ::: "memory");
        }
        __syncthreads();

        const uint32_t sb = s32 + (uint32_t)(ch & 1) * STAGEB;
        const int lra = lane & 15, lka = (lane >> 4) * 8;
        const int lrb = lane & 7,  lkb = ((lane >> 3) & 1) * 8;

        #pragma unroll
        for (int ks = 0; ks < 2; ks++) {
            const int k0 = ks * 16;
            uint32_t ah[4][4], al[4][4], bh[4][2], bl[4][2];
            #pragma unroll
            for (int mt = 0; mt < 4; mt++)
                ldsm_x4(ah[mt], sb + ((wm + mt * 16 + lra) * RS2 + k0 + lka) * 2);
            #pragma unroll
            for (int nt = 0; nt < 4; nt++)
                ldsm_x2(bh[nt], sb + 2 * BUFB + ((wn + nt * 8 + lrb) * RS2 + k0 + lkb) * 2);
            #pragma unroll
            for (int mt = 0; mt < 4; mt++)
                #pragma unroll
                for (int nt = 0; nt < 4; nt++)
                    mma16816(acc[mt][nt], ah[mt], bh[nt]);
            #pragma unroll
            for (int mt = 0; mt < 4; mt++)
                ldsm_x4(al[mt], sb + BUFB + ((wm + mt * 16 + lra) * RS2 + k0 + lka) * 2);
            #pragma unroll
            for (int mt = 0; mt < 4; mt++)
                #pragma unroll
                for (int nt = 0; nt < 4; nt++)
                    mma16816(acc[mt][nt], al[mt], bh[nt]);
            #pragma unroll
            for (int nt = 0; nt < 4; nt++)
                ldsm_x2(bl[nt], sb + 3 * BUFB + ((wn + nt * 8 + lrb) * RS2 + k0 + lkb) * 2);
            #pragma unroll
            for (int mt = 0; mt < 4; mt++)
                #pragma unroll
                for (int nt = 0; nt < 4; nt++)
                    mma16816(acc[mt][nt], ah[mt], bl[nt]);
        }
        __syncthreads();
    }

    #pragma unroll
    for (int mt = 0; mt < 4; mt++) {
        #pragma unroll
        for (int nt = 0; nt < 4; nt++) {
            #pragma unroll
            for (int q = 0; q < 4; q++) {
                const int row = m0 + wm + mt * 16 + (lane >> 2) + (q >> 1) * 8;
                const int col = n0 + wn + nt * 8 + 2 * (lane & 3) + (q & 1);
                if (row >= M) continue;
                float v = acc[mt][nt][q];
                if (EPI >= 1) v += bias[col];
                if (EPI == 1) {
                    v = (v - gm[col]) * (gg[col] * rsqrtf(gv[col] + BN_EPS)) + gb[col];
                    v = v > 0.f ? v : __expf(v) - 1.f;
                }
                C[(size_t)row * NC + col] = v;
                if (EPI == 1) {
                    __nv_bfloat16 hb, lb;
                    split_bf16(v, hb, lb);
                    g_hbh[(size_t)row * EMB + col] = hb;
                    g_hbl[(size_t)row * EMB + col] = lb;
                }
            }
        }
    }
}

// ====== fused GATv2 aggregation: warp per dst node (CSR, no atomics) =====
__global__ __launch_bounds__(256)
void gat_aggregate(const float* __restrict__ att, const float* __restrict__ cb,
                   const float* __restrict__ bg, const float* __restrict__ bb,
                   const float* __restrict__ bm, const float* __restrict__ bv,
                   float* __restrict__ out_h)
{
    const int lane = threadIdx.x & 31;
    const int n = (blockIdx.x * 256 + threadIdx.x) >> 5;
    if (n >= NN) return;
    const int j0 = lane * 8;

    float sA[8], xr8[8];
    {
        const float4* ap = (const float4*)(att + j0);
        float4 a0 = ap[0], a1 = ap[1];
        sA[0]=a0.x; sA[1]=a0.y; sA[2]=a0.z; sA[3]=a0.w;
        sA[4]=a1.x; sA[5]=a1.y; sA[6]=a1.z; sA[7]=a1.w;
        const float4* rp = (const float4*)(g_xlr + (size_t)n * 512 + 256 + j0);
        float4 r0 = rp[0], r1 = rp[1];
        xr8[0]=r0.x; xr8[1]=r0.y; xr8[2]=r0.z; xr8[3]=r0.w;
        xr8[4]=r1.x; xr8[5]=r1.y; xr8[6]=r1.z; xr8[7]=r1.w;
    }

    float acc[8] = {};
    float den = 0.f;
    const int e0 = g_rowp[n], e1 = g_rowp[n + 1];

    // distance-2 software pipeline on the gather
    float4 c0, c1, d0, d1;
    {
        const float4* p = (const float4*)(g_xlr + (size_t)g_col[e0] * 512 + j0);
        c0 = p[0]; c1 = p[1];
        if (e0 + 1 < e1) {
            const float4* p2 = (const float4*)(g_xlr + (size_t)g_col[e0 + 1] * 512 + j0);
            d0 = p2[0]; d1 = p2[1];
        }
    }
    for (int e = e0; e < e1; e++) {
        const float4 l0 = c0, l1 = c1;
        c0 = d0; c1 = d1;
        if (e + 2 < e1) {
            const float4* np = (const float4*)(g_xlr + (size_t)g_col[e + 2] * 512 + j0);
            d0 = np[0]; d1 = np[1];
        }
        float xl8[8] = {l0.x, l0.y, l0.z, l0.w, l1.x, l1.y, l1.z, l1.w};
        float part = 0.f;
        #pragma unroll
        for (int u = 0; u < 8; u++) {
            float s = xl8[u] + xr8[u];
            s = s > 0.f ? s : 0.2f * s;
            part += s * sA[u];
        }
        part += __shfl_xor_sync(0xffffffffu, part, 1);
        part += __shfl_xor_sync(0xffffffffu, part, 2);
        part += __shfl_xor_sync(0xffffffffu, part, 4);
        const float p = __expf(part);
        den += p;
        #pragma unroll
        for (int u = 0; u < 8; u++) acc[u] += p * xl8[u];
    }

    const float inv = 1.f / den;
    float* hp = g_h + (size_t)n * EMB + j0;
    float4 h0 = ((const float4*)hp)[0], h1 = ((const float4*)hp)[1];
    float hold[8] = {h0.x, h0.y, h0.z, h0.w, h1.x, h1.y, h1.z, h1.w};
    float outv[8];
    #pragma unroll
    for (int u = 0; u < 8; u++) {
        const int j = j0 + u;
        float v = acc[u] * inv + cb[j];
        v = (v - bm[j]) * (bg[j] * rsqrtf(bv[j] + BN_EPS)) + bb[j];
        v = v > 0.f ? v : __expf(v) - 1.f;
        outv[u] = hold[u] + v;
    }
    const float4 o0 = make_float4(outv[0], outv[1], outv[2], outv[3]);
    const float4 o1 = make_float4(outv[4], outv[5], outv[6], outv[7]);
    ((float4*)hp)[0] = o0;
    ((float4*)hp)[1] = o1;
    if (out_h) {
        float* op = out_h + (size_t)n * EMB + j0;
        ((float4*)op)[0] = o0;
        ((float4*)op)[1] = o1;
    }
    #pragma unroll
    for (int u = 0; u < 8; u++) {
        __nv_bfloat16 hb, lb;
        split_bf16(outv[u], hb, lb);
        g_hbh[(size_t)n * EMB + j0 + u] = hb;
        g_hbl[(size_t)n * EMB + j0 + u] = lb;
    }
}

// ---------------- heads ----------------
__global__ void head_kernel(const float* __restrict__ hW, const float* __restrict__ hb,
                            float* __restrict__ out)
{
    __shared__ float sW[4 * EMB];
    for (int i = threadIdx.x; i < 4 * EMB; i += blockDim.x) sW[i] = hW[i];
    __syncthreads();

    const int gw = (blockIdx.x * blockDim.x + threadIdx.x) >> 5;
    const int lane = threadIdx.x & 31;
    if (gw >= NN) return;
    const float* hp = g_h + (size_t)gw * EMB;
    float s0 = 0.f, s1 = 0.f, s2 = 0.f, s3 = 0.f;
    #pragma unroll
    for (int k = 0; k < 8; k++) {
        const int c = lane + k * 32;
        const float hv = hp[c];
        s0 += hv * sW[c];
        s1 += hv * sW[EMB + c];
        s2 += hv * sW[2 * EMB + c];
        s3 += hv * sW[3 * EMB + c];
    }
    #pragma unroll
    for (int off = 16; off; off >>= 1) {
        s0 += __shfl_down_sync(0xffffffffu, s0, off);
        s1 += __shfl_down_sync(0xffffffffu, s1, off);
        s2 += __shfl_down_sync(0xffffffffu, s2, off);
        s3 += __shfl_down_sync(0xffffffffu, s3, off);
    }
    if (lane == 0) {
        out[gw]          = s0 + hb[0];
        out[NN + gw]     = s1 + hb[1];
        out[2 * NN + gw] = s2 + hb[2];
        out[3 * NN + gw] = s3 + hb[3];
    }
}

// ---------------- launch ----------------
extern "C" void kernel_launch(void* const* d_in, const int* in_sizes, int n_in,
                              void* d_out, int out_size)
{
    const float* x      = (const float*)d_in[0];
    const int*   ei     = (const int*)  d_in[1];
    const float* proj_W = (const float*)d_in[2];
    const float* proj_b = (const float*)d_in[3];
    const float* ibn_g  = (const float*)d_in[4];
    const float* ibn_b  = (const float*)d_in[5];
    const float* ibn_m  = (const float*)d_in[6];
    const float* ibn_v  = (const float*)d_in[7];
    const float* Wl     = (const float*)d_in[8];
    const float* Wr     = (const float*)d_in[9];
    const float* att    = (const float*)d_in[10];
    const float* conv_b = (const float*)d_in[11];
    const float* bn_g   = (const float*)d_in[12];
    const float* bn_b   = (const float*)d_in[13];
    const float* bn_m   = (const float*)d_in[14];
    const float* bn_v   = (const float*)d_in[15];
    const float* head_W = (const float*)d_in[16];
    const float* head_b = (const float*)d_in[17];
    const float* dec_W  = (const float*)d_in[18];
    const float* dec_b  = (const float*)d_in[19];
    float* out = (float*)d_out;

    float* h;
    float* xlr;
    cudaGetSymbolAddress((void**)&h,   g_h);
    cudaGetSymbolAddress((void**)&xlr, g_xlr);
    __nv_bfloat16 *hbh, *hbl, *xbh, *xbl, *wth, *wtl, *pjh, *pjl, *dch, *dcl;
    cudaGetSymbolAddress((void**)&hbh, g_hbh);
    cudaGetSymbolAddress((void**)&hbl, g_hbl);
    cudaGetSymbolAddress((void**)&xbh, g_xbh);
    cudaGetSymbolAddress((void**)&xbl, g_xbl);
    cudaGetSymbolAddress((void**)&wth, g_wth);
    cudaGetSymbolAddress((void**)&wtl, g_wtl);
    cudaGetSymbolAddress((void**)&pjh, g_pjh);
    cudaGetSymbolAddress((void**)&pjl, g_pjl);
    cudaGetSymbolAddress((void**)&dch, g_dch);
    cudaGetSymbolAddress((void**)&dcl, g_dcl);

    cudaFuncSetAttribute(hgemm<0>, cudaFuncAttributeMaxDynamicSharedMemorySize, SMBYTES);
    cudaFuncSetAttribute(hgemm<1>, cudaFuncAttributeMaxDynamicSharedMemorySize, SMBYTES);
    cudaFuncSetAttribute(hgemm<2>, cudaFuncAttributeMaxDynamicSharedMemorySize, SMBYTES);

    const int gy = (NN + 127) / 128;          // 782
    const int nb = (NN + 255) / 256;          // 391

    // ---- prep: weights, x split, CSR ----
    prep_weights<<<(INC * EMB + 255) / 256, 256>>>(proj_W, INC, EMB, pjh, pjl);
    prep_wlr<<<(NLAYER * 2 * EMB * EMB + 255) / 256, 256>>>(Wl, Wr);
    prep_weights<<<(EMB * INC + 255) / 256, 256>>>(dec_W, EMB, INC, dch, dcl);
    prep_x<<<(NN * INC / 4 + 255) / 256, 256>>>(x);

    csr_zero<<<nb, 256>>>();
    csr_hist<<<(NE + 255) / 256, 256>>>(ei);
    csr_scan1<<<nb, 256>>>();
    csr_scan2<<<1, 512>>>(nb);
    csr_scan3<<<nb, 256>>>();
    csr_fill<<<(NE + 255) / 256, 256>>>(ei);

    // ---- h = elu(bn(x @ proj_W + proj_b)) ----
    hgemm<1><<<dim3(2, gy), 256, SMBYTES>>>(xbh, xbl, pjh, pjl, h, NN, INC, EMB,
                                            proj_b, ibn_g, ibn_b, ibn_m, ibn_v);

    for (int i = 0; i < NLAYER; i++) {
        hgemm<0><<<dim3(4, gy), 256, SMBYTES>>>(hbh, hbl,
                                                wth + (size_t)i * 512 * EMB,
                                                wtl + (size_t)i * 512 * EMB,
                                                xlr, NN, EMB, 512,
                                                nullptr, nullptr, nullptr, nullptr, nullptr);
        gat_aggregate<<<(NN * 32 + 255) / 256, 256>>>(att + (size_t)i * NHEAD * HID,
                                                      conv_b + (size_t)i * EMB,
                                                      bn_g + (size_t)i * EMB, bn_b + (size_t)i * EMB,
                                                      bn_m + (size_t)i * EMB, bn_v + (size_t)i * EMB,
                                                      (i == NLAYER - 1) ? out + (size_t)4 * NN : nullptr);
    }

    // preds (4 x [N]) at out[0 .. 4N)
    head_kernel<<<(NN * 32 + 255) / 256, 256>>>(head_W, head_b, out);
    // recon at out[260N .. 388N)
    hgemm<2><<<dim3(1, gy), 256, SMBYTES>>>(hbh, hbl, dch, dcl, out + (size_t)260 * NN,
                                            NN, EMB, INC, dec_b,
                                            nullptr, nullptr, nullptr, nullptr);
}

// round 10
// speedup vs baseline: 1.1854x; 1.1090x over previous
#include <cuda_runtime.h>
#include <cuda_bf16.h>
#include <math.h>
#include <stdint.h>

#define NN      100000
#define INC     128
#define EMB     256
#define NHEAD   4
#define HID     64
#define NLAYER  3
#define NE      300000
#define ET      400000          // NE + NN self loops
#define BN_EPS  1e-5f

// ---------------- scratch ----------------
__device__ float g_h  [NN * EMB];
__device__ float g_xlr[(size_t)NN * 512];          // cols 0-255: xl, 256-511: xr
__device__ __nv_bfloat16 g_hbh[NN * EMB], g_hbl[NN * EMB];   // h split
__device__ __nv_bfloat16 g_xbh[NN * INC], g_xbl[NN * INC];   // x split
__device__ __nv_bfloat16 g_wth[NLAYER * 512 * EMB], g_wtl[NLAYER * 512 * EMB];
__device__ __nv_bfloat16 g_pjh[EMB * INC], g_pjl[EMB * INC]; // proj^T [256][128]
__device__ __nv_bfloat16 g_dch[INC * EMB], g_dcl[INC * EMB]; // dec^T  [128][256]
// CSR
__device__ int g_cnt[NN];
__device__ int g_rowp[NN + 1];
__device__ int g_col[ET];
__device__ int g_bsum[512];

__device__ __forceinline__ uint32_t smem_u32(const void* p) {
    uint32_t a;
    asm("{ .reg .u64 t; cvta.to.shared.u64 t, %1; cvt.u32.u64 %0, t; }"
        : "=r"(a) : "l"(p));
    return a;
}
__device__ __forceinline__ void split_bf16(float v, __nv_bfloat16& h, __nv_bfloat16& l) {
    h = __float2bfloat16(v);
    l = __float2bfloat16(v - __bfloat162float(h));
}

// ---------------- weight prep ----------------
__global__ void prep_weights(const float* __restrict__ W, int K, int NC,
                             __nv_bfloat16* __restrict__ hi,
                             __nv_bfloat16* __restrict__ lo)
{
    const int idx = blockIdx.x * 256 + threadIdx.x;
    if (idx >= K * NC) return;
    const int k = idx / NC, n = idx - k * NC;
    __nv_bfloat16 h, l;
    split_bf16(W[idx], h, l);
    hi[(size_t)n * K + k] = h;
    lo[(size_t)n * K + k] = l;
}
__global__ void prep_wlr(const float* __restrict__ Wl, const float* __restrict__ Wr)
{
    const int idx = blockIdx.x * 256 + threadIdx.x;   // NLAYER*2*EMB*EMB
    if (idx >= NLAYER * 2 * EMB * EMB) return;
    const int l = idx / (2 * EMB * EMB);
    const int r = idx - l * 2 * EMB * EMB;
    const int sel = r / (EMB * EMB);
    const int t = r - sel * EMB * EMB;
    const int k = t / EMB, n = t - k * EMB;
    const float v = (sel ? Wr : Wl)[(size_t)l * EMB * EMB + t];
    __nv_bfloat16 h, lo;
    split_bf16(v, h, lo);
    const size_t d = (size_t)l * 512 * EMB + (size_t)(sel * 256 + n) * EMB + k;
    g_wth[d] = h;
    g_wtl[d] = lo;
}
// vectorized x split + csr_zero folded in
__global__ void prep_x(const float* __restrict__ x)
{
    const int idx = blockIdx.x * 256 + threadIdx.x;   // NN*INC/4
    if (idx < NN) g_cnt[idx] = 1;                     // self-loop count
    if (idx >= NN * INC / 4) return;
    const float4 v = ((const float4*)x)[idx];
    __nv_bfloat16 h0, h1, h2, h3, l0, l1, l2, l3;
    split_bf16(v.x, h0, l0); split_bf16(v.y, h1, l1);
    split_bf16(v.z, h2, l2); split_bf16(v.w, h3, l3);
    uint2 hp, lp;
    hp.x = ((uint32_t)__bfloat16_as_ushort(h1) << 16) | __bfloat16_as_ushort(h0);
    hp.y = ((uint32_t)__bfloat16_as_ushort(h3) << 16) | __bfloat16_as_ushort(h2);
    lp.x = ((uint32_t)__bfloat16_as_ushort(l1) << 16) | __bfloat16_as_ushort(l0);
    lp.y = ((uint32_t)__bfloat16_as_ushort(l3) << 16) | __bfloat16_as_ushort(l2);
    ((uint2*)g_xbh)[idx] = hp;
    ((uint2*)g_xbl)[idx] = lp;
}

// ---------------- CSR build ----------------
__global__ void csr_hist(const int* __restrict__ ei) {
    const int e = blockIdx.x * 256 + threadIdx.x;
    if (e < NE) atomicAdd(&g_cnt[ei[NE + e]], 1);
}
__global__ void csr_scan1() {
    __shared__ int s[256];
    const int i = blockIdx.x * 256 + threadIdx.x;
    int v = (i < NN) ? g_cnt[i] : 0;
    s[threadIdx.x] = v;
    __syncthreads();
    int sum = v;
    #pragma unroll
    for (int off = 1; off < 256; off <<= 1) {
        int t = (threadIdx.x >= off) ? s[threadIdx.x - off] : 0;
        __syncthreads();
        s[threadIdx.x] = sum = sum + t;
        __syncthreads();
    }
    if (i < NN) g_rowp[i] = sum - v;
    if (threadIdx.x == 255) g_bsum[blockIdx.x] = s[255];
}
__global__ void csr_scan2(int nb) {
    __shared__ int s[512];
    const int t = threadIdx.x;
    int v = (t < nb) ? g_bsum[t] : 0;
    s[t] = v;
    __syncthreads();
    int sum = v;
    #pragma unroll
    for (int off = 1; off < 512; off <<= 1) {
        int u = (t >= off) ? s[t - off] : 0;
        __syncthreads();
        s[t] = sum = sum + u;
        __syncthreads();
    }
    if (t < nb) g_bsum[t] = sum - v;
}
__global__ void csr_scan3() {
    const int i = blockIdx.x * 256 + threadIdx.x;
    if (i == 0) g_rowp[NN] = ET;
    if (i >= NN) return;
    const int r = g_rowp[i] + g_bsum[i >> 8];
    g_rowp[i] = r;
    g_col[r] = i;
    g_cnt[i] = r + 1;
}
__global__ void csr_fill(const int* __restrict__ ei) {
    const int e = blockIdx.x * 256 + threadIdx.x;
    if (e >= NE) return;
    const int pos = atomicAdd(&g_cnt[ei[NE + e]], 1);
    g_col[pos] = ei[e];
}

// ====== bf16 mma.sync GEMM: 2-stage BK=32 pipeline, occ 2 ================
// C[M,NC] = A[M,K] @ W[K,NC]; A, Bt pre-split bf16 hi/lo, Bt = W^T [NC][K].
// xl/proj/dec blocks: 3-term split (Ah*Bh + Al*Bh + Ah*Bl).
// xr blocks (EPI==0, n0>=256): single-term Ah*Bh (attention-logit path only;
// softmax damps the 2^-9 error to ~1e-5 on the output).
#define RS2 40                          // row stride (elems): 80B, 16B-aligned
#define BUF2 (128 * RS2)
#define BUFB (BUF2 * 2)                 // 10240 bytes
#define STAGEB (4 * BUFB)               // 40960 bytes
#define SMBYTES (2 * STAGEB)            // 81920 -> occ 2

#define CPA(dst32, src, pb) \
    asm volatile("cp.async.cg.shared.global [%0], [%1], 16, %2;" \
                 :: "r"(dst32), "l"(src), "r"(pb))

__device__ __forceinline__ void ldsm_x4(uint32_t* r, uint32_t addr) {
    asm volatile("ldmatrix.sync.aligned.m8n8.x4.shared.b16 {%0,%1,%2,%3}, [%4];"
                 : "=r"(r[0]), "=r"(r[1]), "=r"(r[2]), "=r"(r[3]) : "r"(addr));
}
__device__ __forceinline__ void mma16816(float* c, const uint32_t* a, const uint32_t* b) {
    asm volatile("mma.sync.aligned.m16n8k16.row.col.f32.bf16.bf16.f32 "
                 "{%0,%1,%2,%3}, {%4,%5,%6,%7}, {%8,%9}, {%0,%1,%2,%3};"
                 : "+f"(c[0]), "+f"(c[1]), "+f"(c[2]), "+f"(c[3])
                 : "r"(a[0]), "r"(a[1]), "r"(a[2]), "r"(a[3]), "r"(b[0]), "r"(b[1]));
}

template<int EPI>
__global__ __launch_bounds__(256, 2)
void hgemm(const __nv_bfloat16* __restrict__ Ath, const __nv_bfloat16* __restrict__ Atl,
           const __nv_bfloat16* __restrict__ Bth, const __nv_bfloat16* __restrict__ Btl,
           float* __restrict__ C, int M, int K, int NC,
           const float* __restrict__ bias, const float* __restrict__ gg,
           const float* __restrict__ gb, const float* __restrict__ gm,
           const float* __restrict__ gv)
{
    extern __shared__ __nv_bfloat16 sm[];
    const uint32_t s32 = smem_u32(sm);
    const int tid = threadIdx.x, lane = tid & 31, w = tid >> 5;
    const int m0 = blockIdx.y * 128, n0 = blockIdx.x * 128;
    const int wm = (w >> 2) * 64, wn = (w & 3) * 32;

    const bool full = (EPI != 0) || (n0 < 256);   // xr blocks: single term

    float acc[4][4][4] = {};
    const int nchunks = K >> 5;

    const __nv_bfloat16* srcs[4] = {Ath, Atl, Bth, Btl};

    auto load_chunk = [&](int ch, int st) {
        const uint32_t sb = s32 + (uint32_t)st * STAGEB;
        #pragma unroll
        for (int i = 0; i < 8; i++) {
            const int buf = i >> 1;
            if (!full && (buf & 1)) continue;        // skip lo buffers
            const int s = (i & 1) * 256 + tid;
            const int r = s >> 2, q = s & 3;
            const int base = (buf < 2) ? m0 : n0;
            const uint32_t doff = (uint32_t)buf * BUFB + (uint32_t)(r * RS2 + q * 8) * 2;
            const size_t goff = (size_t)(base + r) * K + ch * 32 + q * 8;
            const unsigned pb = (buf >= 2 || base + r < M) ? 16u : 0u;
            CPA(sb + doff, srcs[buf] + goff, pb);
        }
        asm volatile("cp.async.commit_group;" ::: "memory");
    };

    load_chunk(0, 0);

    for (int ch = 0; ch < nchunks; ch++) {
        if (ch + 1 < nchunks) {
            load_chunk(ch + 1, (ch + 1) & 1);
            asm volatile("cp.async.wait_group 1;" ::: "memory");
        } else {
            asm volatile("cp.async.wait_group 0;" ::: "memory");
        }
        __syncthreads();

        const uint32_t sb = s32 + (uint32_t)(ch & 1) * STAGEB;
        const int lra = lane & 15, lka = (lane >> 4) * 8;
        // B x4 lane map: 4 tiles = (rows, k0), (rows, k0+8), (rows+8, k0), (rows+8, k0+8)
        const int bt = lane >> 3, blr = lane & 7;

        #pragma unroll
        for (int ks = 0; ks < 2; ks++) {
            const int k0 = ks * 16;
            uint32_t ah[4][4], bh[4][2];
            #pragma unroll
            for (int mt = 0; mt < 4; mt++)
                ldsm_x4(ah[mt], sb + ((wm + mt * 16 + lra) * RS2 + k0 + lka) * 2);
            #pragma unroll
            for (int ntp = 0; ntp < 2; ntp++) {
                const int row = wn + ntp * 16 + ((bt >> 1) << 3) + blr;
                const int col = k0 + (bt & 1) * 8;
                ldsm_x4(&bh[ntp * 2][0], sb + 2 * BUFB + (row * RS2 + col) * 2);
            }
            #pragma unroll
            for (int mt = 0; mt < 4; mt++)
                #pragma unroll
                for (int nt = 0; nt < 4; nt++)
                    mma16816(acc[mt][nt], ah[mt], bh[nt]);

            if (full) {
                uint32_t al[4][4], bl[4][2];
                #pragma unroll
                for (int mt = 0; mt < 4; mt++)
                    ldsm_x4(al[mt], sb + BUFB + ((wm + mt * 16 + lra) * RS2 + k0 + lka) * 2);
                #pragma unroll
                for (int mt = 0; mt < 4; mt++)
                    #pragma unroll
                    for (int nt = 0; nt < 4; nt++)
                        mma16816(acc[mt][nt], al[mt], bh[nt]);
                #pragma unroll
                for (int ntp = 0; ntp < 2; ntp++) {
                    const int row = wn + ntp * 16 + ((bt >> 1) << 3) + blr;
                    const int col = k0 + (bt & 1) * 8;
                    ldsm_x4(&bl[ntp * 2][0], sb + 3 * BUFB + (row * RS2 + col) * 2);
                }
                #pragma unroll
                for (int mt = 0; mt < 4; mt++)
                    #pragma unroll
                    for (int nt = 0; nt < 4; nt++)
                        mma16816(acc[mt][nt], ah[mt], bl[nt]);
            }
        }
        __syncthreads();
    }

    #pragma unroll
    for (int mt = 0; mt < 4; mt++) {
        #pragma unroll
        for (int nt = 0; nt < 4; nt++) {
            #pragma unroll
            for (int q = 0; q < 4; q++) {
                const int row = m0 + wm + mt * 16 + (lane >> 2) + (q >> 1) * 8;
                const int col = n0 + wn + nt * 8 + 2 * (lane & 3) + (q & 1);
                if (row >= M) continue;
                float v = acc[mt][nt][q];
                if (EPI >= 1) v += bias[col];
                if (EPI == 1) {
                    v = (v - gm[col]) * (gg[col] * rsqrtf(gv[col] + BN_EPS)) + gb[col];
                    v = v > 0.f ? v : __expf(v) - 1.f;
                }
                C[(size_t)row * NC + col] = v;
                if (EPI == 1) {
                    __nv_bfloat16 hb, lb;
                    split_bf16(v, hb, lb);
                    g_hbh[(size_t)row * EMB + col] = hb;
                    g_hbl[(size_t)row * EMB + col] = lb;
                }
            }
        }
    }
}

// ====== fused GATv2 aggregation: warp per dst node (CSR, no atomics) =====
__global__ __launch_bounds__(256)
void gat_aggregate(const float* __restrict__ att, const float* __restrict__ cb,
                   const float* __restrict__ bg, const float* __restrict__ bb,
                   const float* __restrict__ bm, const float* __restrict__ bv,
                   float* __restrict__ out_h)
{
    const int lane = threadIdx.x & 31;
    const int n = (blockIdx.x * 256 + threadIdx.x) >> 5;
    if (n >= NN) return;
    const int j0 = lane * 8;

    float sA[8], xr8[8];
    {
        const float4* ap = (const float4*)(att + j0);
        float4 a0 = ap[0], a1 = ap[1];
        sA[0]=a0.x; sA[1]=a0.y; sA[2]=a0.z; sA[3]=a0.w;
        sA[4]=a1.x; sA[5]=a1.y; sA[6]=a1.z; sA[7]=a1.w;
        const float4* rp = (const float4*)(g_xlr + (size_t)n * 512 + 256 + j0);
        float4 r0 = rp[0], r1 = rp[1];
        xr8[0]=r0.x; xr8[1]=r0.y; xr8[2]=r0.z; xr8[3]=r0.w;
        xr8[4]=r1.x; xr8[5]=r1.y; xr8[6]=r1.z; xr8[7]=r1.w;
    }

    float acc[8] = {};
    float den = 0.f;
    const int e0 = g_rowp[n], e1 = g_rowp[n + 1];

    float4 c0, c1, d0, d1;
    {
        const float4* p = (const float4*)(g_xlr + (size_t)g_col[e0] * 512 + j0);
        c0 = p[0]; c1 = p[1];
        if (e0 + 1 < e1) {
            const float4* p2 = (const float4*)(g_xlr + (size_t)g_col[e0 + 1] * 512 + j0);
            d0 = p2[0]; d1 = p2[1];
        }
    }
    for (int e = e0; e < e1; e++) {
        const float4 l0 = c0, l1 = c1;
        c0 = d0; c1 = d1;
        if (e + 2 < e1) {
            const float4* np = (const float4*)(g_xlr + (size_t)g_col[e + 2] * 512 + j0);
            d0 = np[0]; d1 = np[1];
        }
        float xl8[8] = {l0.x, l0.y, l0.z, l0.w, l1.x, l1.y, l1.z, l1.w};
        float part = 0.f;
        #pragma unroll
        for (int u = 0; u < 8; u++) {
            float s = xl8[u] + xr8[u];
            s = s > 0.f ? s : 0.2f * s;
            part += s * sA[u];
        }
        part += __shfl_xor_sync(0xffffffffu, part, 1);
        part += __shfl_xor_sync(0xffffffffu, part, 2);
        part += __shfl_xor_sync(0xffffffffu, part, 4);
        const float p = __expf(part);
        den += p;
        #pragma unroll
        for (int u = 0; u < 8; u++) acc[u] += p * xl8[u];
    }

    const float inv = 1.f / den;
    float* hp = g_h + (size_t)n * EMB + j0;
    float4 h0 = ((const float4*)hp)[0], h1 = ((const float4*)hp)[1];
    float hold[8] = {h0.x, h0.y, h0.z, h0.w, h1.x, h1.y, h1.z, h1.w};
    float outv[8];
    #pragma unroll
    for (int u = 0; u < 8; u++) {
        const int j = j0 + u;
        float v = acc[u] * inv + cb[j];
        v = (v - bm[j]) * (bg[j] * rsqrtf(bv[j] + BN_EPS)) + bb[j];
        v = v > 0.f ? v : __expf(v) - 1.f;
        outv[u] = hold[u] + v;
    }
    const float4 o0 = make_float4(outv[0], outv[1], outv[2], outv[3]);
    const float4 o1 = make_float4(outv[4], outv[5], outv[6], outv[7]);
    ((float4*)hp)[0] = o0;
    ((float4*)hp)[1] = o1;
    if (out_h) {
        float* op = out_h + (size_t)n * EMB + j0;
        ((float4*)op)[0] = o0;
        ((float4*)op)[1] = o1;
    }
    #pragma unroll
    for (int u = 0; u < 8; u++) {
        __nv_bfloat16 hb, lb;
        split_bf16(outv[u], hb, lb);
        g_hbh[(size_t)n * EMB + j0 + u] = hb;
        g_hbl[(size_t)n * EMB + j0 + u] = lb;
    }
}

// ---------------- heads ----------------
__global__ void head_kernel(const float* __restrict__ hW, const float* __restrict__ hb,
                            float* __restrict__ out)
{
    __shared__ float sW[4 * EMB];
    for (int i = threadIdx.x; i < 4 * EMB; i += blockDim.x) sW[i] = hW[i];
    __syncthreads();

    const int gw = (blockIdx.x * blockDim.x + threadIdx.x) >> 5;
    const int lane = threadIdx.x & 31;
    if (gw >= NN) return;
    const float* hp = g_h + (size_t)gw * EMB;
    float s0 = 0.f, s1 = 0.f, s2 = 0.f, s3 = 0.f;
    #pragma unroll
    for (int k = 0; k < 8; k++) {
        const int c = lane + k * 32;
        const float hv = hp[c];
        s0 += hv * sW[c];
        s1 += hv * sW[EMB + c];
        s2 += hv * sW[2 * EMB + c];
        s3 += hv * sW[3 * EMB + c];
    }
    #pragma unroll
    for (int off = 16; off; off >>= 1) {
        s0 += __shfl_down_sync(0xffffffffu, s0, off);
        s1 += __shfl_down_sync(0xffffffffu, s1, off);
        s2 += __shfl_down_sync(0xffffffffu, s2, off);
        s3 += __shfl_down_sync(0xffffffffu, s3, off);
    }
    if (lane == 0) {
        out[gw]          = s0 + hb[0];
        out[NN + gw]     = s1 + hb[1];
        out[2 * NN + gw] = s2 + hb[2];
        out[3 * NN + gw] = s3 + hb[3];
    }
}

// ---------------- launch ----------------
extern "C" void kernel_launch(void* const* d_in, const int* in_sizes, int n_in,
                              void* d_out, int out_size)
{
    const float* x      = (const float*)d_in[0];
    const int*   ei     = (const int*)  d_in[1];
    const float* proj_W = (const float*)d_in[2];
    const float* proj_b = (const float*)d_in[3];
    const float* ibn_g  = (const float*)d_in[4];
    const float* ibn_b  = (const float*)d_in[5];
    const float* ibn_m  = (const float*)d_in[6];
    const float* ibn_v  = (const float*)d_in[7];
    const float* Wl     = (const float*)d_in[8];
    const float* Wr     = (const float*)d_in[9];
    const float* att    = (const float*)d_in[10];
    const float* conv_b = (const float*)d_in[11];
    const float* bn_g   = (const float*)d_in[12];
    const float* bn_b   = (const float*)d_in[13];
    const float* bn_m   = (const float*)d_in[14];
    const float* bn_v   = (const float*)d_in[15];
    const float* head_W = (const float*)d_in[16];
    const float* head_b = (const float*)d_in[17];
    const float* dec_W  = (const float*)d_in[18];
    const float* dec_b  = (const float*)d_in[19];
    float* out = (float*)d_out;

    float* h;
    float* xlr;
    cudaGetSymbolAddress((void**)&h,   g_h);
    cudaGetSymbolAddress((void**)&xlr, g_xlr);
    __nv_bfloat16 *hbh, *hbl, *xbh, *xbl, *wth, *wtl, *pjh, *pjl, *dch, *dcl;
    cudaGetSymbolAddress((void**)&hbh, g_hbh);
    cudaGetSymbolAddress((void**)&hbl, g_hbl);
    cudaGetSymbolAddress((void**)&xbh, g_xbh);
    cudaGetSymbolAddress((void**)&xbl, g_xbl);
    cudaGetSymbolAddress((void**)&wth, g_wth);
    cudaGetSymbolAddress((void**)&wtl, g_wtl);
    cudaGetSymbolAddress((void**)&pjh, g_pjh);
    cudaGetSymbolAddress((void**)&pjl, g_pjl);
    cudaGetSymbolAddress((void**)&dch, g_dch);
    cudaGetSymbolAddress((void**)&dcl, g_dcl);

    cudaFuncSetAttribute(hgemm<0>, cudaFuncAttributeMaxDynamicSharedMemorySize, SMBYTES);
    cudaFuncSetAttribute(hgemm<1>, cudaFuncAttributeMaxDynamicSharedMemorySize, SMBYTES);
    cudaFuncSetAttribute(hgemm<2>, cudaFuncAttributeMaxDynamicSharedMemorySize, SMBYTES);

    const int gy = (NN + 127) / 128;          // 782
    const int nb = (NN + 255) / 256;          // 391

    // ---- prep: weights, x split (+csr zero), CSR ----
    prep_weights<<<(INC * EMB + 255) / 256, 256>>>(proj_W, INC, EMB, pjh, pjl);
    prep_wlr<<<(NLAYER * 2 * EMB * EMB + 255) / 256, 256>>>(Wl, Wr);
    prep_weights<<<(EMB * INC + 255) / 256, 256>>>(dec_W, EMB, INC, dch, dcl);
    prep_x<<<(NN * INC / 4 + 255) / 256, 256>>>(x);

    csr_hist<<<(NE + 255) / 256, 256>>>(ei);
    csr_scan1<<<nb, 256>>>();
    csr_scan2<<<1, 512>>>(nb);
    csr_scan3<<<nb, 256>>>();
    csr_fill<<<(NE + 255) / 256, 256>>>(ei);

    // ---- h = elu(bn(x @ proj_W + proj_b)) ----
    hgemm<1><<<dim3(2, gy), 256, SMBYTES>>>(xbh, xbl, pjh, pjl, h, NN, INC, EMB,
                                            proj_b, ibn_g, ibn_b, ibn_m, ibn_v);

    for (int i = 0; i < NLAYER; i++) {
        hgemm<0><<<dim3(4, gy), 256, SMBYTES>>>(hbh, hbl,
                                                wth + (size_t)i * 512 * EMB,
                                                wtl + (size_t)i * 512 * EMB,
                                                xlr, NN, EMB, 512,
                                                nullptr, nullptr, nullptr, nullptr, nullptr);
        gat_aggregate<<<(NN * 32 + 255) / 256, 256>>>(att + (size_t)i * NHEAD * HID,
                                                      conv_b + (size_t)i * EMB,
                                                      bn_g + (size_t)i * EMB, bn_b + (size_t)i * EMB,
                                                      bn_m + (size_t)i * EMB, bn_v + (size_t)i * EMB,
                                                      (i == NLAYER - 1) ? out + (size_t)4 * NN : nullptr);
    }

    // preds (4 x [N]) at out[0 .. 4N)
    head_kernel<<<(NN * 32 + 255) / 256, 256>>>(head_W, head_b, out);
    // recon at out[260N .. 388N)
    hgemm<2><<<dim3(1, gy), 256, SMBYTES>>>(hbh, hbl, dch, dcl, out + (size_t)260 * NN,
                                            NN, EMB, INC, dec_b,
                                            nullptr, nullptr, nullptr, nullptr);
}

// round 11
// speedup vs baseline: 1.2988x; 1.0957x over previous
#include <cuda_runtime.h>
#include <cuda_bf16.h>
#include <math.h>
#include <stdint.h>

#define NN      100000
#define INC     128
#define EMB     256
#define NHEAD   4
#define HID     64
#define NLAYER  3
#define NE      300000
#define ET      400000          // NE + NN self loops
#define BN_EPS  1e-5f

// ---------------- scratch ----------------
__device__ float g_xlr[(size_t)NN * 512];          // cols 0-255: xl, 256-511: xr
__device__ __nv_bfloat16 g_hbh[NN * EMB], g_hbl[NN * EMB];   // h as hi/lo pair
__device__ __nv_bfloat16 g_xbh[NN * INC], g_xbl[NN * INC];   // x split
__device__ __nv_bfloat16 g_wth[NLAYER * 512 * EMB], g_wtl[NLAYER * 512 * EMB];
__device__ __nv_bfloat16 g_pjh[EMB * INC], g_pjl[EMB * INC]; // proj^T [256][128]
__device__ __nv_bfloat16 g_dch[INC * EMB], g_dcl[INC * EMB]; // dec^T  [128][256]
// CSR
__device__ int g_cnt[NN];
__device__ int g_rowp[NN + 1];
__device__ int g_col[ET];
__device__ int g_bsum[512];

__device__ __forceinline__ uint32_t smem_u32(const void* p) {
    uint32_t a;
    asm("{ .reg .u64 t; cvta.to.shared.u64 t, %1; cvt.u32.u64 %0, t; }"
        : "=r"(a) : "l"(p));
    return a;
}
__device__ __forceinline__ void split_bf16(float v, __nv_bfloat16& h, __nv_bfloat16& l) {
    h = __float2bfloat16(v);
    l = __float2bfloat16(v - __bfloat162float(h));
}
__device__ __forceinline__ void unpack_bf2(uint32_t w, float& a, float& b) {
    __nv_bfloat162 t = *(__nv_bfloat162*)&w;
    a = __bfloat162float(t.x);
    b = __bfloat162float(t.y);
}

// ---------------- unified weight prep (proj | Wl/Wr | dec) ----------------
#define PJ_N (INC * EMB)                        // 32768
#define WLR_N (NLAYER * 2 * EMB * EMB)          // 393216
#define DC_N (EMB * INC)                        // 32768
__global__ void prep_all(const float* __restrict__ projW, const float* __restrict__ Wl,
                         const float* __restrict__ Wr, const float* __restrict__ decW)
{
    const int idx = blockIdx.x * 256 + threadIdx.x;
    if (idx < PJ_N) {
        const int k = idx >> 8, n = idx & 255;              // [128][256]
        __nv_bfloat16 h, l;
        split_bf16(projW[idx], h, l);
        g_pjh[n * INC + k] = h;
        g_pjl[n * INC + k] = l;
    } else if (idx < PJ_N + WLR_N) {
        const int r0 = idx - PJ_N;
        const int l = r0 / (2 * EMB * EMB);
        const int r = r0 - l * 2 * EMB * EMB;
        const int sel = r / (EMB * EMB);
        const int t = r - sel * EMB * EMB;
        const int k = t / EMB, n = t - k * EMB;
        const float v = (sel ? Wr : Wl)[(size_t)l * EMB * EMB + t];
        __nv_bfloat16 h, lo;
        split_bf16(v, h, lo);
        const size_t d = (size_t)l * 512 * EMB + (size_t)(sel * 256 + n) * EMB + k;
        g_wth[d] = h;
        g_wtl[d] = lo;
    } else if (idx < PJ_N + WLR_N + DC_N) {
        const int t = idx - PJ_N - WLR_N;
        const int k = t >> 7, n = t & 127;                  // [256][128]
        __nv_bfloat16 h, l;
        split_bf16(decW[t], h, l);
        g_dch[(size_t)n * EMB + k] = h;
        g_dcl[(size_t)n * EMB + k] = l;
    }
}
// vectorized x split + csr count init
__global__ void prep_x(const float* __restrict__ x)
{
    const int idx = blockIdx.x * 256 + threadIdx.x;   // NN*INC/4
    if (idx < NN) g_cnt[idx] = 1;                     // self-loop count
    if (idx >= NN * INC / 4) return;
    const float4 v = ((const float4*)x)[idx];
    __nv_bfloat16 h0, h1, h2, h3, l0, l1, l2, l3;
    split_bf16(v.x, h0, l0); split_bf16(v.y, h1, l1);
    split_bf16(v.z, h2, l2); split_bf16(v.w, h3, l3);
    uint2 hp, lp;
    hp.x = ((uint32_t)__bfloat16_as_ushort(h1) << 16) | __bfloat16_as_ushort(h0);
    hp.y = ((uint32_t)__bfloat16_as_ushort(h3) << 16) | __bfloat16_as_ushort(h2);
    lp.x = ((uint32_t)__bfloat16_as_ushort(l1) << 16) | __bfloat16_as_ushort(l0);
    lp.y = ((uint32_t)__bfloat16_as_ushort(l3) << 16) | __bfloat16_as_ushort(l2);
    ((uint2*)g_xbh)[idx] = hp;
    ((uint2*)g_xbl)[idx] = lp;
}

// ---------------- CSR build ----------------
__global__ void csr_hist(const int* __restrict__ ei) {
    const int e = blockIdx.x * 256 + threadIdx.x;
    if (e < NE) atomicAdd(&g_cnt[ei[NE + e]], 1);
}
__global__ void csr_scan1() {
    __shared__ int s[256];
    const int i = blockIdx.x * 256 + threadIdx.x;
    int v = (i < NN) ? g_cnt[i] : 0;
    s[threadIdx.x] = v;
    __syncthreads();
    int sum = v;
    #pragma unroll
    for (int off = 1; off < 256; off <<= 1) {
        int t = (threadIdx.x >= off) ? s[threadIdx.x - off] : 0;
        __syncthreads();
        s[threadIdx.x] = sum = sum + t;
        __syncthreads();
    }
    if (i < NN) g_rowp[i] = sum - v;
    if (threadIdx.x == 255) g_bsum[blockIdx.x] = s[255];
}
__global__ void csr_scan2(int nb) {
    __shared__ int s[512];
    const int t = threadIdx.x;
    int v = (t < nb) ? g_bsum[t] : 0;
    s[t] = v;
    __syncthreads();
    int sum = v;
    #pragma unroll
    for (int off = 1; off < 512; off <<= 1) {
        int u = (t >= off) ? s[t - off] : 0;
        __syncthreads();
        s[t] = sum = sum + u;
        __syncthreads();
    }
    if (t < nb) g_bsum[t] = sum - v;
}
__global__ void csr_scan3() {
    const int i = blockIdx.x * 256 + threadIdx.x;
    if (i == 0) g_rowp[NN] = ET;
    if (i >= NN) return;
    const int r = g_rowp[i] + g_bsum[i >> 8];
    g_rowp[i] = r;
    g_col[r] = i;
    g_cnt[i] = r + 1;
}
__global__ void csr_fill(const int* __restrict__ ei) {
    const int e = blockIdx.x * 256 + threadIdx.x;
    if (e >= NE) return;
    const int pos = atomicAdd(&g_cnt[ei[NE + e]], 1);
    g_col[pos] = ei[e];
}

// ====== bf16 mma.sync GEMM: 2-stage BK=32 pipeline, occ 2 ================
// xl/proj/dec blocks: 3-term split.  xr blocks (EPI==0, n0>=256): 1-term.
// EPI 0: write C   EPI 1: bias+BN+ELU -> hb pair only   EPI 2: +bias -> C
#define RS2 40
#define BUF2 (128 * RS2)
#define BUFB (BUF2 * 2)                 // 10240 bytes
#define STAGEB (4 * BUFB)               // 40960 bytes
#define SMBYTES (2 * STAGEB)            // 81920 -> occ 2

#define CPA(dst32, src, pb) \
    asm volatile("cp.async.cg.shared.global [%0], [%1], 16, %2;" \
                 :: "r"(dst32), "l"(src), "r"(pb))

__device__ __forceinline__ void ldsm_x4(uint32_t* r, uint32_t addr) {
    asm volatile("ldmatrix.sync.aligned.m8n8.x4.shared.b16 {%0,%1,%2,%3}, [%4];"
                 : "=r"(r[0]), "=r"(r[1]), "=r"(r[2]), "=r"(r[3]) : "r"(addr));
}
__device__ __forceinline__ void mma16816(float* c, const uint32_t* a, const uint32_t* b) {
    asm volatile("mma.sync.aligned.m16n8k16.row.col.f32.bf16.bf16.f32 "
                 "{%0,%1,%2,%3}, {%4,%5,%6,%7}, {%8,%9}, {%0,%1,%2,%3};"
                 : "+f"(c[0]), "+f"(c[1]), "+f"(c[2]), "+f"(c[3])
                 : "r"(a[0]), "r"(a[1]), "r"(a[2]), "r"(a[3]), "r"(b[0]), "r"(b[1]));
}

template<int EPI>
__global__ __launch_bounds__(256, 2)
void hgemm(const __nv_bfloat16* __restrict__ Ath, const __nv_bfloat16* __restrict__ Atl,
           const __nv_bfloat16* __restrict__ Bth, const __nv_bfloat16* __restrict__ Btl,
           float* __restrict__ C, int M, int K, int NC,
           const float* __restrict__ bias, const float* __restrict__ gg,
           const float* __restrict__ gb, const float* __restrict__ gm,
           const float* __restrict__ gv)
{
    extern __shared__ __nv_bfloat16 sm[];
    const uint32_t s32 = smem_u32(sm);
    const int tid = threadIdx.x, lane = tid & 31, w = tid >> 5;
    const int m0 = blockIdx.y * 128, n0 = blockIdx.x * 128;
    const int wm = (w >> 2) * 64, wn = (w & 3) * 32;

    const bool full = (EPI != 0) || (n0 < 256);   // xr blocks: single term

    float acc[4][4][4] = {};
    const int nchunks = K >> 5;

    const __nv_bfloat16* srcs[4] = {Ath, Atl, Bth, Btl};

    auto load_chunk = [&](int ch, int st) {
        const uint32_t sb = s32 + (uint32_t)st * STAGEB;
        #pragma unroll
        for (int i = 0; i < 8; i++) {
            const int buf = i >> 1;
            if (!full && (buf & 1)) continue;        // skip lo buffers
            const int s = (i & 1) * 256 + tid;
            const int r = s >> 2, q = s & 3;
            const int base = (buf < 2) ? m0 : n0;
            const uint32_t doff = (uint32_t)buf * BUFB + (uint32_t)(r * RS2 + q * 8) * 2;
            const size_t goff = (size_t)(base + r) * K + ch * 32 + q * 8;
            const unsigned pb = (buf >= 2 || base + r < M) ? 16u : 0u;
            CPA(sb + doff, srcs[buf] + goff, pb);
        }
        asm volatile("cp.async.commit_group;" ::: "memory");
    };

    load_chunk(0, 0);

    for (int ch = 0; ch < nchunks; ch++) {
        if (ch + 1 < nchunks) {
            load_chunk(ch + 1, (ch + 1) & 1);
            asm volatile("cp.async.wait_group 1;" ::: "memory");
        } else {
            asm volatile("cp.async.wait_group 0;" ::: "memory");
        }
        __syncthreads();

        const uint32_t sb = s32 + (uint32_t)(ch & 1) * STAGEB;
        const int lra = lane & 15, lka = (lane >> 4) * 8;
        const int bt = lane >> 3, blr = lane & 7;

        #pragma unroll
        for (int ks = 0; ks < 2; ks++) {
            const int k0 = ks * 16;
            uint32_t ah[4][4], bh[4][2];
            #pragma unroll
            for (int mt = 0; mt < 4; mt++)
                ldsm_x4(ah[mt], sb + ((wm + mt * 16 + lra) * RS2 + k0 + lka) * 2);
            #pragma unroll
            for (int ntp = 0; ntp < 2; ntp++) {
                const int row = wn + ntp * 16 + ((bt >> 1) << 3) + blr;
                const int col = k0 + (bt & 1) * 8;
                ldsm_x4(&bh[ntp * 2][0], sb + 2 * BUFB + (row * RS2 + col) * 2);
            }
            #pragma unroll
            for (int mt = 0; mt < 4; mt++)
                #pragma unroll
                for (int nt = 0; nt < 4; nt++)
                    mma16816(acc[mt][nt], ah[mt], bh[nt]);

            if (full) {
                uint32_t al[4][4], bl[4][2];
                #pragma unroll
                for (int mt = 0; mt < 4; mt++)
                    ldsm_x4(al[mt], sb + BUFB + ((wm + mt * 16 + lra) * RS2 + k0 + lka) * 2);
                #pragma unroll
                for (int mt = 0; mt < 4; mt++)
                    #pragma unroll
                    for (int nt = 0; nt < 4; nt++)
                        mma16816(acc[mt][nt], al[mt], bh[nt]);
                #pragma unroll
                for (int ntp = 0; ntp < 2; ntp++) {
                    const int row = wn + ntp * 16 + ((bt >> 1) << 3) + blr;
                    const int col = k0 + (bt & 1) * 8;
                    ldsm_x4(&bl[ntp * 2][0], sb + 3 * BUFB + (row * RS2 + col) * 2);
                }
                #pragma unroll
                for (int mt = 0; mt < 4; mt++)
                    #pragma unroll
                    for (int nt = 0; nt < 4; nt++)
                        mma16816(acc[mt][nt], ah[mt], bl[nt]);
            }
        }
        __syncthreads();
    }

    #pragma unroll
    for (int mt = 0; mt < 4; mt++) {
        #pragma unroll
        for (int nt = 0; nt < 4; nt++) {
            #pragma unroll
            for (int q = 0; q < 4; q++) {
                const int row = m0 + wm + mt * 16 + (lane >> 2) + (q >> 1) * 8;
                const int col = n0 + wn + nt * 8 + 2 * (lane & 3) + (q & 1);
                if (row >= M) continue;
                float v = acc[mt][nt][q];
                if (EPI >= 1) v += bias[col];
                if (EPI == 1) {
                    v = (v - gm[col]) * (gg[col] * rsqrtf(gv[col] + BN_EPS)) + gb[col];
                    v = v > 0.f ? v : __expf(v) - 1.f;
                    __nv_bfloat16 hb, lb;
                    split_bf16(v, hb, lb);
                    g_hbh[(size_t)row * EMB + col] = hb;
                    g_hbl[(size_t)row * EMB + col] = lb;
                } else {
                    C[(size_t)row * NC + col] = v;
                }
            }
        }
    }
}

// ====== fused GATv2 aggregation: warp per dst node (CSR, no atomics) =====
// residual carried as bf16 hi/lo pair; last layer also emits fp32 h and heads.
__global__ __launch_bounds__(256)
void gat_aggregate(const float* __restrict__ att, const float* __restrict__ cb,
                   const float* __restrict__ bg, const float* __restrict__ bb,
                   const float* __restrict__ bm, const float* __restrict__ bv,
                   float* __restrict__ out_h,
                   const float* __restrict__ hW, const float* __restrict__ hb,
                   float* __restrict__ preds)
{
    const int lane = threadIdx.x & 31;
    const int n = (blockIdx.x * 256 + threadIdx.x) >> 5;
    if (n >= NN) return;
    const int j0 = lane * 8;

    float sA[8], xr8[8];
    {
        const float4* ap = (const float4*)(att + j0);
        float4 a0 = ap[0], a1 = ap[1];
        sA[0]=a0.x; sA[1]=a0.y; sA[2]=a0.z; sA[3]=a0.w;
        sA[4]=a1.x; sA[5]=a1.y; sA[6]=a1.z; sA[7]=a1.w;
        const float4* rp = (const float4*)(g_xlr + (size_t)n * 512 + 256 + j0);
        float4 r0 = rp[0], r1 = rp[1];
        xr8[0]=r0.x; xr8[1]=r0.y; xr8[2]=r0.z; xr8[3]=r0.w;
        xr8[4]=r1.x; xr8[5]=r1.y; xr8[6]=r1.z; xr8[7]=r1.w;
    }

    float acc[8] = {};
    float den = 0.f;
    const int e0 = g_rowp[n], e1 = g_rowp[n + 1];

    float4 c0, c1, d0, d1;
    {
        const float4* p = (const float4*)(g_xlr + (size_t)g_col[e0] * 512 + j0);
        c0 = p[0]; c1 = p[1];
        if (e0 + 1 < e1) {
            const float4* p2 = (const float4*)(g_xlr + (size_t)g_col[e0 + 1] * 512 + j0);
            d0 = p2[0]; d1 = p2[1];
        }
    }
    for (int e = e0; e < e1; e++) {
        const float4 l0 = c0, l1 = c1;
        c0 = d0; c1 = d1;
        if (e + 2 < e1) {
            const float4* np = (const float4*)(g_xlr + (size_t)g_col[e + 2] * 512 + j0);
            d0 = np[0]; d1 = np[1];
        }
        float xl8[8] = {l0.x, l0.y, l0.z, l0.w, l1.x, l1.y, l1.z, l1.w};
        float part = 0.f;
        #pragma unroll
        for (int u = 0; u < 8; u++) {
            float s = xl8[u] + xr8[u];
            s = s > 0.f ? s : 0.2f * s;
            part += s * sA[u];
        }
        part += __shfl_xor_sync(0xffffffffu, part, 1);
        part += __shfl_xor_sync(0xffffffffu, part, 2);
        part += __shfl_xor_sync(0xffffffffu, part, 4);
        const float p = __expf(part);
        den += p;
        #pragma unroll
        for (int u = 0; u < 8; u++) acc[u] += p * xl8[u];
    }

    const float inv = 1.f / den;

    // residual from hi/lo pair (exact to 2^-17)
    float hold[8];
    {
        const uint4 hh = *(const uint4*)(g_hbh + (size_t)n * EMB + j0);
        const uint4 hl = *(const uint4*)(g_hbl + (size_t)n * EMB + j0);
        float a, b;
        unpack_bf2(hh.x, hold[0], hold[1]);
        unpack_bf2(hh.y, hold[2], hold[3]);
        unpack_bf2(hh.z, hold[4], hold[5]);
        unpack_bf2(hh.w, hold[6], hold[7]);
        unpack_bf2(hl.x, a, b); hold[0] += a; hold[1] += b;
        unpack_bf2(hl.y, a, b); hold[2] += a; hold[3] += b;
        unpack_bf2(hl.z, a, b); hold[4] += a; hold[5] += b;
        unpack_bf2(hl.w, a, b); hold[6] += a; hold[7] += b;
    }

    float outv[8];
    #pragma unroll
    for (int u = 0; u < 8; u++) {
        const int j = j0 + u;
        float v = acc[u] * inv + cb[j];
        v = (v - bm[j]) * (bg[j] * rsqrtf(bv[j] + BN_EPS)) + bb[j];
        v = v > 0.f ? v : __expf(v) - 1.f;
        outv[u] = hold[u] + v;
    }

    // write h pair (always; feeds next GEMM / dec)
    uint4 ph, pl;
    {
        __nv_bfloat16 hbv[8], lbv[8];
        #pragma unroll
        for (int u = 0; u < 8; u++) split_bf16(outv[u], hbv[u], lbv[u]);
        ph.x = ((uint32_t)__bfloat16_as_ushort(hbv[1]) << 16) | __bfloat16_as_ushort(hbv[0]);
        ph.y = ((uint32_t)__bfloat16_as_ushort(hbv[3]) << 16) | __bfloat16_as_ushort(hbv[2]);
        ph.z = ((uint32_t)__bfloat16_as_ushort(hbv[5]) << 16) | __bfloat16_as_ushort(hbv[4]);
        ph.w = ((uint32_t)__bfloat16_as_ushort(hbv[7]) << 16) | __bfloat16_as_ushort(hbv[6]);
        pl.x = ((uint32_t)__bfloat16_as_ushort(lbv[1]) << 16) | __bfloat16_as_ushort(lbv[0]);
        pl.y = ((uint32_t)__bfloat16_as_ushort(lbv[3]) << 16) | __bfloat16_as_ushort(lbv[2]);
        pl.z = ((uint32_t)__bfloat16_as_ushort(lbv[5]) << 16) | __bfloat16_as_ushort(lbv[4]);
        pl.w = ((uint32_t)__bfloat16_as_ushort(lbv[7]) << 16) | __bfloat16_as_ushort(lbv[6]);
    }
    *(uint4*)(g_hbh + (size_t)n * EMB + j0) = ph;
    *(uint4*)(g_hbl + (size_t)n * EMB + j0) = pl;

    if (out_h) {
        // final layer: fp32 h to output + fused heads
        float* op = out_h + (size_t)n * EMB + j0;
        ((float4*)op)[0] = make_float4(outv[0], outv[1], outv[2], outv[3]);
        ((float4*)op)[1] = make_float4(outv[4], outv[5], outv[6], outv[7]);

        float s0 = 0.f, s1 = 0.f, s2 = 0.f, s3 = 0.f;
        #pragma unroll
        for (int u = 0; u < 8; u++) {
            const float hv = outv[u];
            s0 += hv * hW[j0 + u];
            s1 += hv * hW[EMB + j0 + u];
            s2 += hv * hW[2 * EMB + j0 + u];
            s3 += hv * hW[3 * EMB + j0 + u];
        }
        #pragma unroll
        for (int off = 16; off; off >>= 1) {
            s0 += __shfl_xor_sync(0xffffffffu, s0, off);
            s1 += __shfl_xor_sync(0xffffffffu, s1, off);
            s2 += __shfl_xor_sync(0xffffffffu, s2, off);
            s3 += __shfl_xor_sync(0xffffffffu, s3, off);
        }
        if (lane == 0) {
            preds[n]          = s0 + hb[0];
            preds[NN + n]     = s1 + hb[1];
            preds[2 * NN + n] = s2 + hb[2];
            preds[3 * NN + n] = s3 + hb[3];
        }
    }
}

// ---------------- launch ----------------
extern "C" void kernel_launch(void* const* d_in, const int* in_sizes, int n_in,
                              void* d_out, int out_size)
{
    const float* x      = (const float*)d_in[0];
    const int*   ei     = (const int*)  d_in[1];
    const float* proj_W = (const float*)d_in[2];
    const float* proj_b = (const float*)d_in[3];
    const float* ibn_g  = (const float*)d_in[4];
    const float* ibn_b  = (const float*)d_in[5];
    const float* ibn_m  = (const float*)d_in[6];
    const float* ibn_v  = (const float*)d_in[7];
    const float* Wl     = (const float*)d_in[8];
    const float* Wr     = (const float*)d_in[9];
    const float* att    = (const float*)d_in[10];
    const float* conv_b = (const float*)d_in[11];
    const float* bn_g   = (const float*)d_in[12];
    const float* bn_b   = (const float*)d_in[13];
    const float* bn_m   = (const float*)d_in[14];
    const float* bn_v   = (const float*)d_in[15];
    const float* head_W = (const float*)d_in[16];
    const float* head_b = (const float*)d_in[17];
    const float* dec_W  = (const float*)d_in[18];
    const float* dec_b  = (const float*)d_in[19];
    float* out = (float*)d_out;

    float* xlr;
    cudaGetSymbolAddress((void**)&xlr, g_xlr);
    __nv_bfloat16 *hbh, *hbl, *xbh, *xbl, *wth, *wtl, *pjh, *pjl, *dch, *dcl;
    cudaGetSymbolAddress((void**)&hbh, g_hbh);
    cudaGetSymbolAddress((void**)&hbl, g_hbl);
    cudaGetSymbolAddress((void**)&xbh, g_xbh);
    cudaGetSymbolAddress((void**)&xbl, g_xbl);
    cudaGetSymbolAddress((void**)&wth, g_wth);
    cudaGetSymbolAddress((void**)&wtl, g_wtl);
    cudaGetSymbolAddress((void**)&pjh, g_pjh);
    cudaGetSymbolAddress((void**)&pjl, g_pjl);
    cudaGetSymbolAddress((void**)&dch, g_dch);
    cudaGetSymbolAddress((void**)&dcl, g_dcl);

    cudaFuncSetAttribute(hgemm<0>, cudaFuncAttributeMaxDynamicSharedMemorySize, SMBYTES);
    cudaFuncSetAttribute(hgemm<1>, cudaFuncAttributeMaxDynamicSharedMemorySize, SMBYTES);
    cudaFuncSetAttribute(hgemm<2>, cudaFuncAttributeMaxDynamicSharedMemorySize, SMBYTES);

    const int gy = (NN + 127) / 128;          // 782
    const int nb = (NN + 255) / 256;          // 391

    // ---- prep: weights (one kernel), x split (+csr zero), CSR ----
    prep_all<<<(PJ_N + WLR_N + DC_N + 255) / 256, 256>>>(proj_W, Wl, Wr, dec_W);
    prep_x<<<(NN * INC / 4 + 255) / 256, 256>>>(x);

    csr_hist<<<(NE + 255) / 256, 256>>>(ei);
    csr_scan1<<<nb, 256>>>();
    csr_scan2<<<1, 512>>>(nb);
    csr_scan3<<<nb, 256>>>();
    csr_fill<<<(NE + 255) / 256, 256>>>(ei);

    // ---- h = elu(bn(x @ proj_W + proj_b)) -> hb pair only ----
    hgemm<1><<<dim3(2, gy), 256, SMBYTES>>>(xbh, xbl, pjh, pjl, nullptr, NN, INC, EMB,
                                            proj_b, ibn_g, ibn_b, ibn_m, ibn_v);

    for (int i = 0; i < NLAYER; i++) {
        hgemm<0><<<dim3(4, gy), 256, SMBYTES>>>(hbh, hbl,
                                                wth + (size_t)i * 512 * EMB,
                                                wtl + (size_t)i * 512 * EMB,
                                                xlr, NN, EMB, 512,
                                                nullptr, nullptr, nullptr, nullptr, nullptr);
        const bool last = (i == NLAYER - 1);
        gat_aggregate<<<(NN * 32 + 255) / 256, 256>>>(att + (size_t)i * NHEAD * HID,
                                                      conv_b + (size_t)i * EMB,
                                                      bn_g + (size_t)i * EMB, bn_b + (size_t)i * EMB,
                                                      bn_m + (size_t)i * EMB, bn_v + (size_t)i * EMB,
                                                      last ? out + (size_t)4 * NN : nullptr,
                                                      head_W, head_b,
                                                      last ? out : nullptr);
    }

    // recon at out[260N .. 388N)
    hgemm<2><<<dim3(1, gy), 256, SMBYTES>>>(hbh, hbl, dch, dcl, out + (size_t)260 * NN,
                                            NN, EMB, INC, dec_b,
                                            nullptr, nullptr, nullptr, nullptr);
}

// round 12
// speedup vs baseline: 1.4858x; 1.1440x over previous
#include <cuda_runtime.h>
#include <cuda_bf16.h>
#include <cuda_fp16.h>
#include <math.h>
#include <stdint.h>

#define NN      100000
#define INC     128
#define EMB     256
#define NHEAD   4
#define HID     64
#define NLAYER  3
#define NE      300000
#define ET      400000          // NE + NN self loops
#define BN_EPS  1e-5f

// ---------------- scratch ----------------
__device__ __half g_xlh[(size_t)NN * EMB];                   // xl, fp16
__device__ __half g_xrh[(size_t)NN * EMB];                   // xr, fp16
__device__ __nv_bfloat16 g_hbh[NN * EMB], g_hbl[NN * EMB];   // h as hi/lo pair
__device__ __nv_bfloat16 g_xbh[NN * INC], g_xbl[NN * INC];   // x split
__device__ __nv_bfloat16 g_wth[NLAYER * 512 * EMB], g_wtl[NLAYER * 512 * EMB];
__device__ __nv_bfloat16 g_pjh[EMB * INC], g_pjl[EMB * INC]; // proj^T [256][128]
__device__ __nv_bfloat16 g_dch[INC * EMB], g_dcl[INC * EMB]; // dec^T  [128][256]
// CSR
__device__ int g_cnt[NN];
__device__ int g_rowp[NN + 1];
__device__ int g_col[ET];
__device__ int g_bsum[512];

__device__ __forceinline__ uint32_t smem_u32(const void* p) {
    uint32_t a;
    asm("{ .reg .u64 t; cvta.to.shared.u64 t, %1; cvt.u32.u64 %0, t; }"
        : "=r"(a) : "l"(p));
    return a;
}
__device__ __forceinline__ void split_bf16(float v, __nv_bfloat16& h, __nv_bfloat16& l) {
    h = __float2bfloat16(v);
    l = __float2bfloat16(v - __bfloat162float(h));
}
__device__ __forceinline__ void unpack_bf2(uint32_t w, float& a, float& b) {
    __nv_bfloat162 t = *(__nv_bfloat162*)&w;
    a = __bfloat162float(t.x);
    b = __bfloat162float(t.y);
}
__device__ __forceinline__ void unpack_h8(uint4 v, float* f) {
    float2 a;
    a = __half22float2(*(__half2*)&v.x); f[0] = a.x; f[1] = a.y;
    a = __half22float2(*(__half2*)&v.y); f[2] = a.x; f[3] = a.y;
    a = __half22float2(*(__half2*)&v.z); f[4] = a.x; f[5] = a.y;
    a = __half22float2(*(__half2*)&v.w); f[6] = a.x; f[7] = a.y;
}

// ---------------- unified weight prep (proj | Wl/Wr | dec) ----------------
#define PJ_N (INC * EMB)                        // 32768
#define WLR_N (NLAYER * 2 * EMB * EMB)          // 393216
#define DC_N (EMB * INC)                        // 32768
__global__ void prep_all(const float* __restrict__ projW, const float* __restrict__ Wl,
                         const float* __restrict__ Wr, const float* __restrict__ decW)
{
    const int idx = blockIdx.x * 256 + threadIdx.x;
    if (idx < PJ_N) {
        const int k = idx >> 8, n = idx & 255;              // [128][256]
        __nv_bfloat16 h, l;
        split_bf16(projW[idx], h, l);
        g_pjh[n * INC + k] = h;
        g_pjl[n * INC + k] = l;
    } else if (idx < PJ_N + WLR_N) {
        const int r0 = idx - PJ_N;
        const int l = r0 / (2 * EMB * EMB);
        const int r = r0 - l * 2 * EMB * EMB;
        const int sel = r / (EMB * EMB);
        const int t = r - sel * EMB * EMB;
        const int k = t / EMB, n = t - k * EMB;
        const float v = (sel ? Wr : Wl)[(size_t)l * EMB * EMB + t];
        __nv_bfloat16 h, lo;
        split_bf16(v, h, lo);
        const size_t d = (size_t)l * 512 * EMB + (size_t)(sel * 256 + n) * EMB + k;
        g_wth[d] = h;
        g_wtl[d] = lo;
    } else if (idx < PJ_N + WLR_N + DC_N) {
        const int t = idx - PJ_N - WLR_N;
        const int k = t >> 7, n = t & 127;                  // [256][128]
        __nv_bfloat16 h, l;
        split_bf16(decW[t], h, l);
        g_dch[(size_t)n * EMB + k] = h;
        g_dcl[(size_t)n * EMB + k] = l;
    }
}
// vectorized x split + csr count init
__global__ void prep_x(const float* __restrict__ x)
{
    const int idx = blockIdx.x * 256 + threadIdx.x;   // NN*INC/4
    if (idx < NN) g_cnt[idx] = 1;                     // self-loop count
    if (idx >= NN * INC / 4) return;
    const float4 v = ((const float4*)x)[idx];
    __nv_bfloat16 h0, h1, h2, h3, l0, l1, l2, l3;
    split_bf16(v.x, h0, l0); split_bf16(v.y, h1, l1);
    split_bf16(v.z, h2, l2); split_bf16(v.w, h3, l3);
    uint2 hp, lp;
    hp.x = ((uint32_t)__bfloat16_as_ushort(h1) << 16) | __bfloat16_as_ushort(h0);
    hp.y = ((uint32_t)__bfloat16_as_ushort(h3) << 16) | __bfloat16_as_ushort(h2);
    lp.x = ((uint32_t)__bfloat16_as_ushort(l1) << 16) | __bfloat16_as_ushort(l0);
    lp.y = ((uint32_t)__bfloat16_as_ushort(l3) << 16) | __bfloat16_as_ushort(l2);
    ((uint2*)g_xbh)[idx] = hp;
    ((uint2*)g_xbl)[idx] = lp;
}

// ---------------- CSR build ----------------
__global__ void csr_hist(const int* __restrict__ ei) {
    const int e = blockIdx.x * 256 + threadIdx.x;
    if (e < NE) atomicAdd(&g_cnt[ei[NE + e]], 1);
}
__global__ void csr_scan1() {
    __shared__ int s[256];
    const int i = blockIdx.x * 256 + threadIdx.x;
    int v = (i < NN) ? g_cnt[i] : 0;
    s[threadIdx.x] = v;
    __syncthreads();
    int sum = v;
    #pragma unroll
    for (int off = 1; off < 256; off <<= 1) {
        int t = (threadIdx.x >= off) ? s[threadIdx.x - off] : 0;
        __syncthreads();
        s[threadIdx.x] = sum = sum + t;
        __syncthreads();
    }
    if (i < NN) g_rowp[i] = sum - v;
    if (threadIdx.x == 255) g_bsum[blockIdx.x] = s[255];
}
__global__ void csr_scan2(int nb) {
    __shared__ int s[512];
    const int t = threadIdx.x;
    int v = (t < nb) ? g_bsum[t] : 0;
    s[t] = v;
    __syncthreads();
    int sum = v;
    #pragma unroll
    for (int off = 1; off < 512; off <<= 1) {
        int u = (t >= off) ? s[t - off] : 0;
        __syncthreads();
        s[t] = sum = sum + u;
        __syncthreads();
    }
    if (t < nb) g_bsum[t] = sum - v;
}
__global__ void csr_scan3() {
    const int i = blockIdx.x * 256 + threadIdx.x;
    if (i == 0) g_rowp[NN] = ET;
    if (i >= NN) return;
    const int r = g_rowp[i] + g_bsum[i >> 8];
    g_rowp[i] = r;
    g_col[r] = i;
    g_cnt[i] = r + 1;
}
__global__ void csr_fill(const int* __restrict__ ei) {
    const int e = blockIdx.x * 256 + threadIdx.x;
    if (e >= NE) return;
    const int pos = atomicAdd(&g_cnt[ei[NE + e]], 1);
    g_col[pos] = ei[e];
}

// ====== bf16 mma.sync GEMM: 2-stage BK=32 pipeline, occ 2 ================
// xl/proj/dec blocks: 3-term split.  xr blocks (EPI==0, n0>=256): 1-term.
// EPI 0: write fp16 xl/xr   EPI 1: bias+BN+ELU -> hb pair   EPI 2: +bias -> C
#define RS2 40
#define BUF2 (128 * RS2)
#define BUFB (BUF2 * 2)                 // 10240 bytes
#define STAGEB (4 * BUFB)               // 40960 bytes
#define SMBYTES (2 * STAGEB)            // 81920 -> occ 2

#define CPA(dst32, src, pb) \
    asm volatile("cp.async.cg.shared.global [%0], [%1], 16, %2;" \
                 :: "r"(dst32), "l"(src), "r"(pb))

__device__ __forceinline__ void ldsm_x4(uint32_t* r, uint32_t addr) {
    asm volatile("ldmatrix.sync.aligned.m8n8.x4.shared.b16 {%0,%1,%2,%3}, [%4];"
                 : "=r"(r[0]), "=r"(r[1]), "=r"(r[2]), "=r"(r[3]) : "r"(addr));
}
__device__ __forceinline__ void mma16816(float* c, const uint32_t* a, const uint32_t* b) {
    asm volatile("mma.sync.aligned.m16n8k16.row.col.f32.bf16.bf16.f32 "
                 "{%0,%1,%2,%3}, {%4,%5,%6,%7}, {%8,%9}, {%0,%1,%2,%3};"
                 : "+f"(c[0]), "+f"(c[1]), "+f"(c[2]), "+f"(c[3])
                 : "r"(a[0]), "r"(a[1]), "r"(a[2]), "r"(a[3]), "r"(b[0]), "r"(b[1]));
}

template<int EPI>
__global__ __launch_bounds__(256, 2)
void hgemm(const __nv_bfloat16* __restrict__ Ath, const __nv_bfloat16* __restrict__ Atl,
           const __nv_bfloat16* __restrict__ Bth, const __nv_bfloat16* __restrict__ Btl,
           float* __restrict__ C, int M, int K, int NC,
           const float* __restrict__ bias, const float* __restrict__ gg,
           const float* __restrict__ gb, const float* __restrict__ gm,
           const float* __restrict__ gv)
{
    extern __shared__ __nv_bfloat16 sm[];
    const uint32_t s32 = smem_u32(sm);
    const int tid = threadIdx.x, lane = tid & 31, w = tid >> 5;
    const int m0 = blockIdx.y * 128, n0 = blockIdx.x * 128;
    const int wm = (w >> 2) * 64, wn = (w & 3) * 32;

    const bool full = (EPI != 0) || (n0 < 256);   // xr blocks: single term

    float acc[4][4][4] = {};
    const int nchunks = K >> 5;

    const __nv_bfloat16* srcs[4] = {Ath, Atl, Bth, Btl};

    auto load_chunk = [&](int ch, int st) {
        const uint32_t sb = s32 + (uint32_t)st * STAGEB;
        #pragma unroll
        for (int i = 0; i < 8; i++) {
            const int buf = i >> 1;
            if (!full && (buf & 1)) continue;        // skip lo buffers
            const int s = (i & 1) * 256 + tid;
            const int r = s >> 2, q = s & 3;
            const int base = (buf < 2) ? m0 : n0;
            const uint32_t doff = (uint32_t)buf * BUFB + (uint32_t)(r * RS2 + q * 8) * 2;
            const size_t goff = (size_t)(base + r) * K + ch * 32 + q * 8;
            const unsigned pb = (buf >= 2 || base + r < M) ? 16u : 0u;
            CPA(sb + doff, srcs[buf] + goff, pb);
        }
        asm volatile("cp.async.commit_group;" ::: "memory");
    };

    load_chunk(0, 0);

    for (int ch = 0; ch < nchunks; ch++) {
        if (ch + 1 < nchunks) {
            load_chunk(ch + 1, (ch + 1) & 1);
            asm volatile("cp.async.wait_group 1;" ::: "memory");
        } else {
            asm volatile("cp.async.wait_group 0;" ::: "memory");
        }
        __syncthreads();

        const uint32_t sb = s32 + (uint32_t)(ch & 1) * STAGEB;
        const int lra = lane & 15, lka = (lane >> 4) * 8;
        const int bt = lane >> 3, blr = lane & 7;

        #pragma unroll
        for (int ks = 0; ks < 2; ks++) {
            const int k0 = ks * 16;
            uint32_t ah[4][4], bh[4][2];
            #pragma unroll
            for (int mt = 0; mt < 4; mt++)
                ldsm_x4(ah[mt], sb + ((wm + mt * 16 + lra) * RS2 + k0 + lka) * 2);
            #pragma unroll
            for (int ntp = 0; ntp < 2; ntp++) {
                const int row = wn + ntp * 16 + ((bt >> 1) << 3) + blr;
                const int col = k0 + (bt & 1) * 8;
                ldsm_x4(&bh[ntp * 2][0], sb + 2 * BUFB + (row * RS2 + col) * 2);
            }
            #pragma unroll
            for (int mt = 0; mt < 4; mt++)
                #pragma unroll
                for (int nt = 0; nt < 4; nt++)
                    mma16816(acc[mt][nt], ah[mt], bh[nt]);

            if (full) {
                uint32_t al[4][4], bl[4][2];
                #pragma unroll
                for (int mt = 0; mt < 4; mt++)
                    ldsm_x4(al[mt], sb + BUFB + ((wm + mt * 16 + lra) * RS2 + k0 + lka) * 2);
                #pragma unroll
                for (int mt = 0; mt < 4; mt++)
                    #pragma unroll
                    for (int nt = 0; nt < 4; nt++)
                        mma16816(acc[mt][nt], al[mt], bh[nt]);
                #pragma unroll
                for (int ntp = 0; ntp < 2; ntp++) {
                    const int row = wn + ntp * 16 + ((bt >> 1) << 3) + blr;
                    const int col = k0 + (bt & 1) * 8;
                    ldsm_x4(&bl[ntp * 2][0], sb + 3 * BUFB + (row * RS2 + col) * 2);
                }
                #pragma unroll
                for (int mt = 0; mt < 4; mt++)
                    #pragma unroll
                    for (int nt = 0; nt < 4; nt++)
                        mma16816(acc[mt][nt], ah[mt], bl[nt]);
            }
        }
        __syncthreads();
    }

    // epilogue: column-paired vectorized stores (q pairs share a row)
    #pragma unroll
    for (int mt = 0; mt < 4; mt++) {
        #pragma unroll
        for (int nt = 0; nt < 4; nt++) {
            #pragma unroll
            for (int qq = 0; qq < 2; qq++) {
                const int row = m0 + wm + mt * 16 + (lane >> 2) + qq * 8;
                const int col = n0 + wn + nt * 8 + 2 * (lane & 3);
                if (row >= M) continue;
                float v0 = acc[mt][nt][qq * 2];
                float v1 = acc[mt][nt][qq * 2 + 1];
                if (EPI == 0) {
                    __half2 hv = __floats2half2_rn(v0, v1);
                    if (n0 < 256)
                        *(__half2*)(g_xlh + (size_t)row * EMB + col) = hv;
                    else
                        *(__half2*)(g_xrh + (size_t)row * EMB + (col - 256)) = hv;
                } else if (EPI == 2) {
                    v0 += bias[col];
                    v1 += bias[col + 1];
                    *(float2*)(C + (size_t)row * NC + col) = make_float2(v0, v1);
                } else {
                    v0 += bias[col];
                    v1 += bias[col + 1];
                    v0 = (v0 - gm[col]) * (gg[col] * rsqrtf(gv[col] + BN_EPS)) + gb[col];
                    v1 = (v1 - gm[col + 1]) * (gg[col + 1] * rsqrtf(gv[col + 1] + BN_EPS)) + gb[col + 1];
                    v0 = v0 > 0.f ? v0 : __expf(v0) - 1.f;
                    v1 = v1 > 0.f ? v1 : __expf(v1) - 1.f;
                    __nv_bfloat16 h0, l0, h1, l1;
                    split_bf16(v0, h0, l0);
                    split_bf16(v1, h1, l1);
                    *(__nv_bfloat162*)(g_hbh + (size_t)row * EMB + col) =
                        __nv_bfloat162(h0, h1);
                    *(__nv_bfloat162*)(g_hbl + (size_t)row * EMB + col) =
                        __nv_bfloat162(l0, l1);
                }
            }
        }
    }
}

// ====== fused GATv2 aggregation: warp per dst node (CSR, no atomics) =====
// xl/xr in fp16 (16B per lane per edge); residual carried as bf16 hi/lo pair.
__global__ __launch_bounds__(256)
void gat_aggregate(const float* __restrict__ att, const float* __restrict__ cb,
                   const float* __restrict__ bg, const float* __restrict__ bb,
                   const float* __restrict__ bm, const float* __restrict__ bv,
                   float* __restrict__ out_h,
                   const float* __restrict__ hW, const float* __restrict__ hb,
                   float* __restrict__ preds)
{
    const int lane = threadIdx.x & 31;
    const int n = (blockIdx.x * 256 + threadIdx.x) >> 5;
    if (n >= NN) return;
    const int j0 = lane * 8;

    float sA[8], xr8[8];
    {
        const float4* ap = (const float4*)(att + j0);
        float4 a0 = ap[0], a1 = ap[1];
        sA[0]=a0.x; sA[1]=a0.y; sA[2]=a0.z; sA[3]=a0.w;
        sA[4]=a1.x; sA[5]=a1.y; sA[6]=a1.z; sA[7]=a1.w;
        unpack_h8(*(const uint4*)(g_xrh + (size_t)n * EMB + j0), xr8);
    }

    float acc[8] = {};
    float den = 0.f;
    const int e0 = g_rowp[n], e1 = g_rowp[n + 1];

    // distance-2 software pipeline on the fp16 gather
    uint4 c0, d0;
    c0 = *(const uint4*)(g_xlh + (size_t)g_col[e0] * EMB + j0);
    if (e0 + 1 < e1)
        d0 = *(const uint4*)(g_xlh + (size_t)g_col[e0 + 1] * EMB + j0);
    for (int e = e0; e < e1; e++) {
        const uint4 lv = c0;
        c0 = d0;
        if (e + 2 < e1)
            d0 = *(const uint4*)(g_xlh + (size_t)g_col[e + 2] * EMB + j0);
        float xl8[8];
        unpack_h8(lv, xl8);
        float part = 0.f;
        #pragma unroll
        for (int u = 0; u < 8; u++) {
            float s = xl8[u] + xr8[u];
            s = s > 0.f ? s : 0.2f * s;
            part += s * sA[u];
        }
        part += __shfl_xor_sync(0xffffffffu, part, 1);
        part += __shfl_xor_sync(0xffffffffu, part, 2);
        part += __shfl_xor_sync(0xffffffffu, part, 4);
        const float p = __expf(part);
        den += p;
        #pragma unroll
        for (int u = 0; u < 8; u++) acc[u] += p * xl8[u];
    }

    const float inv = 1.f / den;

    // residual from hi/lo pair (exact to 2^-17)
    float hold[8];
    {
        const uint4 hh = *(const uint4*)(g_hbh + (size_t)n * EMB + j0);
        const uint4 hl = *(const uint4*)(g_hbl + (size_t)n * EMB + j0);
        float a, b;
        unpack_bf2(hh.x, hold[0], hold[1]);
        unpack_bf2(hh.y, hold[2], hold[3]);
        unpack_bf2(hh.z, hold[4], hold[5]);
        unpack_bf2(hh.w, hold[6], hold[7]);
        unpack_bf2(hl.x, a, b); hold[0] += a; hold[1] += b;
        unpack_bf2(hl.y, a, b); hold[2] += a; hold[3] += b;
        unpack_bf2(hl.z, a, b); hold[4] += a; hold[5] += b;
        unpack_bf2(hl.w, a, b); hold[6] += a; hold[7] += b;
    }

    float outv[8];
    #pragma unroll
    for (int u = 0; u < 8; u++) {
        const int j = j0 + u;
        float v = acc[u] * inv + cb[j];
        v = (v - bm[j]) * (bg[j] * rsqrtf(bv[j] + BN_EPS)) + bb[j];
        v = v > 0.f ? v : __expf(v) - 1.f;
        outv[u] = hold[u] + v;
    }

    // write h pair (always; feeds next GEMM / dec)
    uint4 ph, pl;
    {
        __nv_bfloat16 hbv[8], lbv[8];
        #pragma unroll
        for (int u = 0; u < 8; u++) split_bf16(outv[u], hbv[u], lbv[u]);
        ph.x = ((uint32_t)__bfloat16_as_ushort(hbv[1]) << 16) | __bfloat16_as_ushort(hbv[0]);
        ph.y = ((uint32_t)__bfloat16_as_ushort(hbv[3]) << 16) | __bfloat16_as_ushort(hbv[2]);
        ph.z = ((uint32_t)__bfloat16_as_ushort(hbv[5]) << 16) | __bfloat16_as_ushort(hbv[4]);
        ph.w = ((uint32_t)__bfloat16_as_ushort(hbv[7]) << 16) | __bfloat16_as_ushort(hbv[6]);
        pl.x = ((uint32_t)__bfloat16_as_ushort(lbv[1]) << 16) | __bfloat16_as_ushort(lbv[0]);
        pl.y = ((uint32_t)__bfloat16_as_ushort(lbv[3]) << 16) | __bfloat16_as_ushort(lbv[2]);
        pl.z = ((uint32_t)__bfloat16_as_ushort(lbv[5]) << 16) | __bfloat16_as_ushort(lbv[4]);
        pl.w = ((uint32_t)__bfloat16_as_ushort(lbv[7]) << 16) | __bfloat16_as_ushort(lbv[6]);
    }
    *(uint4*)(g_hbh + (size_t)n * EMB + j0) = ph;
    *(uint4*)(g_hbl + (size_t)n * EMB + j0) = pl;

    if (out_h) {
        // final layer: fp32 h to output + fused heads
        float* op = out_h + (size_t)n * EMB + j0;
        ((float4*)op)[0] = make_float4(outv[0], outv[1], outv[2], outv[3]);
        ((float4*)op)[1] = make_float4(outv[4], outv[5], outv[6], outv[7]);

        float s0 = 0.f, s1 = 0.f, s2 = 0.f, s3 = 0.f;
        #pragma unroll
        for (int u = 0; u < 8; u++) {
            const float hv = outv[u];
            s0 += hv * hW[j0 + u];
            s1 += hv * hW[EMB + j0 + u];
            s2 += hv * hW[2 * EMB + j0 + u];
            s3 += hv * hW[3 * EMB + j0 + u];
        }
        #pragma unroll
        for (int off = 16; off; off >>= 1) {
            s0 += __shfl_xor_sync(0xffffffffu, s0, off);
            s1 += __shfl_xor_sync(0xffffffffu, s1, off);
            s2 += __shfl_xor_sync(0xffffffffu, s2, off);
            s3 += __shfl_xor_sync(0xffffffffu, s3, off);
        }
        if (lane == 0) {
            preds[n]          = s0 + hb[0];
            preds[NN + n]     = s1 + hb[1];
            preds[2 * NN + n] = s2 + hb[2];
            preds[3 * NN + n] = s3 + hb[3];
        }
    }
}

// ---------------- launch ----------------
extern "C" void kernel_launch(void* const* d_in, const int* in_sizes, int n_in,
                              void* d_out, int out_size)
{
    const float* x      = (const float*)d_in[0];
    const int*   ei     = (const int*)  d_in[1];
    const float* proj_W = (const float*)d_in[2];
    const float* proj_b = (const float*)d_in[3];
    const float* ibn_g  = (const float*)d_in[4];
    const float* ibn_b  = (const float*)d_in[5];
    const float* ibn_m  = (const float*)d_in[6];
    const float* ibn_v  = (const float*)d_in[7];
    const float* Wl     = (const float*)d_in[8];
    const float* Wr     = (const float*)d_in[9];
    const float* att    = (const float*)d_in[10];
    const float* conv_b = (const float*)d_in[11];
    const float* bn_g   = (const float*)d_in[12];
    const float* bn_b   = (const float*)d_in[13];
    const float* bn_m   = (const float*)d_in[14];
    const float* bn_v   = (const float*)d_in[15];
    const float* head_W = (const float*)d_in[16];
    const float* head_b = (const float*)d_in[17];
    const float* dec_W  = (const float*)d_in[18];
    const float* dec_b  = (const float*)d_in[19];
    float* out = (float*)d_out;

    __nv_bfloat16 *hbh, *hbl, *xbh, *xbl, *wth, *wtl, *pjh, *pjl, *dch, *dcl;
    cudaGetSymbolAddress((void**)&hbh, g_hbh);
    cudaGetSymbolAddress((void**)&hbl, g_hbl);
    cudaGetSymbolAddress((void**)&xbh, g_xbh);
    cudaGetSymbolAddress((void**)&xbl, g_xbl);
    cudaGetSymbolAddress((void**)&wth, g_wth);
    cudaGetSymbolAddress((void**)&wtl, g_wtl);
    cudaGetSymbolAddress((void**)&pjh, g_pjh);
    cudaGetSymbolAddress((void**)&pjl, g_pjl);
    cudaGetSymbolAddress((void**)&dch, g_dch);
    cudaGetSymbolAddress((void**)&dcl, g_dcl);

    cudaFuncSetAttribute(hgemm<0>, cudaFuncAttributeMaxDynamicSharedMemorySize, SMBYTES);
    cudaFuncSetAttribute(hgemm<1>, cudaFuncAttributeMaxDynamicSharedMemorySize, SMBYTES);
    cudaFuncSetAttribute(hgemm<2>, cudaFuncAttributeMaxDynamicSharedMemorySize, SMBYTES);

    const int gy = (NN + 127) / 128;          // 782
    const int nb = (NN + 255) / 256;          // 391

    // ---- prep: weights (one kernel), x split (+csr zero), CSR ----
    prep_all<<<(PJ_N + WLR_N + DC_N + 255) / 256, 256>>>(proj_W, Wl, Wr, dec_W);
    prep_x<<<(NN * INC / 4 + 255) / 256, 256>>>(x);

    csr_hist<<<(NE + 255) / 256, 256>>>(ei);
    csr_scan1<<<nb, 256>>>();
    csr_scan2<<<1, 512>>>(nb);
    csr_scan3<<<nb, 256>>>();
    csr_fill<<<(NE + 255) / 256, 256>>>(ei);

    // ---- h = elu(bn(x @ proj_W + proj_b)) -> hb pair only ----
    hgemm<1><<<dim3(2, gy), 256, SMBYTES>>>(xbh, xbl, pjh, pjl, nullptr, NN, INC, EMB,
                                            proj_b, ibn_g, ibn_b, ibn_m, ibn_v);

    for (int i = 0; i < NLAYER; i++) {
        hgemm<0><<<dim3(4, gy), 256, SMBYTES>>>(hbh, hbl,
                                                wth + (size_t)i * 512 * EMB,
                                                wtl + (size_t)i * 512 * EMB,
                                                nullptr, NN, EMB, 512,
                                                nullptr, nullptr, nullptr, nullptr, nullptr);
        const bool last = (i == NLAYER - 1);
        gat_aggregate<<<(NN * 32 + 255) / 256, 256>>>(att + (size_t)i * NHEAD * HID,
                                                      conv_b + (size_t)i * EMB,
                                                      bn_g + (size_t)i * EMB, bn_b + (size_t)i * EMB,
                                                      bn_m + (size_t)i * EMB, bn_v + (size_t)i * EMB,
                                                      last ? out + (size_t)4 * NN : nullptr,
                                                      head_W, head_b,
                                                      last ? out : nullptr);
    }

    // recon at out[260N .. 388N)
    hgemm<2><<<dim3(1, gy), 256, SMBYTES>>>(hbh, hbl, dch, dcl, out + (size_t)260 * NN,
                                            NN, EMB, INC, dec_b,
                                            nullptr, nullptr, nullptr, nullptr);
}

// round 14
// speedup vs baseline: 1.5927x; 1.0720x over previous
#include <cuda_runtime.h>
#include <cuda_fp16.h>
#include <math.h>
#include <stdint.h>

#define NN      100000
#define INC     128
#define EMB     256
#define NHEAD   4
#define HID     64
#define NLAYER  3
#define NE      300000
#define ET      400000          // NE + NN self loops
#define BN_EPS  1e-5f

// ---------------- scratch (all fp16) ----------------
__device__ __half g_xlh[(size_t)NN * EMB];                   // xl, fp16
__device__ __half g_xrh[(size_t)NN * EMB];                   // xr, fp16
__device__ __half g_hbh[NN * EMB], g_hbl[NN * EMB];          // h as fp16 hi/lo pair
__device__ __half g_xbh[NN * INC], g_xbl[NN * INC];          // x split fp16
__device__ __half g_wth[NLAYER * 512 * EMB];                 // layer W^T, single fp16
__device__ __half g_pjh[EMB * INC], g_pjl[EMB * INC];        // proj^T hi/lo
__device__ __half g_dch[INC * EMB], g_dcl[INC * EMB];        // dec^T hi/lo
// CSR
__device__ int g_cnt[NN];
__device__ int g_rowp[NN + 1];
__device__ int g_col[ET];
__device__ int g_bsum[512];

__device__ __forceinline__ uint32_t smem_u32(const void* p) {
    uint32_t a;
    asm("{ .reg .u64 t; cvta.to.shared.u64 t, %1; cvt.u32.u64 %0, t; }"
        : "=r"(a) : "l"(p));
    return a;
}
__device__ __forceinline__ void split_f16(float v, __half& h, __half& l) {
    h = __float2half_rn(v);
    l = __float2half_rn(v - __half2float(h));
}
__device__ __forceinline__ void unpack_h8(uint4 v, float* f) {
    float2 a;
    a = __half22float2(*(__half2*)&v.x); f[0] = a.x; f[1] = a.y;
    a = __half22float2(*(__half2*)&v.y); f[2] = a.x; f[3] = a.y;
    a = __half22float2(*(__half2*)&v.z); f[4] = a.x; f[5] = a.y;
    a = __half22float2(*(__half2*)&v.w); f[6] = a.x; f[7] = a.y;
}
__device__ __forceinline__ uint4 pack_h8(const float* f) {
    uint4 r;
    *(__half2*)&r.x = __floats2half2_rn(f[0], f[1]);
    *(__half2*)&r.y = __floats2half2_rn(f[2], f[3]);
    *(__half2*)&r.z = __floats2half2_rn(f[4], f[5]);
    *(__half2*)&r.w = __floats2half2_rn(f[6], f[7]);
    return r;
}

// ---------------- unified weight prep (proj | Wl/Wr | dec) ----------------
#define PJ_N (INC * EMB)                        // 32768
#define WLR_N (NLAYER * 2 * EMB * EMB)          // 393216
#define DC_N (EMB * INC)                        // 32768
__global__ void prep_all(const float* __restrict__ projW, const float* __restrict__ Wl,
                         const float* __restrict__ Wr, const float* __restrict__ decW)
{
    const int idx = blockIdx.x * 256 + threadIdx.x;
    if (idx < PJ_N) {
        const int k = idx >> 8, n = idx & 255;              // [128][256]
        __half h, l;
        split_f16(projW[idx], h, l);
        g_pjh[n * INC + k] = h;
        g_pjl[n * INC + k] = l;
    } else if (idx < PJ_N + WLR_N) {
        const int r0 = idx - PJ_N;
        const int l = r0 / (2 * EMB * EMB);
        const int r = r0 - l * 2 * EMB * EMB;
        const int sel = r / (EMB * EMB);
        const int t = r - sel * EMB * EMB;
        const int k = t / EMB, n = t - k * EMB;
        const float v = (sel ? Wr : Wl)[(size_t)l * EMB * EMB + t];
        const size_t d = (size_t)l * 512 * EMB + (size_t)(sel * 256 + n) * EMB + k;
        g_wth[d] = __float2half_rn(v);
    } else if (idx < PJ_N + WLR_N + DC_N) {
        const int t = idx - PJ_N - WLR_N;
        const int k = t >> 7, n = t & 127;                  // [256][128]
        __half h, l;
        split_f16(decW[t], h, l);
        g_dch[(size_t)n * EMB + k] = h;
        g_dcl[(size_t)n * EMB + k] = l;
    }
}
// vectorized x split + csr count init
__global__ void prep_x(const float* __restrict__ x)
{
    const int idx = blockIdx.x * 256 + threadIdx.x;   // NN*INC/4
    if (idx < NN) g_cnt[idx] = 1;                     // self-loop count
    if (idx >= NN * INC / 4) return;
    const float4 v = ((const float4*)x)[idx];
    __half h0, h1, h2, h3, l0, l1, l2, l3;
    split_f16(v.x, h0, l0); split_f16(v.y, h1, l1);
    split_f16(v.z, h2, l2); split_f16(v.w, h3, l3);
    uint2 hp, lp;
    *(__half2*)&hp.x = __half2(h0, h1);
    *(__half2*)&hp.y = __half2(h2, h3);
    *(__half2*)&lp.x = __half2(l0, l1);
    *(__half2*)&lp.y = __half2(l2, l3);
    ((uint2*)g_xbh)[idx] = hp;
    ((uint2*)g_xbl)[idx] = lp;
}

// ---------------- CSR build ----------------
__global__ void csr_hist(const int* __restrict__ ei) {
    const int e = blockIdx.x * 256 + threadIdx.x;
    if (e < NE) atomicAdd(&g_cnt[ei[NE + e]], 1);
}
__global__ void csr_scan1() {
    __shared__ int s[256];
    const int i = blockIdx.x * 256 + threadIdx.x;
    int v = (i < NN) ? g_cnt[i] : 0;
    s[threadIdx.x] = v;
    __syncthreads();
    int sum = v;
    #pragma unroll
    for (int off = 1; off < 256; off <<= 1) {
        int t = (threadIdx.x >= off) ? s[threadIdx.x - off] : 0;
        __syncthreads();
        s[threadIdx.x] = sum = sum + t;
        __syncthreads();
    }
    if (i < NN) g_rowp[i] = sum - v;
    if (threadIdx.x == 255) g_bsum[blockIdx.x] = s[255];
}
__global__ void csr_scan2(int nb) {
    __shared__ int s[512];
    const int t = threadIdx.x;
    int v = (t < nb) ? g_bsum[t] : 0;
    s[t] = v;
    __syncthreads();
    int sum = v;
    #pragma unroll
    for (int off = 1; off < 512; off <<= 1) {
        int u = (t >= off) ? s[t - off] : 0;
        __syncthreads();
        s[t] = sum = sum + u;
        __syncthreads();
    }
    if (t < nb) g_bsum[t] = sum - v;
}
__global__ void csr_scan3() {
    const int i = blockIdx.x * 256 + threadIdx.x;
    if (i == 0) g_rowp[NN] = ET;
    if (i >= NN) return;
    const int r = g_rowp[i] + g_bsum[i >> 8];
    g_rowp[i] = r;
    g_col[r] = i;
    g_cnt[i] = r + 1;
}
__global__ void csr_fill(const int* __restrict__ ei) {
    const int e = blockIdx.x * 256 + threadIdx.x;
    if (e >= NE) return;
    const int pos = atomicAdd(&g_cnt[ei[NE + e]], 1);
    g_col[pos] = ei[e];
}

// ====== fp16 mma.sync GEMM: 2-stage BK=32 pipeline, occ 2 ================
// terms: 3 (proj/dec: Ah*Bh + Al*Bh + Ah*Bl), 2 (xl: Ah*Bh + Al*Bh, B single),
//        1 (xr: Ah*Bh).
// EPI 0: write fp16 xl/xr   EPI 1: bias+BN+ELU -> h fp16 pair   EPI 2: +bias -> C
#define RS2 40
#define BUF2 (128 * RS2)
#define BUFB (BUF2 * 2)                 // 10240 bytes
#define STAGEB (4 * BUFB)               // 40960 bytes
#define SMBYTES (2 * STAGEB)            // 81920 -> occ 2

#define CPA(dst32, src, pb) \
    asm volatile("cp.async.cg.shared.global [%0], [%1], 16, %2;" \
                 :: "r"(dst32), "l"(src), "r"(pb))

__device__ __forceinline__ void ldsm_x4(uint32_t* r, uint32_t addr) {
    asm volatile("ldmatrix.sync.aligned.m8n8.x4.shared.b16 {%0,%1,%2,%3}, [%4];"
                 : "=r"(r[0]), "=r"(r[1]), "=r"(r[2]), "=r"(r[3]) : "r"(addr));
}
__device__ __forceinline__ void mma16816(float* c, const uint32_t* a, const uint32_t* b) {
    asm volatile("mma.sync.aligned.m16n8k16.row.col.f32.f16.f16.f32 "
                 "{%0,%1,%2,%3}, {%4,%5,%6,%7}, {%8,%9}, {%0,%1,%2,%3};"
                 : "+f"(c[0]), "+f"(c[1]), "+f"(c[2]), "+f"(c[3])
                 : "r"(a[0]), "r"(a[1]), "r"(a[2]), "r"(a[3]), "r"(b[0]), "r"(b[1]));
}

template<int EPI>
__global__ __launch_bounds__(256, 2)
void hgemm(const __half* __restrict__ Ath, const __half* __restrict__ Atl,
           const __half* __restrict__ Bth, const __half* __restrict__ Btl,
           float* __restrict__ C, int M, int K, int NC,
           const float* __restrict__ bias, const float* __restrict__ gg,
           const float* __restrict__ gb, const float* __restrict__ gm,
           const float* __restrict__ gv)
{
    extern __shared__ __half sm[];
    const uint32_t s32 = smem_u32(sm);
    const int tid = threadIdx.x, lane = tid & 31, w = tid >> 5;
    const int m0 = blockIdx.y * 128, n0 = blockIdx.x * 128;
    const int wm = (w >> 2) * 64, wn = (w & 3) * 32;

    // term count: proj/dec = 3, xl = 2, xr = 1
    const int terms = (EPI != 0) ? 3 : (n0 < 256 ? 2 : 1);

    float acc[4][4][4] = {};
    const int nchunks = K >> 5;

    const __half* srcs[4] = {Ath, Atl, Bth, Btl};

    auto load_chunk = [&](int ch, int st) {
        const uint32_t sb = s32 + (uint32_t)st * STAGEB;
        #pragma unroll
        for (int i = 0; i < 8; i++) {
            const int buf = i >> 1;
            if (buf == 1 && terms < 2) continue;     // A-lo only for terms>=2
            if (buf == 3 && terms < 3) continue;     // B-lo only for terms==3
            const int s = (i & 1) * 256 + tid;
            const int r = s >> 2, q = s & 3;
            const int base = (buf < 2) ? m0 : n0;
            const uint32_t doff = (uint32_t)buf * BUFB + (uint32_t)(r * RS2 + q * 8) * 2;
            const size_t goff = (size_t)(base + r) * K + ch * 32 + q * 8;
            const unsigned pb = (buf >= 2 || base + r < M) ? 16u : 0u;
            CPA(sb + doff, srcs[buf] + goff, pb);
        }
        asm volatile("cp.async.commit_group;" ::: "memory");
    };

    load_chunk(0, 0);

    for (int ch = 0; ch < nchunks; ch++) {
        if (ch + 1 < nchunks) {
            load_chunk(ch + 1, (ch + 1) & 1);
            asm volatile("cp.async.wait_group 1;" ::: "memory");
        } else {
            asm volatile("cp.async.wait_group 0;" ::: "memory");
        }
        __syncthreads();

        const uint32_t sb = s32 + (uint32_t)(ch & 1) * STAGEB;
        const int lra = lane & 15, lka = (lane >> 4) * 8;
        const int bt = lane >> 3, blr = lane & 7;

        #pragma unroll
        for (int ks = 0; ks < 2; ks++) {
            const int k0 = ks * 16;
            uint32_t ah[4][4], bh[4][2];
            #pragma unroll
            for (int mt = 0; mt < 4; mt++)
                ldsm_x4(ah[mt], sb + ((wm + mt * 16 + lra) * RS2 + k0 + lka) * 2);
            #pragma unroll
            for (int ntp = 0; ntp < 2; ntp++) {
                const int row = wn + ntp * 16 + ((bt >> 1) << 3) + blr;
                const int col = k0 + (bt & 1) * 8;
                ldsm_x4(&bh[ntp * 2][0], sb + 2 * BUFB + (row * RS2 + col) * 2);
            }
            #pragma unroll
            for (int mt = 0; mt < 4; mt++)
                #pragma unroll
                for (int nt = 0; nt < 4; nt++)
                    mma16816(acc[mt][nt], ah[mt], bh[nt]);

            if (terms >= 2) {
                uint32_t al[4][4];
                #pragma unroll
                for (int mt = 0; mt < 4; mt++)
                    ldsm_x4(al[mt], sb + BUFB + ((wm + mt * 16 + lra) * RS2 + k0 + lka) * 2);
                #pragma unroll
                for (int mt = 0; mt < 4; mt++)
                    #pragma unroll
                    for (int nt = 0; nt < 4; nt++)
                        mma16816(acc[mt][nt], al[mt], bh[nt]);
            }
            if (terms >= 3) {
                uint32_t bl[4][2];
                #pragma unroll
                for (int ntp = 0; ntp < 2; ntp++) {
                    const int row = wn + ntp * 16 + ((bt >> 1) << 3) + blr;
                    const int col = k0 + (bt & 1) * 8;
                    ldsm_x4(&bl[ntp * 2][0], sb + 3 * BUFB + (row * RS2 + col) * 2);
                }
                #pragma unroll
                for (int mt = 0; mt < 4; mt++)
                    #pragma unroll
                    for (int nt = 0; nt < 4; nt++)
                        mma16816(acc[mt][nt], ah[mt], bl[nt]);
            }
        }
        __syncthreads();
    }

    // epilogue: column-paired vectorized stores
    #pragma unroll
    for (int mt = 0; mt < 4; mt++) {
        #pragma unroll
        for (int nt = 0; nt < 4; nt++) {
            #pragma unroll
            for (int qq = 0; qq < 2; qq++) {
                const int row = m0 + wm + mt * 16 + (lane >> 2) + qq * 8;
                const int col = n0 + wn + nt * 8 + 2 * (lane & 3);
                if (row >= M) continue;
                float v0 = acc[mt][nt][qq * 2];
                float v1 = acc[mt][nt][qq * 2 + 1];
                if (EPI == 0) {
                    __half2 hv = __floats2half2_rn(v0, v1);
                    if (n0 < 256)
                        *(__half2*)(g_xlh + (size_t)row * EMB + col) = hv;
                    else
                        *(__half2*)(g_xrh + (size_t)row * EMB + (col - 256)) = hv;
                } else if (EPI == 2) {
                    v0 += bias[col];
                    v1 += bias[col + 1];
                    *(float2*)(C + (size_t)row * NC + col) = make_float2(v0, v1);
                } else {
                    v0 += bias[col];
                    v1 += bias[col + 1];
                    v0 = (v0 - gm[col]) * (gg[col] * rsqrtf(gv[col] + BN_EPS)) + gb[col];
                    v1 = (v1 - gm[col + 1]) * (gg[col + 1] * rsqrtf(gv[col + 1] + BN_EPS)) + gb[col + 1];
                    v0 = v0 > 0.f ? v0 : __expf(v0) - 1.f;
                    v1 = v1 > 0.f ? v1 : __expf(v1) - 1.f;
                    __half h0, l0, h1, l1;
                    split_f16(v0, h0, l0);
                    split_f16(v1, h1, l1);
                    *(__half2*)(g_hbh + (size_t)row * EMB + col) = __half2(h0, h1);
                    *(__half2*)(g_hbl + (size_t)row * EMB + col) = __half2(l0, l1);
                }
            }
        }
    }
}

// ====== fused GATv2 aggregation: warp per dst node (CSR, no atomics) =====
__global__ __launch_bounds__(256)
void gat_aggregate(const float* __restrict__ att, const float* __restrict__ cb,
                   const float* __restrict__ bg, const float* __restrict__ bb,
                   const float* __restrict__ bm, const float* __restrict__ bv,
                   float* __restrict__ out_h,
                   const float* __restrict__ hW, const float* __restrict__ hb,
                   float* __restrict__ preds)
{
    const int lane = threadIdx.x & 31;
    const int n = (blockIdx.x * 256 + threadIdx.x) >> 5;
    if (n >= NN) return;
    const int j0 = lane * 8;

    float sA[8], xr8[8];
    {
        const float4* ap = (const float4*)(att + j0);
        float4 a0 = ap[0], a1 = ap[1];
        sA[0]=a0.x; sA[1]=a0.y; sA[2]=a0.z; sA[3]=a0.w;
        sA[4]=a1.x; sA[5]=a1.y; sA[6]=a1.z; sA[7]=a1.w;
        unpack_h8(*(const uint4*)(g_xrh + (size_t)n * EMB + j0), xr8);
    }

    float acc[8] = {};
    float den = 0.f;
    const int e0 = g_rowp[n], e1 = g_rowp[n + 1];

    // distance-2 software pipeline on the fp16 gather
    uint4 c0, d0;
    c0 = *(const uint4*)(g_xlh + (size_t)g_col[e0] * EMB + j0);
    if (e0 + 1 < e1)
        d0 = *(const uint4*)(g_xlh + (size_t)g_col[e0 + 1] * EMB + j0);
    for (int e = e0; e < e1; e++) {
        const uint4 lv = c0;
        c0 = d0;
        if (e + 2 < e1)
            d0 = *(const uint4*)(g_xlh + (size_t)g_col[e + 2] * EMB + j0);
        float xl8[8];
        unpack_h8(lv, xl8);
        float part = 0.f;
        #pragma unroll
        for (int u = 0; u < 8; u++) {
            float s = xl8[u] + xr8[u];
            s = s > 0.f ? s : 0.2f * s;
            part += s * sA[u];
        }
        part += __shfl_xor_sync(0xffffffffu, part, 1);
        part += __shfl_xor_sync(0xffffffffu, part, 2);
        part += __shfl_xor_sync(0xffffffffu, part, 4);
        const float p = __expf(part);
        den += p;
        #pragma unroll
        for (int u = 0; u < 8; u++) acc[u] += p * xl8[u];
    }

    const float inv = 1.f / den;

    // residual from fp16 hi/lo pair (exact to 2^-22)
    float hold[8];
    {
        float tmp[8];
        unpack_h8(*(const uint4*)(g_hbh + (size_t)n * EMB + j0), hold);
        unpack_h8(*(const uint4*)(g_hbl + (size_t)n * EMB + j0), tmp);
        #pragma unroll
        for (int u = 0; u < 8; u++) hold[u] += tmp[u];
    }

    float outv[8];
    #pragma unroll
    for (int u = 0; u < 8; u++) {
        const int j = j0 + u;
        float v = acc[u] * inv + cb[j];
        v = (v - bm[j]) * (bg[j] * rsqrtf(bv[j] + BN_EPS)) + bb[j];
        v = v > 0.f ? v : __expf(v) - 1.f;
        outv[u] = hold[u] + v;
    }

    // write h pair (always; feeds next GEMM / dec)
    {
        float hi8[8], lo8[8];
        #pragma unroll
        for (int u = 0; u < 8; u++) {
            __half h, l;
            split_f16(outv[u], h, l);
            hi8[u] = __half2float(h);       // re-expand for exact packing below
            lo8[u] = __half2float(l);
        }
        *(uint4*)(g_hbh + (size_t)n * EMB + j0) = pack_h8(hi8);
        *(uint4*)(g_hbl + (size_t)n * EMB + j0) = pack_h8(lo8);
    }

    if (out_h) {
        // final layer: fp32 h to output + fused heads
        float* op = out_h + (size_t)n * EMB + j0;
        ((float4*)op)[0] = make_float4(outv[0], outv[1], outv[2], outv[3]);
        ((float4*)op)[1] = make_float4(outv[4], outv[5], outv[6], outv[7]);

        float s0 = 0.f, s1 = 0.f, s2 = 0.f, s3 = 0.f;
        #pragma unroll
        for (int u = 0; u < 8; u++) {
            const float hv = outv[u];
            s0 += hv * hW[j0 + u];
            s1 += hv * hW[EMB + j0 + u];
            s2 += hv * hW[2 * EMB + j0 + u];
            s3 += hv * hW[3 * EMB + j0 + u];
        }
        #pragma unroll
        for (int off = 16; off; off >>= 1) {
            s0 += __shfl_xor_sync(0xffffffffu, s0, off);
            s1 += __shfl_xor_sync(0xffffffffu, s1, off);
            s2 += __shfl_xor_sync(0xffffffffu, s2, off);
            s3 += __shfl_xor_sync(0xffffffffu, s3, off);
        }
        if (lane == 0) {
            preds[n]          = s0 + hb[0];
            preds[NN + n]     = s1 + hb[1];
            preds[2 * NN + n] = s2 + hb[2];
            preds[3 * NN + n] = s3 + hb[3];
        }
    }
}

// ---------------- launch ----------------
extern "C" void kernel_launch(void* const* d_in, const int* in_sizes, int n_in,
                              void* d_out, int out_size)
{
    const float* x      = (const float*)d_in[0];
    const int*   ei     = (const int*)  d_in[1];
    const float* proj_W = (const float*)d_in[2];
    const float* proj_b = (const float*)d_in[3];
    const float* ibn_g  = (const float*)d_in[4];
    const float* ibn_b  = (const float*)d_in[5];
    const float* ibn_m  = (const float*)d_in[6];
    const float* ibn_v  = (const float*)d_in[7];
    const float* Wl     = (const float*)d_in[8];
    const float* Wr     = (const float*)d_in[9];
    const float* att    = (const float*)d_in[10];
    const float* conv_b = (const float*)d_in[11];
    const float* bn_g   = (const float*)d_in[12];
    const float* bn_b   = (const float*)d_in[13];
    const float* bn_m   = (const float*)d_in[14];
    const float* bn_v   = (const float*)d_in[15];
    const float* head_W = (const float*)d_in[16];
    const float* head_b = (const float*)d_in[17];
    const float* dec_W  = (const float*)d_in[18];
    const float* dec_b  = (const float*)d_in[19];
    float* out = (float*)d_out;

    __half *hbh, *hbl, *xbh, *xbl, *wth, *pjh, *pjl, *dch, *dcl;
    cudaGetSymbolAddress((void**)&hbh, g_hbh);
    cudaGetSymbolAddress((void**)&hbl, g_hbl);
    cudaGetSymbolAddress((void**)&xbh, g_xbh);
    cudaGetSymbolAddress((void**)&xbl, g_xbl);
    cudaGetSymbolAddress((void**)&wth, g_wth);
    cudaGetSymbolAddress((void**)&pjh, g_pjh);
    cudaGetSymbolAddress((void**)&pjl, g_pjl);
    cudaGetSymbolAddress((void**)&dch, g_dch);
    cudaGetSymbolAddress((void**)&dcl, g_dcl);

    cudaFuncSetAttribute(hgemm<0>, cudaFuncAttributeMaxDynamicSharedMemorySize, SMBYTES);
    cudaFuncSetAttribute(hgemm<1>, cudaFuncAttributeMaxDynamicSharedMemorySize, SMBYTES);
    cudaFuncSetAttribute(hgemm<2>, cudaFuncAttributeMaxDynamicSharedMemorySize, SMBYTES);

    const int gy = (NN + 127) / 128;          // 782
    const int nb = (NN + 255) / 256;          // 391

    // ---- prep: weights (one kernel), x split (+csr zero), CSR ----
    prep_all<<<(PJ_N + WLR_N + DC_N + 255) / 256, 256>>>(proj_W, Wl, Wr, dec_W);
    prep_x<<<(NN * INC / 4 + 255) / 256, 256>>>(x);

    csr_hist<<<(NE + 255) / 256, 256>>>(ei);
    csr_scan1<<<nb, 256>>>();
    csr_scan2<<<1, 512>>>(nb);
    csr_scan3<<<nb, 256>>>();
    csr_fill<<<(NE + 255) / 256, 256>>>(ei);

    // ---- h = elu(bn(x @ proj_W + proj_b)) -> h fp16 pair ----
    hgemm<1><<<dim3(2, gy), 256, SMBYTES>>>(xbh, xbl, pjh, pjl, nullptr, NN, INC, EMB,
                                            proj_b, ibn_g, ibn_b, ibn_m, ibn_v);

    for (int i = 0; i < NLAYER; i++) {
        hgemm<0><<<dim3(4, gy), 256, SMBYTES>>>(hbh, hbl,
                                                wth + (size_t)i * 512 * EMB, nullptr,
                                                nullptr, NN, EMB, 512,
                                                nullptr, nullptr, nullptr, nullptr, nullptr);
        const bool last = (i == NLAYER - 1);
        gat_aggregate<<<(NN * 32 + 255) / 256, 256>>>(att + (size_t)i * NHEAD * HID,
                                                      conv_b + (size_t)i * EMB,
                                                      bn_g + (size_t)i * EMB, bn_b + (size_t)i * EMB,
                                                      bn_m + (size_t)i * EMB, bn_v + (size_t)i * EMB,
                                                      last ? out + (size_t)4 * NN : nullptr,
                                                      head_W, head_b,
                                                      last ? out : nullptr);
    }

    // recon at out[260N .. 388N)
    hgemm<2><<<dim3(1, gy), 256, SMBYTES>>>(hbh, hbl, dch, dcl, out + (size_t)260 * NN,
                                            NN, EMB, INC, dec_b,
                                            nullptr, nullptr, nullptr, nullptr);
}

// round 15
// speedup vs baseline: 1.6510x; 1.0366x over previous
#include <cuda_runtime.h>
#include <cuda_fp16.h>
#include <math.h>
#include <stdint.h>

#define NN      100000
#define INC     128
#define EMB     256
#define NHEAD   4
#define HID     64
#define NLAYER  3
#define NE      300000
#define ET      400000          // NE + NN self loops
#define BN_EPS  1e-5f

// ---------------- scratch (all fp16) ----------------
__device__ __half g_xlh[(size_t)NN * EMB];                   // xl, fp16
__device__ __half g_xrh[(size_t)NN * EMB];                   // xr, fp16
__device__ __half g_hbh[NN * EMB], g_hbl[NN * EMB];          // h as fp16 hi/lo pair
__device__ __half g_xbh[NN * INC], g_xbl[NN * INC];          // x split fp16
__device__ __half g_wth[NLAYER * 512 * EMB];                 // layer W^T, single fp16
__device__ __half g_pjh[EMB * INC], g_pjl[EMB * INC];        // proj^T hi/lo
__device__ __half g_dch[INC * EMB], g_dcl[INC * EMB];        // dec^T hi/lo
// CSR
__device__ int g_cnt[NN];
__device__ int g_rowp[NN + 1];
__device__ int g_col[ET];
__device__ int g_bsum[512];

__device__ __forceinline__ uint32_t smem_u32(const void* p) {
    uint32_t a;
    asm("{ .reg .u64 t; cvta.to.shared.u64 t, %1; cvt.u32.u64 %0, t; }"
        : "=r"(a) : "l"(p));
    return a;
}
__device__ __forceinline__ void split_f16(float v, __half& h, __half& l) {
    h = __float2half_rn(v);
    l = __float2half_rn(v - __half2float(h));
}
__device__ __forceinline__ void unpack_h8(uint4 v, float* f) {
    float2 a;
    a = __half22float2(*(__half2*)&v.x); f[0] = a.x; f[1] = a.y;
    a = __half22float2(*(__half2*)&v.y); f[2] = a.x; f[3] = a.y;
    a = __half22float2(*(__half2*)&v.z); f[4] = a.x; f[5] = a.y;
    a = __half22float2(*(__half2*)&v.w); f[6] = a.x; f[7] = a.y;
}
__device__ __forceinline__ uint4 pack_h8(const float* f) {
    uint4 r;
    *(__half2*)&r.x = __floats2half2_rn(f[0], f[1]);
    *(__half2*)&r.y = __floats2half2_rn(f[2], f[3]);
    *(__half2*)&r.z = __floats2half2_rn(f[4], f[5]);
    *(__half2*)&r.w = __floats2half2_rn(f[6], f[7]);
    return r;
}

// ---------------- unified weight prep (proj | Wl/Wr | dec) ----------------
#define PJ_N (INC * EMB)                        // 32768
#define WLR_N (NLAYER * 2 * EMB * EMB)          // 393216
#define DC_N (EMB * INC)                        // 32768
__global__ void prep_all(const float* __restrict__ projW, const float* __restrict__ Wl,
                         const float* __restrict__ Wr, const float* __restrict__ decW)
{
    const int idx = blockIdx.x * 256 + threadIdx.x;
    if (idx < PJ_N) {
        const int k = idx >> 8, n = idx & 255;              // [128][256]
        __half h, l;
        split_f16(projW[idx], h, l);
        g_pjh[n * INC + k] = h;
        g_pjl[n * INC + k] = l;
    } else if (idx < PJ_N + WLR_N) {
        const int r0 = idx - PJ_N;
        const int l = r0 / (2 * EMB * EMB);
        const int r = r0 - l * 2 * EMB * EMB;
        const int sel = r / (EMB * EMB);
        const int t = r - sel * EMB * EMB;
        const int k = t / EMB, n = t - k * EMB;
        const float v = (sel ? Wr : Wl)[(size_t)l * EMB * EMB + t];
        const size_t d = (size_t)l * 512 * EMB + (size_t)(sel * 256 + n) * EMB + k;
        g_wth[d] = __float2half_rn(v);
    } else if (idx < PJ_N + WLR_N + DC_N) {
        const int t = idx - PJ_N - WLR_N;
        const int k = t >> 7, n = t & 127;                  // [256][128]
        __half h, l;
        split_f16(decW[t], h, l);
        g_dch[(size_t)n * EMB + k] = h;
        g_dcl[(size_t)n * EMB + k] = l;
    }
}
// vectorized x split + csr count init
__global__ void prep_x(const float* __restrict__ x)
{
    const int idx = blockIdx.x * 256 + threadIdx.x;   // NN*INC/4
    if (idx < NN) g_cnt[idx] = 1;                     // self-loop count
    if (idx >= NN * INC / 4) return;
    const float4 v = ((const float4*)x)[idx];
    __half h0, h1, h2, h3, l0, l1, l2, l3;
    split_f16(v.x, h0, l0); split_f16(v.y, h1, l1);
    split_f16(v.z, h2, l2); split_f16(v.w, h3, l3);
    uint2 hp, lp;
    *(__half2*)&hp.x = __half2(h0, h1);
    *(__half2*)&hp.y = __half2(h2, h3);
    *(__half2*)&lp.x = __half2(l0, l1);
    *(__half2*)&lp.y = __half2(l2, l3);
    ((uint2*)g_xbh)[idx] = hp;
    ((uint2*)g_xbl)[idx] = lp;
}

// ---------------- CSR build ----------------
__global__ void csr_hist(const int* __restrict__ ei) {
    const int e = blockIdx.x * 256 + threadIdx.x;
    if (e < NE) atomicAdd(&g_cnt[ei[NE + e]], 1);
}
__global__ void csr_scan1() {
    __shared__ int s[256];
    const int i = blockIdx.x * 256 + threadIdx.x;
    int v = (i < NN) ? g_cnt[i] : 0;
    s[threadIdx.x] = v;
    __syncthreads();
    int sum = v;
    #pragma unroll
    for (int off = 1; off < 256; off <<= 1) {
        int t = (threadIdx.x >= off) ? s[threadIdx.x - off] : 0;
        __syncthreads();
        s[threadIdx.x] = sum = sum + t;
        __syncthreads();
    }
    if (i < NN) g_rowp[i] = sum - v;
    if (threadIdx.x == 255) g_bsum[blockIdx.x] = s[255];
}
__global__ void csr_scan2(int nb) {
    __shared__ int s[512];
    const int t = threadIdx.x;
    int v = (t < nb) ? g_bsum[t] : 0;
    s[t] = v;
    __syncthreads();
    int sum = v;
    #pragma unroll
    for (int off = 1; off < 512; off <<= 1) {
        int u = (t >= off) ? s[t - off] : 0;
        __syncthreads();
        s[t] = sum = sum + u;
        __syncthreads();
    }
    if (t < nb) g_bsum[t] = sum - v;
}
__global__ void csr_scan3() {
    const int i = blockIdx.x * 256 + threadIdx.x;
    if (i == 0) g_rowp[NN] = ET;
    if (i >= NN) return;
    const int r = g_rowp[i] + g_bsum[i >> 8];
    g_rowp[i] = r;
    g_col[r] = i;
    g_cnt[i] = r + 1;
}
__global__ void csr_fill(const int* __restrict__ ei) {
    const int e = blockIdx.x * 256 + threadIdx.x;
    if (e >= NE) return;
    const int pos = atomicAdd(&g_cnt[ei[NE + e]], 1);
    g_col[pos] = ei[e];
}

// ====== fp16 mma.sync GEMM, 2-stage pipeline, occ 2 ======================
// EPI 0 (layer): BK=64, 3 buffers (A-hi/A-lo/B-hi); xl blocks 2 terms,
//                xr blocks 1 term. writes fp16 xl/xr.
// EPI 1 (proj) / 2 (dec): BK=32, 4 buffers, 3 terms.
#define CPA(dst32, src, pb) \
    asm volatile("cp.async.cg.shared.global [%0], [%1], 16, %2;" \
                 :: "r"(dst32), "l"(src), "r"(pb))

__device__ __forceinline__ void ldsm_x4(uint32_t* r, uint32_t addr) {
    asm volatile("ldmatrix.sync.aligned.m8n8.x4.shared.b16 {%0,%1,%2,%3}, [%4];"
                 : "=r"(r[0]), "=r"(r[1]), "=r"(r[2]), "=r"(r[3]) : "r"(addr));
}
__device__ __forceinline__ void mma16816(float* c, const uint32_t* a, const uint32_t* b) {
    asm volatile("mma.sync.aligned.m16n8k16.row.col.f32.f16.f16.f32 "
                 "{%0,%1,%2,%3}, {%4,%5,%6,%7}, {%8,%9}, {%0,%1,%2,%3};"
                 : "+f"(c[0]), "+f"(c[1]), "+f"(c[2]), "+f"(c[3])
                 : "r"(a[0]), "r"(a[1]), "r"(a[2]), "r"(a[3]), "r"(b[0]), "r"(b[1]));
}

template<int EPI>
__global__ __launch_bounds__(256, 2)
void hgemm(const __half* __restrict__ Ath, const __half* __restrict__ Atl,
           const __half* __restrict__ Bth, const __half* __restrict__ Btl,
           float* __restrict__ C, int M, int K, int NC,
           const float* __restrict__ bias, const float* __restrict__ gg,
           const float* __restrict__ gb, const float* __restrict__ gm,
           const float* __restrict__ gv)
{
    constexpr int BKT  = (EPI == 0) ? 64 : 32;     // K per chunk
    constexpr int RS   = BKT + 8;                  // row stride (elems)
    constexpr int BUFB = 128 * RS * 2;             // bytes per operand buffer
    constexpr int NBUF = (EPI == 0) ? 3 : 4;       // A-hi, A-lo, B-hi, [B-lo]
    constexpr int STAGE = NBUF * BUFB;
    constexpr int CPR  = BKT / 8;                  // 16B cps per row
    constexpr int CPIT = 128 * CPR / 256;          // cp iters per buffer
    constexpr int KSIT = BKT / 16;                 // k-steps per chunk

    extern __shared__ __half sm[];
    const uint32_t s32 = smem_u32(sm);
    const int tid = threadIdx.x, lane = tid & 31, w = tid >> 5;
    const int m0 = blockIdx.y * 128, n0 = blockIdx.x * 128;
    const int wm = (w >> 2) * 64, wn = (w & 3) * 32;

    // term count: proj/dec = 3, xl = 2, xr = 1
    const int terms = (EPI != 0) ? 3 : (n0 < 256 ? 2 : 1);

    float acc[4][4][4] = {};
    const int nchunks = K / BKT;

    const __half* srcs[4] = {Ath, Atl, Bth, Btl};

    auto load_chunk = [&](int ch, int st) {
        const uint32_t sb = s32 + (uint32_t)st * STAGE;
        #pragma unroll
        for (int buf = 0; buf < NBUF; buf++) {
            if (buf == 1 && terms < 2) continue;     // A-lo only for terms>=2
            if (buf == 3 && terms < 3) continue;     // B-lo only for terms==3
            #pragma unroll
            for (int it = 0; it < CPIT; it++) {
                const int s = it * 256 + tid;
                const int r = s / CPR, q = s % CPR;
                const int base = (buf < 2) ? m0 : n0;
                const uint32_t doff = (uint32_t)buf * BUFB + (uint32_t)(r * RS + q * 8) * 2;
                const size_t goff = (size_t)(base + r) * K + ch * BKT + q * 8;
                const unsigned pb = (buf >= 2 || base + r < M) ? 16u : 0u;
                CPA(sb + doff, srcs[buf] + goff, pb);
            }
        }
        asm volatile("cp.async.commit_group;" ::: "memory");
    };

    load_chunk(0, 0);

    for (int ch = 0; ch < nchunks; ch++) {
        if (ch + 1 < nchunks) {
            load_chunk(ch + 1, (ch + 1) & 1);
            asm volatile("cp.async.wait_group 1;" ::: "memory");
        } else {
            asm volatile("cp.async.wait_group 0;" ::: "memory");
        }
        __syncthreads();

        const uint32_t sb = s32 + (uint32_t)(ch & 1) * STAGE;
        const int lra = lane & 15, lka = (lane >> 4) * 8;
        const int bt = lane >> 3, blr = lane & 7;

        #pragma unroll
        for (int ks = 0; ks < KSIT; ks++) {
            const int k0 = ks * 16;
            uint32_t ah[4][4], bh[4][2];
            #pragma unroll
            for (int mt = 0; mt < 4; mt++)
                ldsm_x4(ah[mt], sb + ((wm + mt * 16 + lra) * RS + k0 + lka) * 2);
            #pragma unroll
            for (int ntp = 0; ntp < 2; ntp++) {
                const int row = wn + ntp * 16 + ((bt >> 1) << 3) + blr;
                const int col = k0 + (bt & 1) * 8;
                ldsm_x4(&bh[ntp * 2][0], sb + 2 * BUFB + (row * RS + col) * 2);
            }
            #pragma unroll
            for (int mt = 0; mt < 4; mt++)
                #pragma unroll
                for (int nt = 0; nt < 4; nt++)
                    mma16816(acc[mt][nt], ah[mt], bh[nt]);

            if (terms >= 2) {
                uint32_t al[4][4];
                #pragma unroll
                for (int mt = 0; mt < 4; mt++)
                    ldsm_x4(al[mt], sb + BUFB + ((wm + mt * 16 + lra) * RS + k0 + lka) * 2);
                #pragma unroll
                for (int mt = 0; mt < 4; mt++)
                    #pragma unroll
                    for (int nt = 0; nt < 4; nt++)
                        mma16816(acc[mt][nt], al[mt], bh[nt]);
            }
            if (NBUF == 4 && terms >= 3) {
                uint32_t bl[4][2];
                #pragma unroll
                for (int ntp = 0; ntp < 2; ntp++) {
                    const int row = wn + ntp * 16 + ((bt >> 1) << 3) + blr;
                    const int col = k0 + (bt & 1) * 8;
                    ldsm_x4(&bl[ntp * 2][0], sb + 3 * BUFB + (row * RS + col) * 2);
                }
                #pragma unroll
                for (int mt = 0; mt < 4; mt++)
                    #pragma unroll
                    for (int nt = 0; nt < 4; nt++)
                        mma16816(acc[mt][nt], ah[mt], bl[nt]);
            }
        }
        __syncthreads();
    }

    // epilogue: column-paired vectorized stores
    #pragma unroll
    for (int mt = 0; mt < 4; mt++) {
        #pragma unroll
        for (int nt = 0; nt < 4; nt++) {
            #pragma unroll
            for (int qq = 0; qq < 2; qq++) {
                const int row = m0 + wm + mt * 16 + (lane >> 2) + qq * 8;
                const int col = n0 + wn + nt * 8 + 2 * (lane & 3);
                if (row >= M) continue;
                float v0 = acc[mt][nt][qq * 2];
                float v1 = acc[mt][nt][qq * 2 + 1];
                if (EPI == 0) {
                    __half2 hv = __floats2half2_rn(v0, v1);
                    if (n0 < 256)
                        *(__half2*)(g_xlh + (size_t)row * EMB + col) = hv;
                    else
                        *(__half2*)(g_xrh + (size_t)row * EMB + (col - 256)) = hv;
                } else if (EPI == 2) {
                    v0 += bias[col];
                    v1 += bias[col + 1];
                    *(float2*)(C + (size_t)row * NC + col) = make_float2(v0, v1);
                } else {
                    v0 += bias[col];
                    v1 += bias[col + 1];
                    v0 = (v0 - gm[col]) * (gg[col] * rsqrtf(gv[col] + BN_EPS)) + gb[col];
                    v1 = (v1 - gm[col + 1]) * (gg[col + 1] * rsqrtf(gv[col + 1] + BN_EPS)) + gb[col + 1];
                    v0 = v0 > 0.f ? v0 : __expf(v0) - 1.f;
                    v1 = v1 > 0.f ? v1 : __expf(v1) - 1.f;
                    __half h0, l0, h1, l1;
                    split_f16(v0, h0, l0);
                    split_f16(v1, h1, l1);
                    *(__half2*)(g_hbh + (size_t)row * EMB + col) = __half2(h0, h1);
                    *(__half2*)(g_hbl + (size_t)row * EMB + col) = __half2(l0, l1);
                }
            }
        }
    }
}

// ====== fused GATv2 aggregation: warp per dst node (CSR, no atomics) =====
__global__ __launch_bounds__(256)
void gat_aggregate(const float* __restrict__ att, const float* __restrict__ cb,
                   const float* __restrict__ bg, const float* __restrict__ bb,
                   const float* __restrict__ bm, const float* __restrict__ bv,
                   float* __restrict__ out_h,
                   const float* __restrict__ hW, const float* __restrict__ hb,
                   float* __restrict__ preds)
{
    const int lane = threadIdx.x & 31;
    const int n = (blockIdx.x * 256 + threadIdx.x) >> 5;
    if (n >= NN) return;
    const int j0 = lane * 8;

    float sA[8], xr8[8];
    {
        const float4* ap = (const float4*)(att + j0);
        float4 a0 = ap[0], a1 = ap[1];
        sA[0]=a0.x; sA[1]=a0.y; sA[2]=a0.z; sA[3]=a0.w;
        sA[4]=a1.x; sA[5]=a1.y; sA[6]=a1.z; sA[7]=a1.w;
        unpack_h8(*(const uint4*)(g_xrh + (size_t)n * EMB + j0), xr8);
    }

    float acc[8] = {};
    float den = 0.f;
    const int e0 = g_rowp[n], e1 = g_rowp[n + 1];

    // distance-2 software pipeline on the fp16 gather
    uint4 c0, d0;
    c0 = *(const uint4*)(g_xlh + (size_t)g_col[e0] * EMB + j0);
    if (e0 + 1 < e1)
        d0 = *(const uint4*)(g_xlh + (size_t)g_col[e0 + 1] * EMB + j0);
    for (int e = e0; e < e1; e++) {
        const uint4 lv = c0;
        c0 = d0;
        if (e + 2 < e1)
            d0 = *(const uint4*)(g_xlh + (size_t)g_col[e + 2] * EMB + j0);
        float xl8[8];
        unpack_h8(lv, xl8);
        float part = 0.f;
        #pragma unroll
        for (int u = 0; u < 8; u++) {
            float s = xl8[u] + xr8[u];
            s = s > 0.f ? s : 0.2f * s;
            part += s * sA[u];
        }
        part += __shfl_xor_sync(0xffffffffu, part, 1);
        part += __shfl_xor_sync(0xffffffffu, part, 2);
        part += __shfl_xor_sync(0xffffffffu, part, 4);
        const float p = __expf(part);
        den += p;
        #pragma unroll
        for (int u = 0; u < 8; u++) acc[u] += p * xl8[u];
    }

    const float inv = 1.f / den;

    // residual from fp16 hi/lo pair (exact to 2^-22)
    float hold[8];
    {
        float tmp[8];
        unpack_h8(*(const uint4*)(g_hbh + (size_t)n * EMB + j0), hold);
        unpack_h8(*(const uint4*)(g_hbl + (size_t)n * EMB + j0), tmp);
        #pragma unroll
        for (int u = 0; u < 8; u++) hold[u] += tmp[u];
    }

    float outv[8];
    #pragma unroll
    for (int u = 0; u < 8; u++) {
        const int j = j0 + u;
        float v = acc[u] * inv + cb[j];
        v = (v - bm[j]) * (bg[j] * rsqrtf(bv[j] + BN_EPS)) + bb[j];
        v = v > 0.f ? v : __expf(v) - 1.f;
        outv[u] = hold[u] + v;
    }

    // write h pair (always; feeds next GEMM / dec)
    {
        float hi8[8], lo8[8];
        #pragma unroll
        for (int u = 0; u < 8; u++) {
            __half h, l;
            split_f16(outv[u], h, l);
            hi8[u] = __half2float(h);
            lo8[u] = __half2float(l);
        }
        *(uint4*)(g_hbh + (size_t)n * EMB + j0) = pack_h8(hi8);
        *(uint4*)(g_hbl + (size_t)n * EMB + j0) = pack_h8(lo8);
    }

    if (out_h) {
        // final layer: fp32 h to output + fused heads
        float* op = out_h + (size_t)n * EMB + j0;
        ((float4*)op)[0] = make_float4(outv[0], outv[1], outv[2], outv[3]);
        ((float4*)op)[1] = make_float4(outv[4], outv[5], outv[6], outv[7]);

        float s0 = 0.f, s1 = 0.f, s2 = 0.f, s3 = 0.f;
        #pragma unroll
        for (int u = 0; u < 8; u++) {
            const float hv = outv[u];
            s0 += hv * hW[j0 + u];
            s1 += hv * hW[EMB + j0 + u];
            s2 += hv * hW[2 * EMB + j0 + u];
            s3 += hv * hW[3 * EMB + j0 + u];
        }
        #pragma unroll
        for (int off = 16; off; off >>= 1) {
            s0 += __shfl_xor_sync(0xffffffffu, s0, off);
            s1 += __shfl_xor_sync(0xffffffffu, s1, off);
            s2 += __shfl_xor_sync(0xffffffffu, s2, off);
            s3 += __shfl_xor_sync(0xffffffffu, s3, off);
        }
        if (lane == 0) {
            preds[n]          = s0 + hb[0];
            preds[NN + n]     = s1 + hb[1];
            preds[2 * NN + n] = s2 + hb[2];
            preds[3 * NN + n] = s3 + hb[3];
        }
    }
}

// ---------------- launch ----------------
extern "C" void kernel_launch(void* const* d_in, const int* in_sizes, int n_in,
                              void* d_out, int out_size)
{
    const float* x      = (const float*)d_in[0];
    const int*   ei     = (const int*)  d_in[1];
    const float* proj_W = (const float*)d_in[2];
    const float* proj_b = (const float*)d_in[3];
    const float* ibn_g  = (const float*)d_in[4];
    const float* ibn_b  = (const float*)d_in[5];
    const float* ibn_m  = (const float*)d_in[6];
    const float* ibn_v  = (const float*)d_in[7];
    const float* Wl     = (const float*)d_in[8];
    const float* Wr     = (const float*)d_in[9];
    const float* att    = (const float*)d_in[10];
    const float* conv_b = (const float*)d_in[11];
    const float* bn_g   = (const float*)d_in[12];
    const float* bn_b   = (const float*)d_in[13];
    const float* bn_m   = (const float*)d_in[14];
    const float* bn_v   = (const float*)d_in[15];
    const float* head_W = (const float*)d_in[16];
    const float* head_b = (const float*)d_in[17];
    const float* dec_W  = (const float*)d_in[18];
    const float* dec_b  = (const float*)d_in[19];
    float* out = (float*)d_out;

    __half *hbh, *hbl, *xbh, *xbl, *wth, *pjh, *pjl, *dch, *dcl;
    cudaGetSymbolAddress((void**)&hbh, g_hbh);
    cudaGetSymbolAddress((void**)&hbl, g_hbl);
    cudaGetSymbolAddress((void**)&xbh, g_xbh);
    cudaGetSymbolAddress((void**)&xbl, g_xbl);
    cudaGetSymbolAddress((void**)&wth, g_wth);
    cudaGetSymbolAddress((void**)&pjh, g_pjh);
    cudaGetSymbolAddress((void**)&pjl, g_pjl);
    cudaGetSymbolAddress((void**)&dch, g_dch);
    cudaGetSymbolAddress((void**)&dcl, g_dcl);

    // smem: EPI0 = 2 stages * 3 bufs * 128*72*2  = 110592
    //       EPI1/2 = 2 stages * 4 bufs * 128*40*2 = 81920
    const int SM_L = 2 * 3 * 128 * 72 * 2;
    const int SM_P = 2 * 4 * 128 * 40 * 2;
    cudaFuncSetAttribute(hgemm<0>, cudaFuncAttributeMaxDynamicSharedMemorySize, SM_L);
    cudaFuncSetAttribute(hgemm<1>, cudaFuncAttributeMaxDynamicSharedMemorySize, SM_P);
    cudaFuncSetAttribute(hgemm<2>, cudaFuncAttributeMaxDynamicSharedMemorySize, SM_P);

    const int gy = (NN + 127) / 128;          // 782
    const int nb = (NN + 255) / 256;          // 391

    // ---- prep: weights (one kernel), x split (+csr zero), CSR ----
    prep_all<<<(PJ_N + WLR_N + DC_N + 255) / 256, 256>>>(proj_W, Wl, Wr, dec_W);
    prep_x<<<(NN * INC / 4 + 255) / 256, 256>>>(x);

    csr_hist<<<(NE + 255) / 256, 256>>>(ei);
    csr_scan1<<<nb, 256>>>();
    csr_scan2<<<1, 512>>>(nb);
    csr_scan3<<<nb, 256>>>();
    csr_fill<<<(NE + 255) / 256, 256>>>(ei);

    // ---- h = elu(bn(x @ proj_W + proj_b)) -> h fp16 pair ----
    hgemm<1><<<dim3(2, gy), 256, SM_P>>>(xbh, xbl, pjh, pjl, nullptr, NN, INC, EMB,
                                         proj_b, ibn_g, ibn_b, ibn_m, ibn_v);

    for (int i = 0; i < NLAYER; i++) {
        hgemm<0><<<dim3(4, gy), 256, SM_L>>>(hbh, hbl,
                                             wth + (size_t)i * 512 * EMB, nullptr,
                                             nullptr, NN, EMB, 512,
                                             nullptr, nullptr, nullptr, nullptr, nullptr);
        const bool last = (i == NLAYER - 1);
        gat_aggregate<<<(NN * 32 + 255) / 256, 256>>>(att + (size_t)i * NHEAD * HID,
                                                      conv_b + (size_t)i * EMB,
                                                      bn_g + (size_t)i * EMB, bn_b + (size_t)i * EMB,
                                                      bn_m + (size_t)i * EMB, bn_v + (size_t)i * EMB,
                                                      last ? out + (size_t)4 * NN : nullptr,
                                                      head_W, head_b,
                                                      last ? out : nullptr);
    }

    // recon at out[260N .. 388N)
    hgemm<2><<<dim3(1, gy), 256, SM_P>>>(hbh, hbl, dch, dcl, out + (size_t)260 * NN,
                                         NN, EMB, INC, dec_b,
                                         nullptr, nullptr, nullptr, nullptr);
}

// round 16
// speedup vs baseline: 1.6786x; 1.0167x over previous
#include <cuda_runtime.h>
#include <cuda_fp16.h>
#include <math.h>
#include <stdint.h>

#define NN      100000
#define INC     128
#define EMB     256
#define NHEAD   4
#define HID     64
#define NLAYER  3
#define NE      300000
#define ET      400000          // NE + NN self loops
#define BN_EPS  1e-5f

// ---------------- scratch (all fp16) ----------------
__device__ __half g_xlh[(size_t)NN * EMB];                   // xl, fp16
__device__ __half g_xrh[(size_t)NN * EMB];                   // xr, fp16
__device__ __half g_hbh[NN * EMB], g_hbl[NN * EMB];          // h as fp16 hi/lo pair
__device__ __half g_xbh[NN * INC], g_xbl[NN * INC];          // x split fp16
__device__ __half g_wth[NLAYER * 512 * EMB];                 // layer W^T, single fp16
__device__ __half g_pjh[EMB * INC], g_pjl[EMB * INC];        // proj^T hi/lo
__device__ __half g_dch[INC * EMB];                          // dec^T single fp16
// CSR
__device__ int g_cnt[NN];
__device__ int g_rowp[NN + 1];
__device__ int g_col[ET];
__device__ int g_bsum[512];

__device__ __forceinline__ uint32_t smem_u32(const void* p) {
    uint32_t a;
    asm("{ .reg .u64 t; cvta.to.shared.u64 t, %1; cvt.u32.u64 %0, t; }"
        : "=r"(a) : "l"(p));
    return a;
}
__device__ __forceinline__ void split_f16(float v, __half& h, __half& l) {
    h = __float2half_rn(v);
    l = __float2half_rn(v - __half2float(h));
}
__device__ __forceinline__ void unpack_h8(uint4 v, float* f) {
    float2 a;
    a = __half22float2(*(__half2*)&v.x); f[0] = a.x; f[1] = a.y;
    a = __half22float2(*(__half2*)&v.y); f[2] = a.x; f[3] = a.y;
    a = __half22float2(*(__half2*)&v.z); f[4] = a.x; f[5] = a.y;
    a = __half22float2(*(__half2*)&v.w); f[6] = a.x; f[7] = a.y;
}
__device__ __forceinline__ uint4 pack_h8(const float* f) {
    uint4 r;
    *(__half2*)&r.x = __floats2half2_rn(f[0], f[1]);
    *(__half2*)&r.y = __floats2half2_rn(f[2], f[3]);
    *(__half2*)&r.z = __floats2half2_rn(f[4], f[5]);
    *(__half2*)&r.w = __floats2half2_rn(f[6], f[7]);
    return r;
}

// ------------- unified prep: weights + x split + csr cnt init -----------
#define PJ_N (INC * EMB)                        // 32768
#define WLR_N (NLAYER * 2 * EMB * EMB)          // 393216
#define DC_N (EMB * INC)                        // 32768
#define XQ_N (NN * INC / 4)                     // 3,200,000
__global__ void prep_all(const float* __restrict__ projW, const float* __restrict__ Wl,
                         const float* __restrict__ Wr, const float* __restrict__ decW,
                         const float* __restrict__ x)
{
    const int idx = blockIdx.x * 256 + threadIdx.x;
    if (idx < NN) g_cnt[idx] = 1;                     // self-loop count
    // x split (float4 granularity)
    if (idx < XQ_N) {
        const float4 v = ((const float4*)x)[idx];
        __half h0, h1, h2, h3, l0, l1, l2, l3;
        split_f16(v.x, h0, l0); split_f16(v.y, h1, l1);
        split_f16(v.z, h2, l2); split_f16(v.w, h3, l3);
        uint2 hp, lp;
        *(__half2*)&hp.x = __half2(h0, h1);
        *(__half2*)&hp.y = __half2(h2, h3);
        *(__half2*)&lp.x = __half2(l0, l1);
        *(__half2*)&lp.y = __half2(l2, l3);
        ((uint2*)g_xbh)[idx] = hp;
        ((uint2*)g_xbl)[idx] = lp;
    }
    // weights
    if (idx < PJ_N) {
        const int k = idx >> 8, n = idx & 255;              // [128][256]
        __half h, l;
        split_f16(projW[idx], h, l);
        g_pjh[n * INC + k] = h;
        g_pjl[n * INC + k] = l;
    } else if (idx < PJ_N + WLR_N) {
        const int r0 = idx - PJ_N;
        const int l = r0 / (2 * EMB * EMB);
        const int r = r0 - l * 2 * EMB * EMB;
        const int sel = r / (EMB * EMB);
        const int t = r - sel * EMB * EMB;
        const int k = t / EMB, n = t - k * EMB;
        const float v = (sel ? Wr : Wl)[(size_t)l * EMB * EMB + t];
        const size_t d = (size_t)l * 512 * EMB + (size_t)(sel * 256 + n) * EMB + k;
        g_wth[d] = __float2half_rn(v);
    } else if (idx < PJ_N + WLR_N + DC_N) {
        const int t = idx - PJ_N - WLR_N;
        const int k = t >> 7, n = t & 127;                  // [256][128]
        g_dch[(size_t)n * EMB + k] = __float2half_rn(decW[t]);
    }
}

// ---------------- CSR build ----------------
__global__ void csr_hist(const int* __restrict__ ei) {
    const int e = blockIdx.x * 256 + threadIdx.x;
    if (e < NE) atomicAdd(&g_cnt[ei[NE + e]], 1);
}
__global__ void csr_scan1() {
    __shared__ int s[256];
    const int i = blockIdx.x * 256 + threadIdx.x;
    int v = (i < NN) ? g_cnt[i] : 0;
    s[threadIdx.x] = v;
    __syncthreads();
    int sum = v;
    #pragma unroll
    for (int off = 1; off < 256; off <<= 1) {
        int t = (threadIdx.x >= off) ? s[threadIdx.x - off] : 0;
        __syncthreads();
        s[threadIdx.x] = sum = sum + t;
        __syncthreads();
    }
    if (i < NN) g_rowp[i] = sum - v;
    if (threadIdx.x == 255) g_bsum[blockIdx.x] = s[255];
}
__global__ void csr_scan2(int nb) {
    __shared__ int s[512];
    const int t = threadIdx.x;
    int v = (t < nb) ? g_bsum[t] : 0;
    s[t] = v;
    __syncthreads();
    int sum = v;
    #pragma unroll
    for (int off = 1; off < 512; off <<= 1) {
        int u = (t >= off) ? s[t - off] : 0;
        __syncthreads();
        s[t] = sum = sum + u;
        __syncthreads();
    }
    if (t < nb) g_bsum[t] = sum - v;
}
__global__ void csr_scan3() {
    const int i = blockIdx.x * 256 + threadIdx.x;
    if (i == 0) g_rowp[NN] = ET;
    if (i >= NN) return;
    const int r = g_rowp[i] + g_bsum[i >> 8];
    g_rowp[i] = r;
    g_col[r] = i;
    g_cnt[i] = r + 1;
}
__global__ void csr_fill(const int* __restrict__ ei) {
    const int e = blockIdx.x * 256 + threadIdx.x;
    if (e >= NE) return;
    const int pos = atomicAdd(&g_cnt[ei[NE + e]], 1);
    g_col[pos] = ei[e];
}

// ====== fp16 mma.sync GEMM, 2-stage pipeline, ONE sync/chunk, occ 2 ======
// EPI 0 (layer): BK=64, 3 buffers; xl 2 terms, xr 1 term. writes fp16 xl/xr.
// EPI 1 (proj):  BK=32, 4 buffers, 3 terms -> h fp16 pair.
// EPI 2 (dec):   BK=64, 3 buffers, 2 terms -> fp32 C (+bias).
#define CPA(dst32, src, pb) \
    asm volatile("cp.async.cg.shared.global [%0], [%1], 16, %2;" \
                 :: "r"(dst32), "l"(src), "r"(pb))

__device__ __forceinline__ void ldsm_x4(uint32_t* r, uint32_t addr) {
    asm volatile("ldmatrix.sync.aligned.m8n8.x4.shared.b16 {%0,%1,%2,%3}, [%4];"
                 : "=r"(r[0]), "=r"(r[1]), "=r"(r[2]), "=r"(r[3]) : "r"(addr));
}
__device__ __forceinline__ void mma16816(float* c, const uint32_t* a, const uint32_t* b) {
    asm volatile("mma.sync.aligned.m16n8k16.row.col.f32.f16.f16.f32 "
                 "{%0,%1,%2,%3}, {%4,%5,%6,%7}, {%8,%9}, {%0,%1,%2,%3};"
                 : "+f"(c[0]), "+f"(c[1]), "+f"(c[2]), "+f"(c[3])
                 : "r"(a[0]), "r"(a[1]), "r"(a[2]), "r"(a[3]), "r"(b[0]), "r"(b[1]));
}

template<int EPI>
__global__ __launch_bounds__(256, 2)
void hgemm(const __half* __restrict__ Ath, const __half* __restrict__ Atl,
           const __half* __restrict__ Bth, const __half* __restrict__ Btl,
           float* __restrict__ C, int M, int K, int NC,
           const float* __restrict__ bias, const float* __restrict__ gg,
           const float* __restrict__ gb, const float* __restrict__ gm,
           const float* __restrict__ gv)
{
    constexpr int BKT  = (EPI == 1) ? 32 : 64;     // K per chunk
    constexpr int RS   = BKT + 8;                  // row stride (elems)
    constexpr int BUFB = 128 * RS * 2;             // bytes per operand buffer
    constexpr int NBUF = (EPI == 1) ? 4 : 3;       // A-hi, A-lo, B-hi, [B-lo]
    constexpr int STAGE = NBUF * BUFB;
    constexpr int CPR  = BKT / 8;                  // 16B cps per row
    constexpr int CPIT = 128 * CPR / 256;          // cp iters per buffer
    constexpr int KSIT = BKT / 16;                 // k-steps per chunk

    extern __shared__ __half sm[];
    const uint32_t s32 = smem_u32(sm);
    const int tid = threadIdx.x, lane = tid & 31, w = tid >> 5;
    const int m0 = blockIdx.y * 128, n0 = blockIdx.x * 128;
    const int wm = (w >> 2) * 64, wn = (w & 3) * 32;

    // term count: proj = 3, dec = 2, xl = 2, xr = 1
    const int terms = (EPI == 1) ? 3 : (EPI == 2) ? 2 : (n0 < 256 ? 2 : 1);

    float acc[4][4][4] = {};
    const int nchunks = K / BKT;

    const __half* srcs[4] = {Ath, Atl, Bth, Btl};

    auto load_chunk = [&](int ch, int st) {
        const uint32_t sb = s32 + (uint32_t)st * STAGE;
        #pragma unroll
        for (int buf = 0; buf < NBUF; buf++) {
            if (buf == 1 && terms < 2) continue;     // A-lo only for terms>=2
            if (buf == 3 && terms < 3) continue;     // B-lo only for terms==3
            #pragma unroll
            for (int it = 0; it < CPIT; it++) {
                const int s = it * 256 + tid;
                const int r = s / CPR, q = s % CPR;
                const int base = (buf < 2) ? m0 : n0;
                const uint32_t doff = (uint32_t)buf * BUFB + (uint32_t)(r * RS + q * 8) * 2;
                const size_t goff = (size_t)(base + r) * K + ch * BKT + q * 8;
                const unsigned pb = (buf >= 2 || base + r < M) ? 16u : 0u;
                CPA(sb + doff, srcs[buf] + goff, pb);
            }
        }
        asm volatile("cp.async.commit_group;" ::: "memory");
    };

    load_chunk(0, 0);

    for (int ch = 0; ch < nchunks; ch++) {
        asm volatile("cp.async.wait_group 0;" ::: "memory");   // chunk ch landed
        __syncthreads();                                        // stage (ch+1)&1 free
        if (ch + 1 < nchunks) load_chunk(ch + 1, (ch + 1) & 1);

        const uint32_t sb = s32 + (uint32_t)(ch & 1) * STAGE;
        const int lra = lane & 15, lka = (lane >> 4) * 8;
        const int bt = lane >> 3, blr = lane & 7;

        #pragma unroll
        for (int ks = 0; ks < KSIT; ks++) {
            const int k0 = ks * 16;
            uint32_t ah[4][4], bh[4][2];
            #pragma unroll
            for (int mt = 0; mt < 4; mt++)
                ldsm_x4(ah[mt], sb + ((wm + mt * 16 + lra) * RS + k0 + lka) * 2);
            #pragma unroll
            for (int ntp = 0; ntp < 2; ntp++) {
                const int row = wn + ntp * 16 + ((bt >> 1) << 3) + blr;
                const int col = k0 + (bt & 1) * 8;
                ldsm_x4(&bh[ntp * 2][0], sb + 2 * BUFB + (row * RS + col) * 2);
            }
            #pragma unroll
            for (int mt = 0; mt < 4; mt++)
                #pragma unroll
                for (int nt = 0; nt < 4; nt++)
                    mma16816(acc[mt][nt], ah[mt], bh[nt]);

            if (terms >= 2) {
                uint32_t al[4][4];
                #pragma unroll
                for (int mt = 0; mt < 4; mt++)
                    ldsm_x4(al[mt], sb + BUFB + ((wm + mt * 16 + lra) * RS + k0 + lka) * 2);
                #pragma unroll
                for (int mt = 0; mt < 4; mt++)
                    #pragma unroll
                    for (int nt = 0; nt < 4; nt++)
                        mma16816(acc[mt][nt], al[mt], bh[nt]);
            }
            if (NBUF == 4 && terms >= 3) {
                uint32_t bl[4][2];
                #pragma unroll
                for (int ntp = 0; ntp < 2; ntp++) {
                    const int row = wn + ntp * 16 + ((bt >> 1) << 3) + blr;
                    const int col = k0 + (bt & 1) * 8;
                    ldsm_x4(&bl[ntp * 2][0], sb + 3 * BUFB + (row * RS + col) * 2);
                }
                #pragma unroll
                for (int mt = 0; mt < 4; mt++)
                    #pragma unroll
                    for (int nt = 0; nt < 4; nt++)
                        mma16816(acc[mt][nt], ah[mt], bl[nt]);
            }
        }
        __syncthreads();   // reading of stage ch&1 complete before next overwrite
    }

    // epilogue: column-paired vectorized stores
    #pragma unroll
    for (int mt = 0; mt < 4; mt++) {
        #pragma unroll
        for (int nt = 0; nt < 4; nt++) {
            #pragma unroll
            for (int qq = 0; qq < 2; qq++) {
                const int row = m0 + wm + mt * 16 + (lane >> 2) + qq * 8;
                const int col = n0 + wn + nt * 8 + 2 * (lane & 3);
                if (row >= M) continue;
                float v0 = acc[mt][nt][qq * 2];
                float v1 = acc[mt][nt][qq * 2 + 1];
                if (EPI == 0) {
                    __half2 hv = __floats2half2_rn(v0, v1);
                    if (n0 < 256)
                        *(__half2*)(g_xlh + (size_t)row * EMB + col) = hv;
                    else
                        *(__half2*)(g_xrh + (size_t)row * EMB + (col - 256)) = hv;
                } else if (EPI == 2) {
                    v0 += bias[col];
                    v1 += bias[col + 1];
                    *(float2*)(C + (size_t)row * NC + col) = make_float2(v0, v1);
                } else {
                    v0 += bias[col];
                    v1 += bias[col + 1];
                    v0 = (v0 - gm[col]) * (gg[col] * rsqrtf(gv[col] + BN_EPS)) + gb[col];
                    v1 = (v1 - gm[col + 1]) * (gg[col + 1] * rsqrtf(gv[col + 1] + BN_EPS)) + gb[col + 1];
                    v0 = v0 > 0.f ? v0 : __expf(v0) - 1.f;
                    v1 = v1 > 0.f ? v1 : __expf(v1) - 1.f;
                    __half h0, l0, h1, l1;
                    split_f16(v0, h0, l0);
                    split_f16(v1, h1, l1);
                    *(__half2*)(g_hbh + (size_t)row * EMB + col) = __half2(h0, h1);
                    *(__half2*)(g_hbl + (size_t)row * EMB + col) = __half2(l0, l1);
                }
            }
        }
    }
}

// ====== fused GATv2 aggregation: warp per dst node (CSR, no atomics) =====
__global__ __launch_bounds__(256)
void gat_aggregate(const float* __restrict__ att, const float* __restrict__ cb,
                   const float* __restrict__ bg, const float* __restrict__ bb,
                   const float* __restrict__ bm, const float* __restrict__ bv,
                   float* __restrict__ out_h,
                   const float* __restrict__ hW, const float* __restrict__ hb,
                   float* __restrict__ preds)
{
    const int lane = threadIdx.x & 31;
    const int n = (blockIdx.x * 256 + threadIdx.x) >> 5;
    if (n >= NN) return;
    const int j0 = lane * 8;

    float sA[8], xr8[8];
    {
        const float4* ap = (const float4*)(att + j0);
        float4 a0 = ap[0], a1 = ap[1];
        sA[0]=a0.x; sA[1]=a0.y; sA[2]=a0.z; sA[3]=a0.w;
        sA[4]=a1.x; sA[5]=a1.y; sA[6]=a1.z; sA[7]=a1.w;
        unpack_h8(*(const uint4*)(g_xrh + (size_t)n * EMB + j0), xr8);
    }

    float acc[8] = {};
    float den = 0.f;
    const int e0 = g_rowp[n], e1 = g_rowp[n + 1];

    // distance-3 software pipeline (clamped index; redundant loads hit L1)
    auto ldxl = [&](int e) -> uint4 {
        const int ee = (e < e1) ? e : (e1 - 1);
        return *(const uint4*)(g_xlh + (size_t)g_col[ee] * EMB + j0);
    };
    uint4 b0 = ldxl(e0), b1 = ldxl(e0 + 1), b2 = ldxl(e0 + 2);
    for (int e = e0; e < e1; e++) {
        const uint4 lv = b0;
        b0 = b1; b1 = b2;
        if (e + 3 < e1) b2 = ldxl(e + 3);
        float xl8[8];
        unpack_h8(lv, xl8);
        float part = 0.f;
        #pragma unroll
        for (int u = 0; u < 8; u++) {
            float s = xl8[u] + xr8[u];
            s = s > 0.f ? s : 0.2f * s;
            part += s * sA[u];
        }
        part += __shfl_xor_sync(0xffffffffu, part, 1);
        part += __shfl_xor_sync(0xffffffffu, part, 2);
        part += __shfl_xor_sync(0xffffffffu, part, 4);
        const float p = __expf(part);
        den += p;
        #pragma unroll
        for (int u = 0; u < 8; u++) acc[u] += p * xl8[u];
    }

    const float inv = 1.f / den;

    // residual from fp16 hi/lo pair (exact to 2^-22)
    float hold[8];
    {
        float tmp[8];
        unpack_h8(*(const uint4*)(g_hbh + (size_t)n * EMB + j0), hold);
        unpack_h8(*(const uint4*)(g_hbl + (size_t)n * EMB + j0), tmp);
        #pragma unroll
        for (int u = 0; u < 8; u++) hold[u] += tmp[u];
    }

    float outv[8];
    #pragma unroll
    for (int u = 0; u < 8; u++) {
        const int j = j0 + u;
        float v = acc[u] * inv + cb[j];
        v = (v - bm[j]) * (bg[j] * rsqrtf(bv[j] + BN_EPS)) + bb[j];
        v = v > 0.f ? v : __expf(v) - 1.f;
        outv[u] = hold[u] + v;
    }

    // write h pair (always; feeds next GEMM / dec)
    {
        float hi8[8], lo8[8];
        #pragma unroll
        for (int u = 0; u < 8; u++) {
            __half h, l;
            split_f16(outv[u], h, l);
            hi8[u] = __half2float(h);
            lo8[u] = __half2float(l);
        }
        *(uint4*)(g_hbh + (size_t)n * EMB + j0) = pack_h8(hi8);
        *(uint4*)(g_hbl + (size_t)n * EMB + j0) = pack_h8(lo8);
    }

    if (out_h) {
        // final layer: fp32 h to output + fused heads
        float* op = out_h + (size_t)n * EMB + j0;
        ((float4*)op)[0] = make_float4(outv[0], outv[1], outv[2], outv[3]);
        ((float4*)op)[1] = make_float4(outv[4], outv[5], outv[6], outv[7]);

        float s0 = 0.f, s1 = 0.f, s2 = 0.f, s3 = 0.f;
        #pragma unroll
        for (int u = 0; u < 8; u++) {
            const float hv = outv[u];
            s0 += hv * hW[j0 + u];
            s1 += hv * hW[EMB + j0 + u];
            s2 += hv * hW[2 * EMB + j0 + u];
            s3 += hv * hW[3 * EMB + j0 + u];
        }
        #pragma unroll
        for (int off = 16; off; off >>= 1) {
            s0 += __shfl_xor_sync(0xffffffffu, s0, off);
            s1 += __shfl_xor_sync(0xffffffffu, s1, off);
            s2 += __shfl_xor_sync(0xffffffffu, s2, off);
            s3 += __shfl_xor_sync(0xffffffffu, s3, off);
        }
        if (lane == 0) {
            preds[n]          = s0 + hb[0];
            preds[NN + n]     = s1 + hb[1];
            preds[2 * NN + n] = s2 + hb[2];
            preds[3 * NN + n] = s3 + hb[3];
        }
    }
}

// ---------------- launch ----------------
extern "C" void kernel_launch(void* const* d_in, const int* in_sizes, int n_in,
                              void* d_out, int out_size)
{
    const float* x      = (const float*)d_in[0];
    const int*   ei     = (const int*)  d_in[1];
    const float* proj_W = (const float*)d_in[2];
    const float* proj_b = (const float*)d_in[3];
    const float* ibn_g  = (const float*)d_in[4];
    const float* ibn_b  = (const float*)d_in[5];
    const float* ibn_m  = (const float*)d_in[6];
    const float* ibn_v  = (const float*)d_in[7];
    const float* Wl     = (const float*)d_in[8];
    const float* Wr     = (const float*)d_in[9];
    const float* att    = (const float*)d_in[10];
    const float* conv_b = (const float*)d_in[11];
    const float* bn_g   = (const float*)d_in[12];
    const float* bn_b   = (const float*)d_in[13];
    const float* bn_m   = (const float*)d_in[14];
    const float* bn_v   = (const float*)d_in[15];
    const float* head_W = (const float*)d_in[16];
    const float* head_b = (const float*)d_in[17];
    const float* dec_W  = (const float*)d_in[18];
    const float* dec_b  = (const float*)d_in[19];
    float* out = (float*)d_out;

    __half *hbh, *hbl, *xbh, *xbl, *wth, *pjh, *pjl, *dch;
    cudaGetSymbolAddress((void**)&hbh, g_hbh);
    cudaGetSymbolAddress((void**)&hbl, g_hbl);
    cudaGetSymbolAddress((void**)&xbh, g_xbh);
    cudaGetSymbolAddress((void**)&xbl, g_xbl);
    cudaGetSymbolAddress((void**)&wth, g_wth);
    cudaGetSymbolAddress((void**)&pjh, g_pjh);
    cudaGetSymbolAddress((void**)&pjl, g_pjl);
    cudaGetSymbolAddress((void**)&dch, g_dch);

    // smem: EPI0/2 = 2 stages * 3 bufs * 128*72*2 = 110592
    //       EPI1   = 2 stages * 4 bufs * 128*40*2 = 81920
    const int SM_L = 2 * 3 * 128 * 72 * 2;
    const int SM_P = 2 * 4 * 128 * 40 * 2;
    cudaFuncSetAttribute(hgemm<0>, cudaFuncAttributeMaxDynamicSharedMemorySize, SM_L);
    cudaFuncSetAttribute(hgemm<1>, cudaFuncAttributeMaxDynamicSharedMemorySize, SM_P);
    cudaFuncSetAttribute(hgemm<2>, cudaFuncAttributeMaxDynamicSharedMemorySize, SM_L);

    const int gy = (NN + 127) / 128;          // 782
    const int nb = (NN + 255) / 256;          // 391

    // ---- prep: weights + x split + csr cnt (one kernel), CSR ----
    prep_all<<<(XQ_N + 255) / 256, 256>>>(proj_W, Wl, Wr, dec_W, x);

    csr_hist<<<(NE + 255) / 256, 256>>>(ei);
    csr_scan1<<<nb, 256>>>();
    csr_scan2<<<1, 512>>>(nb);
    csr_scan3<<<nb, 256>>>();
    csr_fill<<<(NE + 255) / 256, 256>>>(ei);

    // ---- h = elu(bn(x @ proj_W + proj_b)) -> h fp16 pair ----
    hgemm<1><<<dim3(2, gy), 256, SM_P>>>(xbh, xbl, pjh, pjl, nullptr, NN, INC, EMB,
                                         proj_b, ibn_g, ibn_b, ibn_m, ibn_v);

    for (int i = 0; i < NLAYER; i++) {
        hgemm<0><<<dim3(4, gy), 256, SM_L>>>(hbh, hbl,
                                             wth + (size_t)i * 512 * EMB, nullptr,
                                             nullptr, NN, EMB, 512,
                                             nullptr, nullptr, nullptr, nullptr, nullptr);
        const bool last = (i == NLAYER - 1);
        gat_aggregate<<<(NN * 32 + 255) / 256, 256>>>(att + (size_t)i * NHEAD * HID,
                                                      conv_b + (size_t)i * EMB,
                                                      bn_g + (size_t)i * EMB, bn_b + (size_t)i * EMB,
                                                      bn_m + (size_t)i * EMB, bn_v + (size_t)i * EMB,
                                                      last ? out + (size_t)4 * NN : nullptr,
                                                      head_W, head_b,
                                                      last ? out : nullptr);
    }

    // recon at out[260N .. 388N): dec 2-term (single fp16 dec_W)
    hgemm<2><<<dim3(1, gy), 256, SM_L>>>(hbh, hbl, dch, nullptr, out + (size_t)260 * NN,
                                         NN, EMB, INC, dec_b,
                                         nullptr, nullptr, nullptr, nullptr);
}

// round 17
// speedup vs baseline: 1.7985x; 1.0715x over previous
#include <cuda_runtime.h>
#include <cuda_fp16.h>
#include <math.h>
#include <stdint.h>

#define NN      100000
#define INC     128
#define EMB     256
#define NHEAD   4
#define HID     64
#define NLAYER  3
#define NE      300000
#define ET      400000          // NE + NN self loops
#define BN_EPS  1e-5f

// ---------------- scratch (all fp16) ----------------
__device__ __half g_xlh[(size_t)NN * EMB];                   // xl, fp16
__device__ __half g_xrh[(size_t)NN * EMB];                   // xr, fp16
__device__ __half g_hbh[NN * EMB], g_hbl[NN * EMB];          // h as fp16 hi/lo pair
__device__ __half g_xbh[NN * INC], g_xbl[NN * INC];          // x split fp16
__device__ __half g_wth[NLAYER * 512 * EMB];                 // layer W^T, single fp16
__device__ __half g_pjh[EMB * INC], g_pjl[EMB * INC];        // proj^T hi/lo
__device__ __half g_dch[INC * EMB];                          // dec^T single fp16
// CSR
__device__ int g_cnt[NN];
__device__ int g_rowp[NN + 1];
__device__ int g_col[ET];
__device__ int g_bsum[512];

__device__ __forceinline__ uint32_t smem_u32(const void* p) {
    uint32_t a;
    asm("{ .reg .u64 t; cvta.to.shared.u64 t, %1; cvt.u32.u64 %0, t; }"
        : "=r"(a) : "l"(p));
    return a;
}
__device__ __forceinline__ void split_f16(float v, __half& h, __half& l) {
    h = __float2half_rn(v);
    l = __float2half_rn(v - __half2float(h));
}
__device__ __forceinline__ void unpack_h8(uint4 v, float* f) {
    float2 a;
    a = __half22float2(*(__half2*)&v.x); f[0] = a.x; f[1] = a.y;
    a = __half22float2(*(__half2*)&v.y); f[2] = a.x; f[3] = a.y;
    a = __half22float2(*(__half2*)&v.z); f[4] = a.x; f[5] = a.y;
    a = __half22float2(*(__half2*)&v.w); f[6] = a.x; f[7] = a.y;
}
__device__ __forceinline__ uint4 pack_h8(const float* f) {
    uint4 r;
    *(__half2*)&r.x = __floats2half2_rn(f[0], f[1]);
    *(__half2*)&r.y = __floats2half2_rn(f[2], f[3]);
    *(__half2*)&r.z = __floats2half2_rn(f[4], f[5]);
    *(__half2*)&r.w = __floats2half2_rn(f[6], f[7]);
    return r;
}

// ------------- unified prep: weights + x split + csr cnt init -----------
#define PJ_N (INC * EMB)                        // 32768
#define WLR_N (NLAYER * 2 * EMB * EMB)          // 393216
#define DC_N (EMB * INC)                        // 32768
#define XQ_N (NN * INC / 4)                     // 3,200,000
__global__ void prep_all(const float* __restrict__ projW, const float* __restrict__ Wl,
                         const float* __restrict__ Wr, const float* __restrict__ decW,
                         const float* __restrict__ x)
{
    const int idx = blockIdx.x * 256 + threadIdx.x;
    if (idx < NN) g_cnt[idx] = 1;                     // self-loop count
    if (idx < XQ_N) {
        const float4 v = ((const float4*)x)[idx];
        __half h0, h1, h2, h3, l0, l1, l2, l3;
        split_f16(v.x, h0, l0); split_f16(v.y, h1, l1);
        split_f16(v.z, h2, l2); split_f16(v.w, h3, l3);
        uint2 hp, lp;
        *(__half2*)&hp.x = __half2(h0, h1);
        *(__half2*)&hp.y = __half2(h2, h3);
        *(__half2*)&lp.x = __half2(l0, l1);
        *(__half2*)&lp.y = __half2(l2, l3);
        ((uint2*)g_xbh)[idx] = hp;
        ((uint2*)g_xbl)[idx] = lp;
    }
    if (idx < PJ_N) {
        const int k = idx >> 8, n = idx & 255;              // [128][256]
        __half h, l;
        split_f16(projW[idx], h, l);
        g_pjh[n * INC + k] = h;
        g_pjl[n * INC + k] = l;
    } else if (idx < PJ_N + WLR_N) {
        const int r0 = idx - PJ_N;
        const int l = r0 / (2 * EMB * EMB);
        const int r = r0 - l * 2 * EMB * EMB;
        const int sel = r / (EMB * EMB);
        const int t = r - sel * EMB * EMB;
        const int k = t / EMB, n = t - k * EMB;
        const float v = (sel ? Wr : Wl)[(size_t)l * EMB * EMB + t];
        const size_t d = (size_t)l * 512 * EMB + (size_t)(sel * 256 + n) * EMB + k;
        g_wth[d] = __float2half_rn(v);
    } else if (idx < PJ_N + WLR_N + DC_N) {
        const int t = idx - PJ_N - WLR_N;
        const int k = t >> 7, n = t & 127;                  // [256][128]
        g_dch[(size_t)n * EMB + k] = __float2half_rn(decW[t]);
    }
}

// ---------------- CSR build ----------------
__global__ void csr_hist(const int* __restrict__ ei) {
    const int e = blockIdx.x * 256 + threadIdx.x;
    if (e < NE) atomicAdd(&g_cnt[ei[NE + e]], 1);
}
__global__ void csr_scan1() {
    __shared__ int s[256];
    const int i = blockIdx.x * 256 + threadIdx.x;
    int v = (i < NN) ? g_cnt[i] : 0;
    s[threadIdx.x] = v;
    __syncthreads();
    int sum = v;
    #pragma unroll
    for (int off = 1; off < 256; off <<= 1) {
        int t = (threadIdx.x >= off) ? s[threadIdx.x - off] : 0;
        __syncthreads();
        s[threadIdx.x] = sum = sum + t;
        __syncthreads();
    }
    if (i < NN) g_rowp[i] = sum - v;
    if (threadIdx.x == 255) g_bsum[blockIdx.x] = s[255];
}
__global__ void csr_scan2(int nb) {
    __shared__ int s[512];
    const int t = threadIdx.x;
    int v = (t < nb) ? g_bsum[t] : 0;
    s[t] = v;
    __syncthreads();
    int sum = v;
    #pragma unroll
    for (int off = 1; off < 512; off <<= 1) {
        int u = (t >= off) ? s[t - off] : 0;
        __syncthreads();
        s[t] = sum = sum + u;
        __syncthreads();
    }
    if (t < nb) g_bsum[t] = sum - v;
}
__global__ void csr_scan3() {
    const int i = blockIdx.x * 256 + threadIdx.x;
    if (i == 0) g_rowp[NN] = ET;
    if (i >= NN) return;
    const int r = g_rowp[i] + g_bsum[i >> 8];
    g_rowp[i] = r;
    g_col[r] = i;
    g_cnt[i] = r + 1;
}
__global__ void csr_fill(const int* __restrict__ ei) {
    const int e = blockIdx.x * 256 + threadIdx.x;
    if (e >= NE) return;
    const int pos = atomicAdd(&g_cnt[ei[NE + e]], 1);
    g_col[pos] = ei[e];
}

// ====== fp16 mma.sync GEMM, 2-stage pipeline, ONE sync/chunk, occ 2 ======
// EPI 0 (layer): BK=64, 2 buffers (A-hi/B-hi), 1 term -> fp16 xl/xr.
// EPI 1 (proj):  BK=32, 4 buffers, 3 terms -> h fp16 pair.
// EPI 2 (dec):   BK=64, 3 buffers (A-hi/A-lo/B-hi), 2 terms -> fp32 C (+bias).
#define CPA(dst32, src, pb) \
    asm volatile("cp.async.cg.shared.global [%0], [%1], 16, %2;" \
                 :: "r"(dst32), "l"(src), "r"(pb))

__device__ __forceinline__ void ldsm_x4(uint32_t* r, uint32_t addr) {
    asm volatile("ldmatrix.sync.aligned.m8n8.x4.shared.b16 {%0,%1,%2,%3}, [%4];"
                 : "=r"(r[0]), "=r"(r[1]), "=r"(r[2]), "=r"(r[3]) : "r"(addr));
}
__device__ __forceinline__ void mma16816(float* c, const uint32_t* a, const uint32_t* b) {
    asm volatile("mma.sync.aligned.m16n8k16.row.col.f32.f16.f16.f32 "
                 "{%0,%1,%2,%3}, {%4,%5,%6,%7}, {%8,%9}, {%0,%1,%2,%3};"
                 : "+f"(c[0]), "+f"(c[1]), "+f"(c[2]), "+f"(c[3])
                 : "r"(a[0]), "r"(a[1]), "r"(a[2]), "r"(a[3]), "r"(b[0]), "r"(b[1]));
}

template<int EPI>
__global__ __launch_bounds__(256, 2)
void hgemm(const __half* __restrict__ Ath, const __half* __restrict__ Atl,
           const __half* __restrict__ Bth, const __half* __restrict__ Btl,
           float* __restrict__ C, int M, int K, int NC,
           const float* __restrict__ bias, const float* __restrict__ gg,
           const float* __restrict__ gb, const float* __restrict__ gm,
           const float* __restrict__ gv)
{
    constexpr int BKT  = (EPI == 1) ? 32 : 64;     // K per chunk
    constexpr int RS   = BKT + 8;                  // row stride (elems)
    constexpr int BUFB = 128 * RS * 2;             // bytes per operand buffer
    constexpr int NBUF = (EPI == 0) ? 2 : (EPI == 2) ? 3 : 4;
    constexpr int BHI  = (EPI == 0) ? 1 : 2;       // B-hi buffer slot
    constexpr int STAGE = NBUF * BUFB;
    constexpr int CPR  = BKT / 8;                  // 16B cps per row
    constexpr int CPIT = 128 * CPR / 256;          // cp iters per buffer
    constexpr int KSIT = BKT / 16;                 // k-steps per chunk

    extern __shared__ __half sm[];
    const uint32_t s32 = smem_u32(sm);
    const int tid = threadIdx.x, lane = tid & 31, w = tid >> 5;
    const int m0 = blockIdx.y * 128, n0 = blockIdx.x * 128;
    const int wm = (w >> 2) * 64, wn = (w & 3) * 32;

    float acc[4][4][4] = {};
    const int nchunks = K / BKT;

    // buffer -> (src ptr, row base)
    const __half* bsrc[4];
    int bbase[4];
    bsrc[0] = Ath; bbase[0] = m0;
    if (EPI == 0)      { bsrc[1] = Bth; bbase[1] = n0; }
    else               { bsrc[1] = Atl; bbase[1] = m0;
                         bsrc[2] = Bth; bbase[2] = n0; }
    if (EPI == 1)      { bsrc[3] = Btl; bbase[3] = n0; }

    auto load_chunk = [&](int ch, int st) {
        const uint32_t sb = s32 + (uint32_t)st * STAGE;
        #pragma unroll
        for (int buf = 0; buf < NBUF; buf++) {
            #pragma unroll
            for (int it = 0; it < CPIT; it++) {
                const int s = it * 256 + tid;
                const int r = s / CPR, q = s % CPR;
                const uint32_t doff = (uint32_t)buf * BUFB + (uint32_t)(r * RS + q * 8) * 2;
                const size_t goff = (size_t)(bbase[buf] + r) * K + ch * BKT + q * 8;
                const unsigned pb = (buf >= BHI || bbase[buf] + r < M) ? 16u : 0u;
                CPA(sb + doff, bsrc[buf] + goff, pb);
            }
        }
        asm volatile("cp.async.commit_group;" ::: "memory");
    };

    load_chunk(0, 0);

    for (int ch = 0; ch < nchunks; ch++) {
        asm volatile("cp.async.wait_group 0;" ::: "memory");   // chunk ch landed
        __syncthreads();                                        // stage (ch+1)&1 free
        if (ch + 1 < nchunks) load_chunk(ch + 1, (ch + 1) & 1);

        const uint32_t sb = s32 + (uint32_t)(ch & 1) * STAGE;
        const int lra = lane & 15, lka = (lane >> 4) * 8;
        const int bt = lane >> 3, blr = lane & 7;

        #pragma unroll
        for (int ks = 0; ks < KSIT; ks++) {
            const int k0 = ks * 16;
            uint32_t ah[4][4], bh[4][2];
            #pragma unroll
            for (int mt = 0; mt < 4; mt++)
                ldsm_x4(ah[mt], sb + ((wm + mt * 16 + lra) * RS + k0 + lka) * 2);
            #pragma unroll
            for (int ntp = 0; ntp < 2; ntp++) {
                const int row = wn + ntp * 16 + ((bt >> 1) << 3) + blr;
                const int col = k0 + (bt & 1) * 8;
                ldsm_x4(&bh[ntp * 2][0], sb + BHI * BUFB + (row * RS + col) * 2);
            }
            #pragma unroll
            for (int mt = 0; mt < 4; mt++)
                #pragma unroll
                for (int nt = 0; nt < 4; nt++)
                    mma16816(acc[mt][nt], ah[mt], bh[nt]);

            if (EPI != 0) {   // A-lo term (proj, dec)
                uint32_t al[4][4];
                #pragma unroll
                for (int mt = 0; mt < 4; mt++)
                    ldsm_x4(al[mt], sb + BUFB + ((wm + mt * 16 + lra) * RS + k0 + lka) * 2);
                #pragma unroll
                for (int mt = 0; mt < 4; mt++)
                    #pragma unroll
                    for (int nt = 0; nt < 4; nt++)
                        mma16816(acc[mt][nt], al[mt], bh[nt]);
            }
            if (EPI == 1) {   // B-lo term (proj only)
                uint32_t bl[4][2];
                #pragma unroll
                for (int ntp = 0; ntp < 2; ntp++) {
                    const int row = wn + ntp * 16 + ((bt >> 1) << 3) + blr;
                    const int col = k0 + (bt & 1) * 8;
                    ldsm_x4(&bl[ntp * 2][0], sb + 3 * BUFB + (row * RS + col) * 2);
                }
                #pragma unroll
                for (int mt = 0; mt < 4; mt++)
                    #pragma unroll
                    for (int nt = 0; nt < 4; nt++)
                        mma16816(acc[mt][nt], ah[mt], bl[nt]);
            }
        }
        __syncthreads();   // reads of stage ch&1 complete before next overwrite
    }

    // epilogue: column-paired vectorized stores
    #pragma unroll
    for (int mt = 0; mt < 4; mt++) {
        #pragma unroll
        for (int nt = 0; nt < 4; nt++) {
            #pragma unroll
            for (int qq = 0; qq < 2; qq++) {
                const int row = m0 + wm + mt * 16 + (lane >> 2) + qq * 8;
                const int col = n0 + wn + nt * 8 + 2 * (lane & 3);
                if (row >= M) continue;
                float v0 = acc[mt][nt][qq * 2];
                float v1 = acc[mt][nt][qq * 2 + 1];
                if (EPI == 0) {
                    __half2 hv = __floats2half2_rn(v0, v1);
                    if (n0 < 256)
                        *(__half2*)(g_xlh + (size_t)row * EMB + col) = hv;
                    else
                        *(__half2*)(g_xrh + (size_t)row * EMB + (col - 256)) = hv;
                } else if (EPI == 2) {
                    v0 += bias[col];
                    v1 += bias[col + 1];
                    *(float2*)(C + (size_t)row * NC + col) = make_float2(v0, v1);
                } else {
                    v0 += bias[col];
                    v1 += bias[col + 1];
                    v0 = (v0 - gm[col]) * (gg[col] * rsqrtf(gv[col] + BN_EPS)) + gb[col];
                    v1 = (v1 - gm[col + 1]) * (gg[col + 1] * rsqrtf(gv[col + 1] + BN_EPS)) + gb[col + 1];
                    v0 = v0 > 0.f ? v0 : __expf(v0) - 1.f;
                    v1 = v1 > 0.f ? v1 : __expf(v1) - 1.f;
                    __half h0, l0, h1, l1;
                    split_f16(v0, h0, l0);
                    split_f16(v1, h1, l1);
                    *(__half2*)(g_hbh + (size_t)row * EMB + col) = __half2(h0, h1);
                    *(__half2*)(g_hbl + (size_t)row * EMB + col) = __half2(l0, l1);
                }
            }
        }
    }
}

// ====== fused GATv2 aggregation: warp per dst node (CSR, no atomics) =====
__global__ __launch_bounds__(256)
void gat_aggregate(const float* __restrict__ att, const float* __restrict__ cb,
                   const float* __restrict__ bg, const float* __restrict__ bb,
                   const float* __restrict__ bm, const float* __restrict__ bv,
                   float* __restrict__ out_h,
                   const float* __restrict__ hW, const float* __restrict__ hb,
                   float* __restrict__ preds)
{
    const int lane = threadIdx.x & 31;
    const int n = (blockIdx.x * 256 + threadIdx.x) >> 5;
    if (n >= NN) return;
    const int j0 = lane * 8;

    float sA[8], xr8[8];
    {
        const float4* ap = (const float4*)(att + j0);
        float4 a0 = ap[0], a1 = ap[1];
        sA[0]=a0.x; sA[1]=a0.y; sA[2]=a0.z; sA[3]=a0.w;
        sA[4]=a1.x; sA[5]=a1.y; sA[6]=a1.z; sA[7]=a1.w;
        unpack_h8(*(const uint4*)(g_xrh + (size_t)n * EMB + j0), xr8);
    }

    float acc[8] = {};
    float den = 0.f;
    const int e0 = g_rowp[n], e1 = g_rowp[n + 1];

    // distance-3 software pipeline (clamped index; redundant loads hit L1)
    auto ldxl = [&](int e) -> uint4 {
        const int ee = (e < e1) ? e : (e1 - 1);
        return *(const uint4*)(g_xlh + (size_t)g_col[ee] * EMB + j0);
    };
    uint4 b0 = ldxl(e0), b1 = ldxl(e0 + 1), b2 = ldxl(e0 + 2);
    for (int e = e0; e < e1; e++) {
        const uint4 lv = b0;
        b0 = b1; b1 = b2;
        if (e + 3 < e1) b2 = ldxl(e + 3);
        float xl8[8];
        unpack_h8(lv, xl8);
        float part = 0.f;
        #pragma unroll
        for (int u = 0; u < 8; u++) {
            float s = xl8[u] + xr8[u];
            s = s > 0.f ? s : 0.2f * s;
            part += s * sA[u];
        }
        part += __shfl_xor_sync(0xffffffffu, part, 1);
        part += __shfl_xor_sync(0xffffffffu, part, 2);
        part += __shfl_xor_sync(0xffffffffu, part, 4);
        const float p = __expf(part);
        den += p;
        #pragma unroll
        for (int u = 0; u < 8; u++) acc[u] += p * xl8[u];
    }

    const float inv = 1.f / den;

    // residual from fp16 hi/lo pair (exact to 2^-22)
    float hold[8];
    {
        float tmp[8];
        unpack_h8(*(const uint4*)(g_hbh + (size_t)n * EMB + j0), hold);
        unpack_h8(*(const uint4*)(g_hbl + (size_t)n * EMB + j0), tmp);
        #pragma unroll
        for (int u = 0; u < 8; u++) hold[u] += tmp[u];
    }

    float outv[8];
    #pragma unroll
    for (int u = 0; u < 8; u++) {
        const int j = j0 + u;
        float v = acc[u] * inv + cb[j];
        v = (v - bm[j]) * (bg[j] * rsqrtf(bv[j] + BN_EPS)) + bb[j];
        v = v > 0.f ? v : __expf(v) - 1.f;
        outv[u] = hold[u] + v;
    }

    // write h pair (always; feeds next GEMM / dec)
    {
        float hi8[8], lo8[8];
        #pragma unroll
        for (int u = 0; u < 8; u++) {
            __half h, l;
            split_f16(outv[u], h, l);
            hi8[u] = __half2float(h);
            lo8[u] = __half2float(l);
        }
        *(uint4*)(g_hbh + (size_t)n * EMB + j0) = pack_h8(hi8);
        *(uint4*)(g_hbl + (size_t)n * EMB + j0) = pack_h8(lo8);
    }

    if (out_h) {
        // final layer: fp32 h to output + fused heads
        float* op = out_h + (size_t)n * EMB + j0;
        ((float4*)op)[0] = make_float4(outv[0], outv[1], outv[2], outv[3]);
        ((float4*)op)[1] = make_float4(outv[4], outv[5], outv[6], outv[7]);

        float s0 = 0.f, s1 = 0.f, s2 = 0.f, s3 = 0.f;
        #pragma unroll
        for (int u = 0; u < 8; u++) {
            const float hv = outv[u];
            s0 += hv * hW[j0 + u];
            s1 += hv * hW[EMB + j0 + u];
            s2 += hv * hW[2 * EMB + j0 + u];
            s3 += hv * hW[3 * EMB + j0 + u];
        }
        #pragma unroll
        for (int off = 16; off; off >>= 1) {
            s0 += __shfl_xor_sync(0xffffffffu, s0, off);
            s1 += __shfl_xor_sync(0xffffffffu, s1, off);
            s2 += __shfl_xor_sync(0xffffffffu, s2, off);
            s3 += __shfl_xor_sync(0xffffffffu, s3, off);
        }
        if (lane == 0) {
            preds[n]          = s0 + hb[0];
            preds[NN + n]     = s1 + hb[1];
            preds[2 * NN + n] = s2 + hb[2];
            preds[3 * NN + n] = s3 + hb[3];
        }
    }
}

// ---------------- launch ----------------
extern "C" void kernel_launch(void* const* d_in, const int* in_sizes, int n_in,
                              void* d_out, int out_size)
{
    const float* x      = (const float*)d_in[0];
    const int*   ei     = (const int*)  d_in[1];
    const float* proj_W = (const float*)d_in[2];
    const float* proj_b = (const float*)d_in[3];
    const float* ibn_g  = (const float*)d_in[4];
    const float* ibn_b  = (const float*)d_in[5];
    const float* ibn_m  = (const float*)d_in[6];
    const float* ibn_v  = (const float*)d_in[7];
    const float* Wl     = (const float*)d_in[8];
    const float* Wr     = (const float*)d_in[9];
    const float* att    = (const float*)d_in[10];
    const float* conv_b = (const float*)d_in[11];
    const float* bn_g   = (const float*)d_in[12];
    const float* bn_b   = (const float*)d_in[13];
    const float* bn_m   = (const float*)d_in[14];
    const float* bn_v   = (const float*)d_in[15];
    const float* head_W = (const float*)d_in[16];
    const float* head_b = (const float*)d_in[17];
    const float* dec_W  = (const float*)d_in[18];
    const float* dec_b  = (const float*)d_in[19];
    float* out = (float*)d_out;

    __half *hbh, *hbl, *xbh, *xbl, *wth, *pjh, *pjl, *dch;
    cudaGetSymbolAddress((void**)&hbh, g_hbh);
    cudaGetSymbolAddress((void**)&hbl, g_hbl);
    cudaGetSymbolAddress((void**)&xbh, g_xbh);
    cudaGetSymbolAddress((void**)&xbl, g_xbl);
    cudaGetSymbolAddress((void**)&wth, g_wth);
    cudaGetSymbolAddress((void**)&pjh, g_pjh);
    cudaGetSymbolAddress((void**)&pjl, g_pjl);
    cudaGetSymbolAddress((void**)&dch, g_dch);

    // smem: EPI0 = 2*2*128*72*2 = 73728, EPI2 = 2*3*128*72*2 = 110592,
    //       EPI1 = 2*4*128*40*2 = 81920
    const int SM_L = 2 * 2 * 128 * 72 * 2;
    const int SM_D = 2 * 3 * 128 * 72 * 2;
    const int SM_P = 2 * 4 * 128 * 40 * 2;
    cudaFuncSetAttribute(hgemm<0>, cudaFuncAttributeMaxDynamicSharedMemorySize, SM_L);
    cudaFuncSetAttribute(hgemm<1>, cudaFuncAttributeMaxDynamicSharedMemorySize, SM_P);
    cudaFuncSetAttribute(hgemm<2>, cudaFuncAttributeMaxDynamicSharedMemorySize, SM_D);

    const int gy = (NN + 127) / 128;          // 782
    const int nb = (NN + 255) / 256;          // 391

    // ---- prep: weights + x split + csr cnt (one kernel), CSR ----
    prep_all<<<(XQ_N + 255) / 256, 256>>>(proj_W, Wl, Wr, dec_W, x);

    csr_hist<<<(NE + 255) / 256, 256>>>(ei);
    csr_scan1<<<nb, 256>>>();
    csr_scan2<<<1, 512>>>(nb);
    csr_scan3<<<nb, 256>>>();
    csr_fill<<<(NE + 255) / 256, 256>>>(ei);

    // ---- h = elu(bn(x @ proj_W + proj_b)) -> h fp16 pair ----
    hgemm<1><<<dim3(2, gy), 256, SM_P>>>(xbh, xbl, pjh, pjl, nullptr, NN, INC, EMB,
                                         proj_b, ibn_g, ibn_b, ibn_m, ibn_v);

    for (int i = 0; i < NLAYER; i++) {
        hgemm<0><<<dim3(4, gy), 256, SM_L>>>(hbh, nullptr,
                                             wth + (size_t)i * 512 * EMB, nullptr,
                                             nullptr, NN, EMB, 512,
                                             nullptr, nullptr, nullptr, nullptr, nullptr);
        const bool last = (i == NLAYER - 1);
        gat_aggregate<<<(NN * 32 + 255) / 256, 256>>>(att + (size_t)i * NHEAD * HID,
                                                      conv_b + (size_t)i * EMB,
                                                      bn_g + (size_t)i * EMB, bn_b + (size_t)i * EMB,
                                                      bn_m + (size_t)i * EMB, bn_v + (size_t)i * EMB,
                                                      last ? out + (size_t)4 * NN : nullptr,
                                                      head_W, head_b,
                                                      last ? out : nullptr);
    }

    // recon at out[260N .. 388N): dec 2-term (hi/lo A, single fp16 dec_W)
    hgemm<2><<<dim3(1, gy), 256, SM_D>>>(hbh, hbl, dch, nullptr, out + (size_t)260 * NN,
                                         NN, EMB, INC, dec_b,
                                         nullptr, nullptr, nullptr, nullptr);
}